// round 2
// baseline (speedup 1.0000x reference)
#include <cuda_runtime.h>
#include <math.h>

#define BATCH 256
#define NT 512
#define DIM 512
#define KTOP 153
#define BKTOK (BATCH*KTOP)      /* 39168 = 306*128 */
#define EDIM 1024
#define NHEADS 8
#define HD 64
#define NBLK_BN 306

/* ---------------- scratch (device globals; no allocation) ---------------- */
__device__ int   g_idx[BKTOK];
__device__ int   g_lens[BATCH];
__device__ float g_tok[(size_t)BKTOK*DIM];
__device__ float g_q[(size_t)BKTOK*DIM];          /* LN out, later reused as sa2 */
__device__ float g_qkv[(size_t)BKTOK*3*DIM];
__device__ float g_sa[(size_t)BKTOK*DIM];
__device__ float g_y1[(size_t)BKTOK*2*DIM];
__device__ float g_cap[(size_t)BKTOK*EDIM];
__device__ float g_h[(size_t)BKTOK*DIM];
__device__ float g_feat[(size_t)BKTOK*EDIM];
__device__ float g_p1[NBLK_BN*512];
__device__ float g_p2[NBLK_BN*512];
__device__ float g_mu[512];
__device__ float g_rstd[512];

/* ---------------- top-k selection (exact jax.lax.top_k order) ------------ */
__global__ void topk_kernel(const int* __restrict__ text,
                            const float* __restrict__ atten)
{
    int b = blockIdx.x;
    int t = threadIdx.x;            /* 512 threads */
    __shared__ float sval[NT];
    __shared__ int   sidx[NT];
    __shared__ int   red[NT];

    int tv = text[b*NT + t];

    /* eos = argmax(text), first occurrence of max */
    red[t] = (tv << 10) | (NT - 1 - t);
    __syncthreads();
    for (int s = NT/2; s > 0; s >>= 1) {
        if (t < s) red[t] = max(red[t], red[t+s]);
        __syncthreads();
    }
    int eos = NT - 1 - (red[0] & 1023);
    __syncthreads();

    /* lengths = nnz - 2 */
    red[t] = (tv != 0) ? 1 : 0;
    __syncthreads();
    for (int s = NT/2; s > 0; s >>= 1) {
        if (t < s) red[t] += red[t+s];
        __syncthreads();
    }
    int nz = red[0];
    __syncthreads();

    /* row with BOS/EOS suppressed, pad-masked */
    float v;
    if (t == 0 || t == eos) v = -1.0f;
    else                    v = atten[((size_t)b*NT + eos)*NT + t];
    if (tv == 0) v = 0.0f;

    sval[t] = v; sidx[t] = t;
    __syncthreads();

    /* bitonic sort, key = (val desc, idx asc)  — matches jax top_k ties */
    for (int ksz = 2; ksz <= NT; ksz <<= 1) {
        for (int j = ksz >> 1; j > 0; j >>= 1) {
            int ixj = t ^ j;
            if (ixj > t) {
                float va = sval[t], vb = sval[ixj];
                int   ia = sidx[t], ib = sidx[ixj];
                bool aBefore = (va > vb) || (va == vb && ia < ib);
                bool desc = ((t & ksz) == 0);
                if (desc ? !aBefore : aBefore) {
                    sval[t] = vb; sval[ixj] = va;
                    sidx[t] = ib; sidx[ixj] = ia;
                }
            }
            __syncthreads();
        }
    }
    if (t < KTOP) g_idx[b*KTOP + t] = sidx[t];
    if (t == 0) {
        int l = nz - 2;
        if (l > KTOP) l = KTOP;
        if (l < 1) l = 1;
        g_lens[b] = l;
    }
}

/* ---------- gather + L2 normalize + LayerNorm (fused, one pass) ---------- */
__global__ void gather_ln_kernel(const float* __restrict__ features,
                                 const float* __restrict__ lnw,
                                 const float* __restrict__ lnb)
{
    int token = blockIdx.x;               /* 0..BKTOK-1 */
    int b = token / KTOP;
    int src = g_idx[token];
    int tid = threadIdx.x;                /* 128 threads */
    const float* f = features + ((size_t)b*NT + src)*DIM;

    float v[4];
    float s1 = 0.f, s2 = 0.f;
#pragma unroll
    for (int i = 0; i < 4; i++) {
        v[i] = f[tid + i*128];
        s1 += v[i];
        s2 += v[i]*v[i];
    }
    __shared__ float r1[128], r2[128];
    r1[tid] = s1; r2[tid] = s2;
    __syncthreads();
    for (int s = 64; s > 0; s >>= 1) {
        if (tid < s) { r1[tid] += r1[tid+s]; r2[tid] += r2[tid+s]; }
        __syncthreads();
    }
    float sumf = r1[0], ss = r2[0];
    float inv  = 1.0f / (sqrtf(ss) + 1e-6f);
    float mean = sumf * inv * (1.0f/DIM);
    float et2  = ss * inv * inv * (1.0f/DIM);
    float var  = et2 - mean*mean;
    float rstd = rsqrtf(var + 1e-5f);

    float* tokp = g_tok + (size_t)token*DIM;
    float* qp   = g_q   + (size_t)token*DIM;
#pragma unroll
    for (int i = 0; i < 4; i++) {
        int c = tid + i*128;
        float tvv = v[i] * inv;
        tokp[c] = tvv;
        qp[c]   = (tvv - mean) * rstd * lnw[c] + lnb[c];
    }
}

/* --------------------- SGEMM: C = A @ W^T + bias (+epi) ------------------ */
/* A [M,K] row-major, W [N,K] row-major. M%128==0, N%128==0, K%16==0.       */
/* EPI: 0=bias  1=gelu(bias)  2=C = aux + sigmoid(g)*(acc+bias)  3=+aux     */
template<int EPI>
__global__ __launch_bounds__(256)
void sgemm(const float* __restrict__ A, const float* __restrict__ W,
           const float* __restrict__ bias, float* __restrict__ C,
           int M, int N, int K,
           const float* __restrict__ aux, const float* __restrict__ gptr)
{
    __shared__ float As[16][128];
    __shared__ float Ws[16][128];
    int tid = threadIdx.x;
    int tx = tid & 15, ty = tid >> 4;
    int m0 = blockIdx.y * 128;
    int n0 = blockIdx.x * 128;
    int lr = tid >> 2;            /* 0..63 */
    int lc = (tid & 3) << 2;      /* 0,4,8,12 */

    float acc[8][8];
#pragma unroll
    for (int i = 0; i < 8; i++)
#pragma unroll
        for (int j = 0; j < 8; j++) acc[i][j] = 0.f;

    for (int kt = 0; kt < K; kt += 16) {
        float4 a0 = *(const float4*)(A + (size_t)(m0+lr   )*K + kt + lc);
        float4 a1 = *(const float4*)(A + (size_t)(m0+lr+64)*K + kt + lc);
        float4 w0 = *(const float4*)(W + (size_t)(n0+lr   )*K + kt + lc);
        float4 w1 = *(const float4*)(W + (size_t)(n0+lr+64)*K + kt + lc);
        As[lc+0][lr] = a0.x; As[lc+1][lr] = a0.y; As[lc+2][lr] = a0.z; As[lc+3][lr] = a0.w;
        As[lc+0][lr+64] = a1.x; As[lc+1][lr+64] = a1.y; As[lc+2][lr+64] = a1.z; As[lc+3][lr+64] = a1.w;
        Ws[lc+0][lr] = w0.x; Ws[lc+1][lr] = w0.y; Ws[lc+2][lr] = w0.z; Ws[lc+3][lr] = w0.w;
        Ws[lc+0][lr+64] = w1.x; Ws[lc+1][lr+64] = w1.y; Ws[lc+2][lr+64] = w1.z; Ws[lc+3][lr+64] = w1.w;
        __syncthreads();
#pragma unroll
        for (int kk = 0; kk < 16; kk++) {
            float a[8], b[8];
#pragma unroll
            for (int i = 0; i < 8; i++) a[i] = As[kk][ty*8 + i];
#pragma unroll
            for (int j = 0; j < 8; j++) b[j] = Ws[kk][tx*8 + j];
#pragma unroll
            for (int i = 0; i < 8; i++)
#pragma unroll
                for (int j = 0; j < 8; j++) acc[i][j] += a[i]*b[j];
        }
        __syncthreads();
    }

    float sg = 0.f;
    if (EPI == 2) sg = 1.0f / (1.0f + expf(-gptr[0]));

#pragma unroll
    for (int i = 0; i < 8; i++) {
        int m = m0 + ty*8 + i;
#pragma unroll
        for (int j = 0; j < 8; j++) {
            int n = n0 + tx*8 + j;
            float v = acc[i][j] + bias[n];
            if (EPI == 1) v = 0.5f * v * (1.0f + erff(v * 0.70710678118654752f));
            if (EPI == 2) v = aux[(size_t)m*N + n] + sg * v;
            if (EPI == 3) v = v + aux[(size_t)m*N + n];
            C[(size_t)m*N + n] = v;
        }
    }
}

/* ------------------------- self-attention (per b,h) ---------------------- */
__global__ void attn_kernel()
{
    int h = blockIdx.x, b = blockIdx.y;
    int t = threadIdx.x;                  /* 160 threads; 153 active */
    __shared__ float ksh[64][64];
    __shared__ float vsh[64][64];

    float q[HD], acc[HD];
    float m = -1e30f, l = 0.f;
    const float* qbase = g_qkv + (size_t)(b*KTOP)*1536 + h*HD;
    if (t < KTOP) {
#pragma unroll
        for (int c = 0; c < HD; c++) q[c] = qbase[(size_t)t*1536 + c];
    }
#pragma unroll
    for (int c = 0; c < HD; c++) acc[c] = 0.f;

    for (int s0 = 0; s0 < KTOP; s0 += 64) {
        int sc = min(64, KTOP - s0);
        __syncthreads();
        for (int i = threadIdx.x; i < sc*64; i += blockDim.x) {
            int s = i >> 6, c = i & 63;
            const float* kb = g_qkv + (size_t)(b*KTOP + s0 + s)*1536;
            ksh[s][c] = kb[512  + h*HD + c];
            vsh[s][c] = kb[1024 + h*HD + c];
        }
        __syncthreads();
        if (t < KTOP) {
            for (int s = 0; s < sc; s++) {
                float dot = 0.f;
#pragma unroll
                for (int c = 0; c < HD; c++) dot += q[c]*ksh[s][c];
                float sv = dot * 0.125f;
                float mn = fmaxf(m, sv);
                float corr = __expf(m - mn);
                float p    = __expf(sv - mn);
                l = l*corr + p;
#pragma unroll
                for (int c = 0; c < HD; c++) acc[c] = acc[c]*corr + p*vsh[s][c];
                m = mn;
            }
        }
    }
    if (t < KTOP) {
        float invl = 1.0f / l;
        float* outp = g_sa + (size_t)(b*KTOP + t)*DIM + h*HD;
#pragma unroll
        for (int c = 0; c < HD; c++) outp[c] = acc[c]*invl;
    }
}

/* --------------------------- BatchNorm (train) --------------------------- */
__global__ void bn_partial()
{
    int col = threadIdx.x;                 /* 512 */
    int r0 = blockIdx.x * 128;
    float s1 = 0.f, s2 = 0.f;
    for (int r = 0; r < 128; r++) {
        float x = g_h[(size_t)(r0 + r)*512 + col];
        s1 += x; s2 += x*x;
    }
    g_p1[blockIdx.x*512 + col] = s1;
    g_p2[blockIdx.x*512 + col] = s2;
}

__global__ void bn_final()
{
    int c = threadIdx.x;                   /* 512 */
    float s1 = 0.f, s2 = 0.f;
    for (int i = 0; i < NBLK_BN; i++) { s1 += g_p1[i*512+c]; s2 += g_p2[i*512+c]; }
    float mean = s1 / (float)BKTOK;
    float var  = s2 / (float)BKTOK - mean*mean;
    g_mu[c]   = mean;
    g_rstd[c] = rsqrtf(var + 1e-5f);
}

__global__ void bn_apply(const float* __restrict__ bnw, const float* __restrict__ bnb)
{
    size_t i = (size_t)blockIdx.x*blockDim.x + threadIdx.x;
    if (i < (size_t)BKTOK*512) {
        int c = (int)(i & 511);
        float x = g_h[i];
        x = (x - g_mu[c]) * g_rstd[c] * bnw[c] + bnb[c];
        g_h[i] = fmaxf(x, 0.f);
    }
}

/* ------------------------ variable-length max pool ----------------------- */
__global__ void pool_kernel(float* __restrict__ out)
{
    int b = blockIdx.x;
    int tid = threadIdx.x;                 /* 256 */
    int L = g_lens[b];
    float mx[4] = {-1e30f, -1e30f, -1e30f, -1e30f};
    const float* fp = g_feat + (size_t)b*KTOP*EDIM;
    for (int t = 0; t < L; t++) {
#pragma unroll
        for (int i = 0; i < 4; i++)
            mx[i] = fmaxf(mx[i], fp[(size_t)t*EDIM + tid + i*256]);
    }
#pragma unroll
    for (int i = 0; i < 4; i++)
        out[(size_t)b*EDIM + tid + i*256] = mx[i];
}

/* ------------------------------- launcher -------------------------------- */
extern "C" void kernel_launch(void* const* d_in, const int* in_sizes, int n_in,
                              void* d_out, int out_size)
{
    const float* features = (const float*)d_in[0];
    const int*   text     = (const int*)  d_in[1];
    const float* atten    = (const float*)d_in[2];
    const float* ln_q_w   = (const float*)d_in[3];
    const float* ln_q_b   = (const float*)d_in[4];
    const float* sa_in_w  = (const float*)d_in[5];
    const float* sa_in_b  = (const float*)d_in[6];
    const float* sa_out_w = (const float*)d_in[7];
    const float* sa_out_b = (const float*)d_in[8];
    const float* ref_w1   = (const float*)d_in[9];
    const float* ref_b1   = (const float*)d_in[10];
    const float* ref_w2   = (const float*)d_in[11];
    const float* ref_b2   = (const float*)d_in[12];
    const float* gscal    = (const float*)d_in[13];
    const float* lin_w    = (const float*)d_in[14];
    const float* lin_b    = (const float*)d_in[15];
    const float* mlp_w1   = (const float*)d_in[16];
    const float* mlp_b1   = (const float*)d_in[17];
    const float* bn_w     = (const float*)d_in[18];
    const float* bn_b     = (const float*)d_in[19];
    const float* mlp_w2   = (const float*)d_in[20];
    const float* mlp_b2   = (const float*)d_in[21];
    float* out = (float*)d_out;

    float *p_tok, *p_q, *p_qkv, *p_sa, *p_y1, *p_cap, *p_h, *p_feat;
    cudaGetSymbolAddress((void**)&p_tok,  g_tok);
    cudaGetSymbolAddress((void**)&p_q,    g_q);
    cudaGetSymbolAddress((void**)&p_qkv,  g_qkv);
    cudaGetSymbolAddress((void**)&p_sa,   g_sa);
    cudaGetSymbolAddress((void**)&p_y1,   g_y1);
    cudaGetSymbolAddress((void**)&p_cap,  g_cap);
    cudaGetSymbolAddress((void**)&p_h,    g_h);
    cudaGetSymbolAddress((void**)&p_feat, g_feat);

    const int MROWS = BKTOK;             /* 39168 = 306*128 */

    topk_kernel<<<BATCH, NT>>>(text, atten);
    gather_ln_kernel<<<BKTOK, 128>>>(features, ln_q_w, ln_q_b);

    /* qkv = LN(tok) @ sa_in_w^T + b */
    sgemm<0><<<dim3(1536/128, MROWS/128), 256>>>(p_q, sa_in_w, sa_in_b, p_qkv,
                                                 MROWS, 1536, 512, nullptr, nullptr);
    attn_kernel<<<dim3(NHEADS, BATCH), 160>>>();

    /* sa2 = sa @ sa_out_w^T + b   (into g_q, which is free now) */
    sgemm<0><<<dim3(512/128, MROWS/128), 256>>>(p_sa, sa_out_w, sa_out_b, p_q,
                                                MROWS, 512, 512, nullptr, nullptr);
    /* y1 = gelu(sa2 @ ref_w1^T + b) */
    sgemm<1><<<dim3(1024/128, MROWS/128), 256>>>(p_q, ref_w1, ref_b1, p_y1,
                                                 MROWS, 1024, 512, nullptr, nullptr);
    /* tok += sigmoid(g) * (y1 @ ref_w2^T + b) */
    sgemm<2><<<dim3(512/128, MROWS/128), 256>>>(p_y1, ref_w2, ref_b2, p_tok,
                                                MROWS, 512, 1024, p_tok, gscal);
    /* cap = tok @ lin_w^T + b */
    sgemm<0><<<dim3(1024/128, MROWS/128), 256>>>(p_tok, lin_w, lin_b, p_cap,
                                                 MROWS, 1024, 512, nullptr, nullptr);
    /* h = tok @ mlp_w1^T + b */
    sgemm<0><<<dim3(512/128, MROWS/128), 256>>>(p_tok, mlp_w1, mlp_b1, p_h,
                                                MROWS, 512, 512, nullptr, nullptr);
    bn_partial<<<NBLK_BN, 512>>>();
    bn_final<<<1, 512>>>();
    bn_apply<<<(int)(((size_t)BKTOK*512 + 255)/256), 256>>>(bn_w, bn_b);

    /* feat = relu_bn(h) @ mlp_w2^T + b + cap */
    sgemm<3><<<dim3(1024/128, MROWS/128), 256>>>(p_h, mlp_w2, mlp_b2, p_feat,
                                                 MROWS, 1024, 512, p_cap, nullptr);
    pool_kernel<<<BATCH, 256>>>(out);
}

// round 3
// speedup vs baseline: 1.0009x; 1.0009x over previous
#include <cuda_runtime.h>
#include <math.h>

#define BATCH 256
#define NT 512
#define DIM 512
#define KTOP 153
#define BKTOK (BATCH*KTOP)      /* 39168 = 306*128 */
#define EDIM 1024
#define NHEADS 8
#define HD 64
#define NBLK_BN 306

/* ---------------- scratch (device globals; no allocation) ---------------- */
__device__ int   g_idx[BKTOK];
__device__ int   g_lens[BATCH];
__device__ float g_tok[(size_t)BKTOK*DIM];
__device__ float g_q[(size_t)BKTOK*DIM];          /* LN out, later reused as sa2 */
__device__ float g_qkv[(size_t)BKTOK*3*DIM];
__device__ float g_sa[(size_t)BKTOK*DIM];
__device__ float g_y1[(size_t)BKTOK*2*DIM];
__device__ float g_cap[(size_t)BKTOK*EDIM];
__device__ float g_h[(size_t)BKTOK*DIM];
__device__ float g_feat[(size_t)BKTOK*EDIM];
__device__ float g_p1[NBLK_BN*512];
__device__ float g_p2[NBLK_BN*512];
__device__ float g_mu[512];
__device__ float g_rstd[512];

/* ---------------- top-k selection (exact jax.lax.top_k order) ------------ */
__global__ void topk_kernel(const int* __restrict__ text,
                            const float* __restrict__ atten)
{
    int b = blockIdx.x;
    int t = threadIdx.x;            /* 512 threads */
    __shared__ float sval[NT];
    __shared__ int   sidx[NT];
    __shared__ int   red[NT];

    int tv = text[b*NT + t];

    /* eos = argmax(text), first occurrence of max */
    red[t] = (tv << 10) | (NT - 1 - t);
    __syncthreads();
    for (int s = NT/2; s > 0; s >>= 1) {
        if (t < s) red[t] = max(red[t], red[t+s]);
        __syncthreads();
    }
    int eos = NT - 1 - (red[0] & 1023);
    __syncthreads();

    /* lengths = nnz - 2 */
    red[t] = (tv != 0) ? 1 : 0;
    __syncthreads();
    for (int s = NT/2; s > 0; s >>= 1) {
        if (t < s) red[t] += red[t+s];
        __syncthreads();
    }
    int nz = red[0];
    __syncthreads();

    /* row with BOS/EOS suppressed, pad-masked */
    float v;
    if (t == 0 || t == eos) v = -1.0f;
    else                    v = atten[((size_t)b*NT + eos)*NT + t];
    if (tv == 0) v = 0.0f;

    sval[t] = v; sidx[t] = t;
    __syncthreads();

    /* bitonic sort, key = (val desc, idx asc)  — matches jax top_k ties */
    for (int ksz = 2; ksz <= NT; ksz <<= 1) {
        for (int j = ksz >> 1; j > 0; j >>= 1) {
            int ixj = t ^ j;
            if (ixj > t) {
                float va = sval[t], vb = sval[ixj];
                int   ia = sidx[t], ib = sidx[ixj];
                bool aBefore = (va > vb) || (va == vb && ia < ib);
                bool desc = ((t & ksz) == 0);
                if (desc ? !aBefore : aBefore) {
                    sval[t] = vb; sval[ixj] = va;
                    sidx[t] = ib; sidx[ixj] = ia;
                }
            }
            __syncthreads();
        }
    }
    if (t < KTOP) g_idx[b*KTOP + t] = sidx[t];
    if (t == 0) {
        int l = nz - 2;
        if (l > KTOP) l = KTOP;
        if (l < 1) l = 1;
        g_lens[b] = l;
    }
}

/* ---------- gather + L2 normalize + LayerNorm (fused, one pass) ---------- */
__global__ void gather_ln_kernel(const float* __restrict__ features,
                                 const float* __restrict__ lnw,
                                 const float* __restrict__ lnb)
{
    int token = blockIdx.x;               /* 0..BKTOK-1 */
    int b = token / KTOP;
    int src = g_idx[token];
    int tid = threadIdx.x;                /* 128 threads */
    const float* f = features + ((size_t)b*NT + src)*DIM;

    float v[4];
    float s1 = 0.f, s2 = 0.f;
#pragma unroll
    for (int i = 0; i < 4; i++) {
        v[i] = f[tid + i*128];
        s1 += v[i];
        s2 += v[i]*v[i];
    }
    __shared__ float r1[128], r2[128];
    r1[tid] = s1; r2[tid] = s2;
    __syncthreads();
    for (int s = 64; s > 0; s >>= 1) {
        if (tid < s) { r1[tid] += r1[tid+s]; r2[tid] += r2[tid+s]; }
        __syncthreads();
    }
    float sumf = r1[0], ss = r2[0];
    float inv  = 1.0f / (sqrtf(ss) + 1e-6f);
    float mean = sumf * inv * (1.0f/DIM);
    float et2  = ss * inv * inv * (1.0f/DIM);
    float var  = et2 - mean*mean;
    float rstd = rsqrtf(var + 1e-5f);

    float* tokp = g_tok + (size_t)token*DIM;
    float* qp   = g_q   + (size_t)token*DIM;
#pragma unroll
    for (int i = 0; i < 4; i++) {
        int c = tid + i*128;
        float tvv = v[i] * inv;
        tokp[c] = tvv;
        qp[c]   = (tvv - mean) * rstd * lnw[c] + lnb[c];
    }
}

/* --------------------- SGEMM: C = A @ W^T + bias (+epi) ------------------ */
/* A [M,K] row-major, W [N,K] row-major. M%128==0, N%128==0, K%16==0.       */
/* EPI: 0=bias  1=gelu(bias)  2=C = aux + sigmoid(g)*(acc+bias)  3=+aux     */
template<int EPI>
__global__ __launch_bounds__(256)
void sgemm(const float* __restrict__ A, const float* __restrict__ W,
           const float* __restrict__ bias, float* __restrict__ C,
           int M, int N, int K,
           const float* __restrict__ aux, const float* __restrict__ gptr)
{
    __shared__ float As[16][128];
    __shared__ float Ws[16][128];
    int tid = threadIdx.x;
    int tx = tid & 15, ty = tid >> 4;
    int m0 = blockIdx.y * 128;
    int n0 = blockIdx.x * 128;
    int lr = tid >> 2;            /* 0..63 */
    int lc = (tid & 3) << 2;      /* 0,4,8,12 */

    float acc[8][8];
#pragma unroll
    for (int i = 0; i < 8; i++)
#pragma unroll
        for (int j = 0; j < 8; j++) acc[i][j] = 0.f;

    for (int kt = 0; kt < K; kt += 16) {
        float4 a0 = *(const float4*)(A + (size_t)(m0+lr   )*K + kt + lc);
        float4 a1 = *(const float4*)(A + (size_t)(m0+lr+64)*K + kt + lc);
        float4 w0 = *(const float4*)(W + (size_t)(n0+lr   )*K + kt + lc);
        float4 w1 = *(const float4*)(W + (size_t)(n0+lr+64)*K + kt + lc);
        As[lc+0][lr] = a0.x; As[lc+1][lr] = a0.y; As[lc+2][lr] = a0.z; As[lc+3][lr] = a0.w;
        As[lc+0][lr+64] = a1.x; As[lc+1][lr+64] = a1.y; As[lc+2][lr+64] = a1.z; As[lc+3][lr+64] = a1.w;
        Ws[lc+0][lr] = w0.x; Ws[lc+1][lr] = w0.y; Ws[lc+2][lr] = w0.z; Ws[lc+3][lr] = w0.w;
        Ws[lc+0][lr+64] = w1.x; Ws[lc+1][lr+64] = w1.y; Ws[lc+2][lr+64] = w1.z; Ws[lc+3][lr+64] = w1.w;
        __syncthreads();
#pragma unroll
        for (int kk = 0; kk < 16; kk++) {
            float a[8], b[8];
#pragma unroll
            for (int i = 0; i < 8; i++) a[i] = As[kk][ty*8 + i];
#pragma unroll
            for (int j = 0; j < 8; j++) b[j] = Ws[kk][tx*8 + j];
#pragma unroll
            for (int i = 0; i < 8; i++)
#pragma unroll
                for (int j = 0; j < 8; j++) acc[i][j] += a[i]*b[j];
        }
        __syncthreads();
    }

    float sg = 0.f;
    if (EPI == 2) sg = 1.0f / (1.0f + expf(-gptr[0]));

#pragma unroll
    for (int i = 0; i < 8; i++) {
        int m = m0 + ty*8 + i;
#pragma unroll
        for (int j = 0; j < 8; j++) {
            int n = n0 + tx*8 + j;
            float v = acc[i][j] + bias[n];
            if (EPI == 1) v = 0.5f * v * (1.0f + erff(v * 0.70710678118654752f));
            if (EPI == 2) v = aux[(size_t)m*N + n] + sg * v;
            if (EPI == 3) v = v + aux[(size_t)m*N + n];
            C[(size_t)m*N + n] = v;
        }
    }
}

/* ------------------------- self-attention (per b,h) ---------------------- */
__global__ void attn_kernel()
{
    int h = blockIdx.x, b = blockIdx.y;
    int t = threadIdx.x;                  /* 160 threads; 153 active */
    __shared__ float ksh[64][64];
    __shared__ float vsh[64][64];

    float q[HD], acc[HD];
    float m = -1e30f, l = 0.f;
    const float* qbase = g_qkv + (size_t)(b*KTOP)*1536 + h*HD;
    if (t < KTOP) {
#pragma unroll
        for (int c = 0; c < HD; c++) q[c] = qbase[(size_t)t*1536 + c];
    }
#pragma unroll
    for (int c = 0; c < HD; c++) acc[c] = 0.f;

    for (int s0 = 0; s0 < KTOP; s0 += 64) {
        int sc = min(64, KTOP - s0);
        __syncthreads();
        for (int i = threadIdx.x; i < sc*64; i += blockDim.x) {
            int s = i >> 6, c = i & 63;
            const float* kb = g_qkv + (size_t)(b*KTOP + s0 + s)*1536;
            ksh[s][c] = kb[512  + h*HD + c];
            vsh[s][c] = kb[1024 + h*HD + c];
        }
        __syncthreads();
        if (t < KTOP) {
            for (int s = 0; s < sc; s++) {
                float dot = 0.f;
#pragma unroll
                for (int c = 0; c < HD; c++) dot += q[c]*ksh[s][c];
                float sv = dot * 0.125f;
                float mn = fmaxf(m, sv);
                float corr = __expf(m - mn);
                float p    = __expf(sv - mn);
                l = l*corr + p;
#pragma unroll
                for (int c = 0; c < HD; c++) acc[c] = acc[c]*corr + p*vsh[s][c];
                m = mn;
            }
        }
    }
    if (t < KTOP) {
        float invl = 1.0f / l;
        float* outp = g_sa + (size_t)(b*KTOP + t)*DIM + h*HD;
#pragma unroll
        for (int c = 0; c < HD; c++) outp[c] = acc[c]*invl;
    }
}

/* --------------------------- BatchNorm (train) --------------------------- */
__global__ void bn_partial()
{
    int col = threadIdx.x;                 /* 512 */
    int r0 = blockIdx.x * 128;
    float s1 = 0.f, s2 = 0.f;
    for (int r = 0; r < 128; r++) {
        float x = g_h[(size_t)(r0 + r)*512 + col];
        s1 += x; s2 += x*x;
    }
    g_p1[blockIdx.x*512 + col] = s1;
    g_p2[blockIdx.x*512 + col] = s2;
}

__global__ void bn_final()
{
    int c = threadIdx.x;                   /* 512 */
    float s1 = 0.f, s2 = 0.f;
    for (int i = 0; i < NBLK_BN; i++) { s1 += g_p1[i*512+c]; s2 += g_p2[i*512+c]; }
    float mean = s1 / (float)BKTOK;
    float var  = s2 / (float)BKTOK - mean*mean;
    g_mu[c]   = mean;
    g_rstd[c] = rsqrtf(var + 1e-5f);
}

__global__ void bn_apply(const float* __restrict__ bnw, const float* __restrict__ bnb)
{
    size_t i = (size_t)blockIdx.x*blockDim.x + threadIdx.x;
    if (i < (size_t)BKTOK*512) {
        int c = (int)(i & 511);
        float x = g_h[i];
        x = (x - g_mu[c]) * g_rstd[c] * bnw[c] + bnb[c];
        g_h[i] = fmaxf(x, 0.f);
    }
}

/* ------------------------ variable-length max pool ----------------------- */
__global__ void pool_kernel(float* __restrict__ out)
{
    int b = blockIdx.x;
    int tid = threadIdx.x;                 /* 256 */
    int L = g_lens[b];
    float mx[4] = {-1e30f, -1e30f, -1e30f, -1e30f};
    const float* fp = g_feat + (size_t)b*KTOP*EDIM;
    for (int t = 0; t < L; t++) {
#pragma unroll
        for (int i = 0; i < 4; i++)
            mx[i] = fmaxf(mx[i], fp[(size_t)t*EDIM + tid + i*256]);
    }
#pragma unroll
    for (int i = 0; i < 4; i++)
        out[(size_t)b*EDIM + tid + i*256] = mx[i];
}

/* ------------------------------- launcher -------------------------------- */
extern "C" void kernel_launch(void* const* d_in, const int* in_sizes, int n_in,
                              void* d_out, int out_size)
{
    const float* features = (const float*)d_in[0];
    const int*   text     = (const int*)  d_in[1];
    const float* atten    = (const float*)d_in[2];
    const float* ln_q_w   = (const float*)d_in[3];
    const float* ln_q_b   = (const float*)d_in[4];
    const float* sa_in_w  = (const float*)d_in[5];
    const float* sa_in_b  = (const float*)d_in[6];
    const float* sa_out_w = (const float*)d_in[7];
    const float* sa_out_b = (const float*)d_in[8];
    const float* ref_w1   = (const float*)d_in[9];
    const float* ref_b1   = (const float*)d_in[10];
    const float* ref_w2   = (const float*)d_in[11];
    const float* ref_b2   = (const float*)d_in[12];
    const float* gscal    = (const float*)d_in[13];
    const float* lin_w    = (const float*)d_in[14];
    const float* lin_b    = (const float*)d_in[15];
    const float* mlp_w1   = (const float*)d_in[16];
    const float* mlp_b1   = (const float*)d_in[17];
    const float* bn_w     = (const float*)d_in[18];
    const float* bn_b     = (const float*)d_in[19];
    const float* mlp_w2   = (const float*)d_in[20];
    const float* mlp_b2   = (const float*)d_in[21];
    float* out = (float*)d_out;

    float *p_tok, *p_q, *p_qkv, *p_sa, *p_y1, *p_cap, *p_h, *p_feat;
    cudaGetSymbolAddress((void**)&p_tok,  g_tok);
    cudaGetSymbolAddress((void**)&p_q,    g_q);
    cudaGetSymbolAddress((void**)&p_qkv,  g_qkv);
    cudaGetSymbolAddress((void**)&p_sa,   g_sa);
    cudaGetSymbolAddress((void**)&p_y1,   g_y1);
    cudaGetSymbolAddress((void**)&p_cap,  g_cap);
    cudaGetSymbolAddress((void**)&p_h,    g_h);
    cudaGetSymbolAddress((void**)&p_feat, g_feat);

    const int MROWS = BKTOK;             /* 39168 = 306*128 */

    topk_kernel<<<BATCH, NT>>>(text, atten);
    gather_ln_kernel<<<BKTOK, 128>>>(features, ln_q_w, ln_q_b);

    /* qkv = LN(tok) @ sa_in_w^T + b */
    sgemm<0><<<dim3(1536/128, MROWS/128), 256>>>(p_q, sa_in_w, sa_in_b, p_qkv,
                                                 MROWS, 1536, 512, nullptr, nullptr);
    attn_kernel<<<dim3(NHEADS, BATCH), 160>>>();

    /* sa2 = sa @ sa_out_w^T + b   (into g_q, which is free now) */
    sgemm<0><<<dim3(512/128, MROWS/128), 256>>>(p_sa, sa_out_w, sa_out_b, p_q,
                                                MROWS, 512, 512, nullptr, nullptr);
    /* y1 = gelu(sa2 @ ref_w1^T + b) */
    sgemm<1><<<dim3(1024/128, MROWS/128), 256>>>(p_q, ref_w1, ref_b1, p_y1,
                                                 MROWS, 1024, 512, nullptr, nullptr);
    /* tok += sigmoid(g) * (y1 @ ref_w2^T + b) */
    sgemm<2><<<dim3(512/128, MROWS/128), 256>>>(p_y1, ref_w2, ref_b2, p_tok,
                                                MROWS, 512, 1024, p_tok, gscal);
    /* cap = tok @ lin_w^T + b */
    sgemm<0><<<dim3(1024/128, MROWS/128), 256>>>(p_tok, lin_w, lin_b, p_cap,
                                                 MROWS, 1024, 512, nullptr, nullptr);
    /* h = tok @ mlp_w1^T + b */
    sgemm<0><<<dim3(512/128, MROWS/128), 256>>>(p_tok, mlp_w1, mlp_b1, p_h,
                                                MROWS, 512, 512, nullptr, nullptr);
    bn_partial<<<NBLK_BN, 512>>>();
    bn_final<<<1, 512>>>();
    bn_apply<<<(int)(((size_t)BKTOK*512 + 255)/256), 256>>>(bn_w, bn_b);

    /* feat = relu_bn(h) @ mlp_w2^T + b + cap */
    sgemm<3><<<dim3(1024/128, MROWS/128), 256>>>(p_h, mlp_w2, mlp_b2, p_feat,
                                                 MROWS, 1024, 512, p_cap, nullptr);
    pool_kernel<<<BATCH, 256>>>(out);
}

// round 5
// speedup vs baseline: 1.9154x; 1.9137x over previous
#include <cuda_runtime.h>
#include <math.h>
#include <stdint.h>

#define BATCH 256
#define NT 512
#define DIM 512
#define KTOP 153
#define BKTOK (BATCH*KTOP)      /* 39168 = 306*128 */
#define EDIM 1024
#define NHEADS 8
#define HD 64
#define NBLK_BN 306

/* GEMM tiling */
#define BM 128
#define BN 128
#define BK 32
#define ASTRIDE 36                       /* floats per smem row (conflict-free frags) */
#define ATILE (128*ASTRIDE)              /* 4608 u32 per operand tile */
#define STAGE_ELEMS (2*ATILE)            /* A + W per stage */
#define GEMM_SMEM (2*STAGE_ELEMS*4)      /* 73728 bytes, double buffered */

/* ---------------- scratch (device globals; no allocation) ---------------- */
__device__ int   g_idx[BKTOK];
__device__ int   g_lens[BATCH];
__device__ float g_tok[(size_t)BKTOK*DIM];
__device__ float g_q[(size_t)BKTOK*DIM];          /* LN out, later reused as sa2 */
__device__ float g_qkv[(size_t)BKTOK*3*DIM];
__device__ float g_sa[(size_t)BKTOK*DIM];
__device__ float g_y1[(size_t)BKTOK*2*DIM];
__device__ float g_cap[(size_t)BKTOK*EDIM];
__device__ float g_h[(size_t)BKTOK*DIM];
__device__ float g_feat[(size_t)BKTOK*EDIM];
__device__ float g_p1[NBLK_BN*512];
__device__ float g_p2[NBLK_BN*512];
__device__ float g_mu[512];
__device__ float g_rstd[512];

/* ------------------------------ helpers ---------------------------------- */
__device__ __forceinline__ uint32_t f2tf(float f) {
    uint32_t u;
    asm("cvt.rna.tf32.f32 %0, %1;" : "=r"(u) : "f"(f));
    return u;
}

__device__ __forceinline__ void mma_tf32(float& d0, float& d1, float& d2, float& d3,
                                         uint32_t a0, uint32_t a1, uint32_t a2, uint32_t a3,
                                         uint32_t b0, uint32_t b1)
{
    asm volatile(
        "mma.sync.aligned.m16n8k8.row.col.f32.tf32.tf32.f32 "
        "{%0,%1,%2,%3}, {%4,%5,%6,%7}, {%8,%9}, {%0,%1,%2,%3};"
        : "+f"(d0), "+f"(d1), "+f"(d2), "+f"(d3)
        : "r"(a0), "r"(a1), "r"(a2), "r"(a3), "r"(b0), "r"(b1));
}

/* -------- tensor-core tf32 GEMM: C[M,N] = A[M,K] @ W[N,K]^T + bias ------- */
/* EPI: 0=bias 1=gelu(bias) 2=C=aux+sigmoid(g)*(acc+bias) 3=acc+bias+aux     */
template<int EPI>
__global__ __launch_bounds__(256, 1)
void gemm_mma(const float* __restrict__ A, const float* __restrict__ W,
              const float* __restrict__ bias, float* __restrict__ C,
              int M, int N, int K,
              const float* __restrict__ aux, const float* __restrict__ gptr)
{
    extern __shared__ uint32_t sm[];
    const int tid  = threadIdx.x;
    const int wid  = tid >> 5;
    const int lane = tid & 31;
    const int gid  = lane >> 2;          /* 0..7  */
    const int tig  = lane & 3;           /* 0..3  */
    const int wm   = (wid & 1) * 64;     /* warp m base in tile */
    const int wn   = (wid >> 1) * 32;    /* warp n base in tile */
    const int m0   = blockIdx.y * BM;
    const int n0   = blockIdx.x * BN;

    /* global load pattern: 256 threads, rows (tid>>3)+32p, float4 col (tid&7) */
    const int lrow = tid >> 3;
    const int lc4  = tid & 7;
    const float* Ag = A + (size_t)(m0 + lrow) * K + lc4 * 4;
    const float* Wg = W + (size_t)(n0 + lrow) * K + lc4 * 4;
    const size_t rstep = (size_t)32 * K;

    float acc[4][4][4];
#pragma unroll
    for (int i = 0; i < 4; i++)
#pragma unroll
        for (int j = 0; j < 4; j++)
#pragma unroll
            for (int c = 0; c < 4; c++) acc[i][j][c] = 0.f;

    const int ntile = K >> 5;
    float4 pa[4], pw[4];

    /* preload tile 0 */
#pragma unroll
    for (int p = 0; p < 4; p++) {
        pa[p] = *(const float4*)(Ag + p * rstep);
        pw[p] = *(const float4*)(Wg + p * rstep);
    }
    {
        uint32_t* dA = sm + lrow * ASTRIDE + lc4 * 4;
        uint32_t* dW = dA + ATILE;
#pragma unroll
        for (int p = 0; p < 4; p++) {
            uint4 ua = make_uint4(f2tf(pa[p].x), f2tf(pa[p].y), f2tf(pa[p].z), f2tf(pa[p].w));
            uint4 uw = make_uint4(f2tf(pw[p].x), f2tf(pw[p].y), f2tf(pw[p].z), f2tf(pw[p].w));
            *(uint4*)(dA + p * 32 * ASTRIDE) = ua;
            *(uint4*)(dW + p * 32 * ASTRIDE) = uw;
        }
    }
    __syncthreads();

    int cur = 0;
    for (int kt = 0; kt < ntile; kt++) {
        if (kt + 1 < ntile) {
            const float* ga = Ag + (kt + 1) * 32;
            const float* gw = Wg + (kt + 1) * 32;
#pragma unroll
            for (int p = 0; p < 4; p++) {
                pa[p] = *(const float4*)(ga + p * rstep);
                pw[p] = *(const float4*)(gw + p * rstep);
            }
        }

        /* compute current stage */
        const uint32_t* smA = sm + cur * STAGE_ELEMS;
        const uint32_t* smW = smA + ATILE;
#pragma unroll
        for (int ks = 0; ks < 32; ks += 8) {
            uint32_t af[4][4], bf[4][2];
#pragma unroll
            for (int mt = 0; mt < 4; mt++) {
                const uint32_t* p = smA + (wm + mt * 16 + gid) * ASTRIDE + ks + tig;
                af[mt][0] = p[0];
                af[mt][1] = p[8 * ASTRIDE];
                af[mt][2] = p[4];
                af[mt][3] = p[8 * ASTRIDE + 4];
            }
#pragma unroll
            for (int nt = 0; nt < 4; nt++) {
                const uint32_t* p = smW + (wn + nt * 8 + gid) * ASTRIDE + ks + tig;
                bf[nt][0] = p[0];
                bf[nt][1] = p[4];
            }
#pragma unroll
            for (int mt = 0; mt < 4; mt++)
#pragma unroll
                for (int nt = 0; nt < 4; nt++)
                    mma_tf32(acc[mt][nt][0], acc[mt][nt][1], acc[mt][nt][2], acc[mt][nt][3],
                             af[mt][0], af[mt][1], af[mt][2], af[mt][3],
                             bf[nt][0], bf[nt][1]);
        }

        if (kt + 1 < ntile) {
            uint32_t* dA = sm + (cur ^ 1) * STAGE_ELEMS + lrow * ASTRIDE + lc4 * 4;
            uint32_t* dW = dA + ATILE;
#pragma unroll
            for (int p = 0; p < 4; p++) {
                uint4 ua = make_uint4(f2tf(pa[p].x), f2tf(pa[p].y), f2tf(pa[p].z), f2tf(pa[p].w));
                uint4 uw = make_uint4(f2tf(pw[p].x), f2tf(pw[p].y), f2tf(pw[p].z), f2tf(pw[p].w));
                *(uint4*)(dA + p * 32 * ASTRIDE) = ua;
                *(uint4*)(dW + p * 32 * ASTRIDE) = uw;
            }
        }
        __syncthreads();
        cur ^= 1;
    }

    /* epilogue: direct float2 stores with fused op */
    float sg = 0.f;
    if (EPI == 2) sg = 1.0f / (1.0f + expf(-gptr[0]));

#pragma unroll
    for (int mt = 0; mt < 4; mt++) {
#pragma unroll
        for (int nt = 0; nt < 4; nt++) {
            int r  = m0 + wm + mt * 16 + gid;
            int cc = n0 + wn + nt * 8 + 2 * tig;
            float b0v = bias[cc], b1v = bias[cc + 1];
            float v[4];
            v[0] = acc[mt][nt][0] + b0v;
            v[1] = acc[mt][nt][1] + b1v;
            v[2] = acc[mt][nt][2] + b0v;
            v[3] = acc[mt][nt][3] + b1v;
            if (EPI == 1) {
#pragma unroll
                for (int c = 0; c < 4; c++)
                    v[c] = 0.5f * v[c] * (1.0f + erff(v[c] * 0.70710678118654752f));
            }
            if (EPI == 2) {
                const float* x0 = aux + (size_t)r * N + cc;
                const float* x1 = aux + (size_t)(r + 8) * N + cc;
                v[0] = x0[0] + sg * v[0]; v[1] = x0[1] + sg * v[1];
                v[2] = x1[0] + sg * v[2]; v[3] = x1[1] + sg * v[3];
            }
            if (EPI == 3) {
                const float* x0 = aux + (size_t)r * N + cc;
                const float* x1 = aux + (size_t)(r + 8) * N + cc;
                v[0] += x0[0]; v[1] += x0[1]; v[2] += x1[0]; v[3] += x1[1];
            }
            *(float2*)(C + (size_t)r * N + cc)       = make_float2(v[0], v[1]);
            *(float2*)(C + (size_t)(r + 8) * N + cc) = make_float2(v[2], v[3]);
        }
    }
}

/* ---------------- top-k selection (exact jax.lax.top_k order) ------------ */
__global__ void topk_kernel(const int* __restrict__ text,
                            const float* __restrict__ atten)
{
    int b = blockIdx.x;
    int t = threadIdx.x;            /* 512 threads */
    __shared__ float sval[NT];
    __shared__ int   sidx[NT];
    __shared__ int   red[NT];

    int tv = text[b*NT + t];

    red[t] = (tv << 10) | (NT - 1 - t);
    __syncthreads();
    for (int s = NT/2; s > 0; s >>= 1) {
        if (t < s) red[t] = max(red[t], red[t+s]);
        __syncthreads();
    }
    int eos = NT - 1 - (red[0] & 1023);
    __syncthreads();

    red[t] = (tv != 0) ? 1 : 0;
    __syncthreads();
    for (int s = NT/2; s > 0; s >>= 1) {
        if (t < s) red[t] += red[t+s];
        __syncthreads();
    }
    int nz = red[0];
    __syncthreads();

    float v;
    if (t == 0 || t == eos) v = -1.0f;
    else                    v = atten[((size_t)b*NT + eos)*NT + t];
    if (tv == 0) v = 0.0f;

    sval[t] = v; sidx[t] = t;
    __syncthreads();

    for (int ksz = 2; ksz <= NT; ksz <<= 1) {
        for (int j = ksz >> 1; j > 0; j >>= 1) {
            int ixj = t ^ j;
            if (ixj > t) {
                float va = sval[t], vb = sval[ixj];
                int   ia = sidx[t], ib = sidx[ixj];
                bool aBefore = (va > vb) || (va == vb && ia < ib);
                bool desc = ((t & ksz) == 0);
                if (desc ? !aBefore : aBefore) {
                    sval[t] = vb; sval[ixj] = va;
                    sidx[t] = ib; sidx[ixj] = ia;
                }
            }
            __syncthreads();
        }
    }
    if (t < KTOP) g_idx[b*KTOP + t] = sidx[t];
    if (t == 0) {
        int lnn = nz - 2;
        if (lnn > KTOP) lnn = KTOP;
        if (lnn < 1) lnn = 1;
        g_lens[b] = lnn;
    }
}

/* ---------- gather + L2 normalize + LayerNorm (fused, one pass) ---------- */
__global__ void gather_ln_kernel(const float* __restrict__ features,
                                 const float* __restrict__ lnw,
                                 const float* __restrict__ lnb)
{
    int token = blockIdx.x;
    int b = token / KTOP;
    int src = g_idx[token];
    int tid = threadIdx.x;                /* 128 threads */
    const float* f = features + ((size_t)b*NT + src)*DIM;

    float v[4];
    float s1 = 0.f, s2 = 0.f;
#pragma unroll
    for (int i = 0; i < 4; i++) {
        v[i] = f[tid + i*128];
        s1 += v[i];
        s2 += v[i]*v[i];
    }
    __shared__ float r1[128], r2[128];
    r1[tid] = s1; r2[tid] = s2;
    __syncthreads();
    for (int s = 64; s > 0; s >>= 1) {
        if (tid < s) { r1[tid] += r1[tid+s]; r2[tid] += r2[tid+s]; }
        __syncthreads();
    }
    float sumf = r1[0], ss = r2[0];
    float inv  = 1.0f / (sqrtf(ss) + 1e-6f);
    float mean = sumf * inv * (1.0f/DIM);
    float et2  = ss * inv * inv * (1.0f/DIM);
    float var  = et2 - mean*mean;
    float rstd = rsqrtf(var + 1e-5f);

    float* tokp = g_tok + (size_t)token*DIM;
    float* qp   = g_q   + (size_t)token*DIM;
#pragma unroll
    for (int i = 0; i < 4; i++) {
        int c = tid + i*128;
        float tvv = v[i] * inv;
        tokp[c] = tvv;
        qp[c]   = (tvv - mean) * rstd * lnw[c] + lnb[c];
    }
}

/* ---------------- self-attention: 4 threads per token -------------------- */
__global__ __launch_bounds__(640) void attn_kernel()
{
    int h = blockIdx.x, b = blockIdx.y;
    int tt = threadIdx.x >> 2;            /* token 0..159 */
    int qu = threadIdx.x & 3;             /* channel quarter */
    __shared__ float ksh[64][64];
    __shared__ float vsh[64][64];

    float q[16], acc[16];
    float m = -1e30f, l = 0.f;
    bool act = tt < KTOP;
    const float* qb = g_qkv + (size_t)(b*KTOP + (act ? tt : 0))*1536 + h*HD + qu*16;
#pragma unroll
    for (int c = 0; c < 16; c++) { q[c] = act ? qb[c] : 0.f; acc[c] = 0.f; }

    for (int s0 = 0; s0 < KTOP; s0 += 64) {
        int sc = min(64, KTOP - s0);
        __syncthreads();
        for (int i = threadIdx.x; i < sc*64; i += blockDim.x) {
            int s = i >> 6, c = i & 63;
            const float* kb = g_qkv + (size_t)(b*KTOP + s0 + s)*1536;
            ksh[s][c] = kb[512  + h*HD + c];
            vsh[s][c] = kb[1024 + h*HD + c];
        }
        __syncthreads();
        for (int s = 0; s < sc; s++) {
            float d = 0.f;
#pragma unroll
            for (int c = 0; c < 16; c++) d += q[c]*ksh[s][qu*16 + c];
            d += __shfl_xor_sync(0xffffffffu, d, 1);
            d += __shfl_xor_sync(0xffffffffu, d, 2);
            float sv = d * 0.125f;
            float mn = fmaxf(m, sv);
            float corr = __expf(m - mn);
            float p    = __expf(sv - mn);
            l = l*corr + p;
#pragma unroll
            for (int c = 0; c < 16; c++) acc[c] = acc[c]*corr + p*vsh[s][qu*16 + c];
            m = mn;
        }
    }
    if (act) {
        float invl = 1.0f / l;
        float* outp = g_sa + (size_t)(b*KTOP + tt)*DIM + h*HD + qu*16;
#pragma unroll
        for (int c = 0; c < 16; c++) outp[c] = acc[c]*invl;
    }
}

/* --------------------------- BatchNorm (train) --------------------------- */
__global__ void bn_partial()
{
    int col = threadIdx.x;                 /* 512 */
    int r0 = blockIdx.x * 128;
    float s1 = 0.f, s2 = 0.f;
    for (int r = 0; r < 128; r++) {
        float x = g_h[(size_t)(r0 + r)*512 + col];
        s1 += x; s2 += x*x;
    }
    g_p1[blockIdx.x*512 + col] = s1;
    g_p2[blockIdx.x*512 + col] = s2;
}

__global__ void bn_final()
{
    int c = threadIdx.x;                   /* 512 */
    float s1 = 0.f, s2 = 0.f;
    for (int i = 0; i < NBLK_BN; i++) { s1 += g_p1[i*512+c]; s2 += g_p2[i*512+c]; }
    float mean = s1 / (float)BKTOK;
    float var  = s2 / (float)BKTOK - mean*mean;
    g_mu[c]   = mean;
    g_rstd[c] = rsqrtf(var + 1e-5f);
}

__global__ void bn_apply(const float* __restrict__ bnw, const float* __restrict__ bnb)
{
    size_t i = (size_t)blockIdx.x*blockDim.x + threadIdx.x;
    if (i < (size_t)BKTOK*512) {
        int c = (int)(i & 511);
        float x = g_h[i];
        x = (x - g_mu[c]) * g_rstd[c] * bnw[c] + bnb[c];
        g_h[i] = fmaxf(x, 0.f);
    }
}

/* ------------------------ variable-length max pool ----------------------- */
__global__ void pool_kernel(float* __restrict__ out)
{
    int b = blockIdx.x;
    int tid = threadIdx.x;                 /* 256 */
    int L = g_lens[b];
    float mx[4] = {-1e30f, -1e30f, -1e30f, -1e30f};
    const float* fp = g_feat + (size_t)b*KTOP*EDIM;
    for (int t = 0; t < L; t++) {
#pragma unroll
        for (int i = 0; i < 4; i++)
            mx[i] = fmaxf(mx[i], fp[(size_t)t*EDIM + tid + i*256]);
    }
#pragma unroll
    for (int i = 0; i < 4; i++)
        out[(size_t)b*EDIM + tid + i*256] = mx[i];
}

/* ------------------------------- launcher -------------------------------- */
extern "C" void kernel_launch(void* const* d_in, const int* in_sizes, int n_in,
                              void* d_out, int out_size)
{
    const float* features = (const float*)d_in[0];
    const int*   text     = (const int*)  d_in[1];
    const float* atten    = (const float*)d_in[2];
    const float* ln_q_w   = (const float*)d_in[3];
    const float* ln_q_b   = (const float*)d_in[4];
    const float* sa_in_w  = (const float*)d_in[5];
    const float* sa_in_b  = (const float*)d_in[6];
    const float* sa_out_w = (const float*)d_in[7];
    const float* sa_out_b = (const float*)d_in[8];
    const float* ref_w1   = (const float*)d_in[9];
    const float* ref_b1   = (const float*)d_in[10];
    const float* ref_w2   = (const float*)d_in[11];
    const float* ref_b2   = (const float*)d_in[12];
    const float* gscal    = (const float*)d_in[13];
    const float* lin_w    = (const float*)d_in[14];
    const float* lin_b    = (const float*)d_in[15];
    const float* mlp_w1   = (const float*)d_in[16];
    const float* mlp_b1   = (const float*)d_in[17];
    const float* bn_w     = (const float*)d_in[18];
    const float* bn_b     = (const float*)d_in[19];
    const float* mlp_w2   = (const float*)d_in[20];
    const float* mlp_b2   = (const float*)d_in[21];
    float* out = (float*)d_out;

    float *p_tok, *p_q, *p_qkv, *p_sa, *p_y1, *p_cap, *p_h, *p_feat;
    cudaGetSymbolAddress((void**)&p_tok,  g_tok);
    cudaGetSymbolAddress((void**)&p_q,    g_q);
    cudaGetSymbolAddress((void**)&p_qkv,  g_qkv);
    cudaGetSymbolAddress((void**)&p_sa,   g_sa);
    cudaGetSymbolAddress((void**)&p_y1,   g_y1);
    cudaGetSymbolAddress((void**)&p_cap,  g_cap);
    cudaGetSymbolAddress((void**)&p_h,    g_h);
    cudaGetSymbolAddress((void**)&p_feat, g_feat);

    cudaFuncSetAttribute(gemm_mma<0>, cudaFuncAttributeMaxDynamicSharedMemorySize, GEMM_SMEM);
    cudaFuncSetAttribute(gemm_mma<1>, cudaFuncAttributeMaxDynamicSharedMemorySize, GEMM_SMEM);
    cudaFuncSetAttribute(gemm_mma<2>, cudaFuncAttributeMaxDynamicSharedMemorySize, GEMM_SMEM);
    cudaFuncSetAttribute(gemm_mma<3>, cudaFuncAttributeMaxDynamicSharedMemorySize, GEMM_SMEM);

    const int MROWS = BKTOK;             /* 39168 = 306*128 */

    topk_kernel<<<BATCH, NT>>>(text, atten);
    gather_ln_kernel<<<BKTOK, 128>>>(features, ln_q_w, ln_q_b);

    /* qkv = LN(tok) @ sa_in_w^T + b */
    gemm_mma<0><<<dim3(1536/128, MROWS/128), 256, GEMM_SMEM>>>(
        p_q, sa_in_w, sa_in_b, p_qkv, MROWS, 1536, 512, nullptr, nullptr);
    attn_kernel<<<dim3(NHEADS, BATCH), 640>>>();

    /* sa2 = sa @ sa_out_w^T + b  (into g_q) */
    gemm_mma<0><<<dim3(512/128, MROWS/128), 256, GEMM_SMEM>>>(
        p_sa, sa_out_w, sa_out_b, p_q, MROWS, 512, 512, nullptr, nullptr);
    /* y1 = gelu(sa2 @ ref_w1^T + b) */
    gemm_mma<1><<<dim3(1024/128, MROWS/128), 256, GEMM_SMEM>>>(
        p_q, ref_w1, ref_b1, p_y1, MROWS, 1024, 512, nullptr, nullptr);
    /* tok += sigmoid(g) * (y1 @ ref_w2^T + b) */
    gemm_mma<2><<<dim3(512/128, MROWS/128), 256, GEMM_SMEM>>>(
        p_y1, ref_w2, ref_b2, p_tok, MROWS, 512, 1024, p_tok, gscal);
    /* cap = tok @ lin_w^T + b */
    gemm_mma<0><<<dim3(1024/128, MROWS/128), 256, GEMM_SMEM>>>(
        p_tok, lin_w, lin_b, p_cap, MROWS, 1024, 512, nullptr, nullptr);
    /* h = tok @ mlp_w1^T + b */
    gemm_mma<0><<<dim3(512/128, MROWS/128), 256, GEMM_SMEM>>>(
        p_tok, mlp_w1, mlp_b1, p_h, MROWS, 512, 512, nullptr, nullptr);
    bn_partial<<<NBLK_BN, 512>>>();
    bn_final<<<1, 512>>>();
    bn_apply<<<(int)(((size_t)BKTOK*512 + 255)/256), 256>>>(bn_w, bn_b);

    /* feat = relu_bn(h) @ mlp_w2^T + b + cap */
    gemm_mma<3><<<dim3(1024/128, MROWS/128), 256, GEMM_SMEM>>>(
        p_h, mlp_w2, mlp_b2, p_feat, MROWS, 1024, 512, p_cap, nullptr);
    pool_kernel<<<BATCH, 256>>>(out);
}

// round 6
// speedup vs baseline: 2.2322x; 1.1654x over previous
#include <cuda_runtime.h>
#include <math.h>
#include <stdint.h>

#define BATCH 256
#define NT 512
#define DIM 512
#define KTOP 153
#define BKTOK (BATCH*KTOP)      /* 39168 = 306*128 */
#define EDIM 1024
#define NHEADS 8
#define HD 64
#define NBLK_BN 306

#define GEMM_SMEM (3*32768)     /* 3 stages x (A 16KB + B 16KB) */

/* ---------------- scratch (device globals; no allocation) ---------------- */
__device__ int   g_idx[BKTOK];
__device__ int   g_lens[BATCH];
__device__ float g_tok[(size_t)BKTOK*DIM];
__device__ float g_q[(size_t)BKTOK*DIM];          /* LN out (tf32), later sa2 */
__device__ float g_qkv[(size_t)BKTOK*3*DIM];
__device__ float g_sa[(size_t)BKTOK*DIM];
__device__ float g_y1[(size_t)BKTOK*2*DIM];
__device__ float g_cap[(size_t)BKTOK*EDIM];
__device__ float g_h[(size_t)BKTOK*DIM];
__device__ float g_feat[(size_t)BKTOK*EDIM];
__device__ float g_p1[NBLK_BN*512];
__device__ float g_p2[NBLK_BN*512];
__device__ float g_mu[512];
__device__ float g_rstd[512];
/* tf32-converted weights */
__device__ float g_w_sain[1536*512];
__device__ float g_w_saout[512*512];
__device__ float g_w_ref1[1024*512];
__device__ float g_w_ref2[512*1024];
__device__ float g_w_lin[1024*512];
__device__ float g_w_mlp1[512*512];
__device__ float g_w_mlp2[1024*512];

/* ------------------------------ helpers ---------------------------------- */
__device__ __forceinline__ uint32_t f2tf(float f) {
    uint32_t u;
    asm("cvt.rna.tf32.f32 %0, %1;" : "=r"(u) : "f"(f));
    return u;
}
__device__ __forceinline__ float tf32r(float f) { return __uint_as_float(f2tf(f)); }

__device__ __forceinline__ uint32_t smem_u32(const void* p) {
    uint32_t a;
    asm("{ .reg .u64 t; cvta.to.shared.u64 t, %1; cvt.u32.u64 %0, t; }"
        : "=r"(a) : "l"(p));
    return a;
}

#define CP_ASYNC16(dst, src) \
    asm volatile("cp.async.cg.shared.global [%0], [%1], 16;" :: "r"(dst), "l"(src))
#define CP_COMMIT() asm volatile("cp.async.commit_group;" ::: "memory")
#define CP_WAIT1()  asm volatile("cp.async.wait_group 1;" ::: "memory")

__device__ __forceinline__ void mma_tf32(float& d0, float& d1, float& d2, float& d3,
                                         uint32_t a0, uint32_t a1, uint32_t a2, uint32_t a3,
                                         uint32_t b0, uint32_t b1)
{
    asm volatile(
        "mma.sync.aligned.m16n8k8.row.col.f32.tf32.tf32.f32 "
        "{%0,%1,%2,%3}, {%4,%5,%6,%7}, {%8,%9}, {%0,%1,%2,%3};"
        : "+f"(d0), "+f"(d1), "+f"(d2), "+f"(d3)
        : "r"(a0), "r"(a1), "r"(a2), "r"(a3), "r"(b0), "r"(b1));
}

/* ------------------- weight conversion fp32 -> tf32 bits ----------------- */
__global__ void cvt_tf32_kernel(const float* __restrict__ src, float* __restrict__ dst, int n)
{
    int i = blockIdx.x * 256 + threadIdx.x;
    if (i < n) dst[i] = tf32r(src[i]);
}

/* ---- tensor-core tf32 GEMM (cp.async pipelined): C = A @ W^T + bias ----- */
/* Inputs A,W already tf32-rounded. SW128-swizzled smem, 3 stages.           */
/* EPI: 0=bias 1=gelu(bias) 2=C=aux+sigmoid(g)*(acc+bias) 3=acc+bias+aux     */
/* RND: round stored C to tf32 (when C feeds another GEMM as A)              */
template<int EPI, int RND>
__global__ __launch_bounds__(256, 2)
void gemm_cp(const float* __restrict__ A, const float* __restrict__ W,
             const float* __restrict__ bias, float* __restrict__ C,
             int M, int N, int K,
             const float* __restrict__ aux, const float* __restrict__ gptr)
{
    extern __shared__ float sm[];
    const int tid  = threadIdx.x;
    const int wid  = tid >> 5;
    const int lane = tid & 31;
    const int gid  = lane >> 2;          /* 0..7 */
    const int tig  = lane & 3;           /* 0..3 */
    const int wm   = (wid & 1) * 64;
    const int wn   = (wid >> 1) * 32;
    const int m0   = blockIdx.y * 128;
    const int n0   = blockIdx.x * 128;
    const int lrow = tid >> 3;           /* 0..31 */
    const int lc4  = tid & 7;            /* 16B chunk in 128B row */

    const uint32_t sbase = smem_u32(sm);
    /* SW128 swizzled store offsets (bytes), rows lrow+32p */
    uint32_t dA[4];
    const float* srcA[4];
    const float* srcB[4];
#pragma unroll
    for (int p = 0; p < 4; p++) {
        int row = lrow + 32 * p;
        dA[p] = (uint32_t)(row * 128 + ((lc4 ^ (lrow & 7)) * 16));
        srcA[p] = A + (size_t)(m0 + row) * K + lc4 * 4;
        srcB[p] = W + (size_t)(n0 + row) * K + lc4 * 4;
    }

    float acc[4][4][4];
#pragma unroll
    for (int i = 0; i < 4; i++)
#pragma unroll
        for (int j = 0; j < 4; j++)
#pragma unroll
            for (int c = 0; c < 4; c++) acc[i][j][c] = 0.f;

    const int nch = K >> 5;

    auto load_chunk = [&](int c) {
        uint32_t sb = sbase + (uint32_t)(c % 3) * 32768u;
        size_t ko = (size_t)c * 32;
#pragma unroll
        for (int p = 0; p < 4; p++) {
            CP_ASYNC16(sb + dA[p],          srcA[p] + ko);
            CP_ASYNC16(sb + 16384 + dA[p],  srcB[p] + ko);
        }
    };

    load_chunk(0); CP_COMMIT();
    load_chunk(1); CP_COMMIT();

    const int g4 = gid << 2;

    for (int c = 0; c < nch; c++) {
        CP_WAIT1();                 /* own group c done (g_{c+1} may pend) */
        __syncthreads();            /* stage c globally ready; compute c-1 done */
        if (c + 2 < nch) load_chunk(c + 2);
        CP_COMMIT();

        const uint32_t* uA = (const uint32_t*)(sm + (c % 3) * 8192);
        const uint32_t* uB = uA + 4096;
#pragma unroll
        for (int ks = 0; ks < 32; ks += 8) {
            const int c0 = (ks ^ g4) + tig;
            const int c1 = ((ks ^ g4) ^ 4) + tig;
            uint32_t af[4][4], bf[4][2];
#pragma unroll
            for (int mt = 0; mt < 4; mt++) {
                const uint32_t* p0 = uA + (wm + mt * 16 + gid) * 32;
                af[mt][0] = p0[c0];
                af[mt][1] = p0[256 + c0];
                af[mt][2] = p0[c1];
                af[mt][3] = p0[256 + c1];
            }
#pragma unroll
            for (int nj = 0; nj < 4; nj++) {
                const uint32_t* pb = uB + (wn + nj * 8 + gid) * 32;
                bf[nj][0] = pb[c0];
                bf[nj][1] = pb[c1];
            }
#pragma unroll
            for (int mt = 0; mt < 4; mt++)
#pragma unroll
                for (int nj = 0; nj < 4; nj++)
                    mma_tf32(acc[mt][nj][0], acc[mt][nj][1], acc[mt][nj][2], acc[mt][nj][3],
                             af[mt][0], af[mt][1], af[mt][2], af[mt][3],
                             bf[nj][0], bf[nj][1]);
        }
    }

    /* epilogue */
    float sg = 0.f;
    if (EPI == 2) sg = 1.0f / (1.0f + expf(-gptr[0]));

#pragma unroll
    for (int mt = 0; mt < 4; mt++) {
#pragma unroll
        for (int nj = 0; nj < 4; nj++) {
            int r  = m0 + wm + mt * 16 + gid;
            int cc = n0 + wn + nj * 8 + 2 * tig;
            float b0v = bias[cc], b1v = bias[cc + 1];
            float v[4];
            v[0] = acc[mt][nj][0] + b0v;
            v[1] = acc[mt][nj][1] + b1v;
            v[2] = acc[mt][nj][2] + b0v;
            v[3] = acc[mt][nj][3] + b1v;
            if (EPI == 1) {
#pragma unroll
                for (int c = 0; c < 4; c++)
                    v[c] = 0.5f * v[c] * (1.0f + erff(v[c] * 0.70710678118654752f));
            }
            if (EPI == 2) {
                const float* x0 = aux + (size_t)r * N + cc;
                const float* x1 = aux + (size_t)(r + 8) * N + cc;
                v[0] = x0[0] + sg * v[0]; v[1] = x0[1] + sg * v[1];
                v[2] = x1[0] + sg * v[2]; v[3] = x1[1] + sg * v[3];
            }
            if (EPI == 3) {
                const float* x0 = aux + (size_t)r * N + cc;
                const float* x1 = aux + (size_t)(r + 8) * N + cc;
                v[0] += x0[0]; v[1] += x0[1]; v[2] += x1[0]; v[3] += x1[1];
            }
            if (RND) {
#pragma unroll
                for (int c = 0; c < 4; c++) v[c] = tf32r(v[c]);
            }
            *(float2*)(C + (size_t)r * N + cc)       = make_float2(v[0], v[1]);
            *(float2*)(C + (size_t)(r + 8) * N + cc) = make_float2(v[2], v[3]);
        }
    }
}

/* ---------------- top-k selection (exact jax.lax.top_k order) ------------ */
__global__ void topk_kernel(const int* __restrict__ text,
                            const float* __restrict__ atten)
{
    int b = blockIdx.x;
    int t = threadIdx.x;            /* 512 threads */
    __shared__ float sval[NT];
    __shared__ int   sidx[NT];
    __shared__ int   red[NT];

    int tv = text[b*NT + t];

    red[t] = (tv << 10) | (NT - 1 - t);
    __syncthreads();
    for (int s = NT/2; s > 0; s >>= 1) {
        if (t < s) red[t] = max(red[t], red[t+s]);
        __syncthreads();
    }
    int eos = NT - 1 - (red[0] & 1023);
    __syncthreads();

    red[t] = (tv != 0) ? 1 : 0;
    __syncthreads();
    for (int s = NT/2; s > 0; s >>= 1) {
        if (t < s) red[t] += red[t+s];
        __syncthreads();
    }
    int nz = red[0];
    __syncthreads();

    float v;
    if (t == 0 || t == eos) v = -1.0f;
    else                    v = atten[((size_t)b*NT + eos)*NT + t];
    if (tv == 0) v = 0.0f;

    sval[t] = v; sidx[t] = t;
    __syncthreads();

    for (int ksz = 2; ksz <= NT; ksz <<= 1) {
        for (int j = ksz >> 1; j > 0; j >>= 1) {
            int ixj = t ^ j;
            if (ixj > t) {
                float va = sval[t], vb = sval[ixj];
                int   ia = sidx[t], ib = sidx[ixj];
                bool aBefore = (va > vb) || (va == vb && ia < ib);
                bool desc = ((t & ksz) == 0);
                if (desc ? !aBefore : aBefore) {
                    sval[t] = vb; sval[ixj] = va;
                    sidx[t] = ib; sidx[ixj] = ia;
                }
            }
            __syncthreads();
        }
    }
    if (t < KTOP) g_idx[b*KTOP + t] = sidx[t];
    if (t == 0) {
        int lnn = nz - 2;
        if (lnn > KTOP) lnn = KTOP;
        if (lnn < 1) lnn = 1;
        g_lens[b] = lnn;
    }
}

/* ---------- gather + L2 normalize + LayerNorm (fused, one pass) ---------- */
__global__ void gather_ln_kernel(const float* __restrict__ features,
                                 const float* __restrict__ lnw,
                                 const float* __restrict__ lnb)
{
    int token = blockIdx.x;
    int b = token / KTOP;
    int src = g_idx[token];
    int tid = threadIdx.x;                /* 128 threads */
    const float* f = features + ((size_t)b*NT + src)*DIM;

    float v[4];
    float s1 = 0.f, s2 = 0.f;
#pragma unroll
    for (int i = 0; i < 4; i++) {
        v[i] = f[tid + i*128];
        s1 += v[i];
        s2 += v[i]*v[i];
    }
    __shared__ float r1[128], r2[128];
    r1[tid] = s1; r2[tid] = s2;
    __syncthreads();
    for (int s = 64; s > 0; s >>= 1) {
        if (tid < s) { r1[tid] += r1[tid+s]; r2[tid] += r2[tid+s]; }
        __syncthreads();
    }
    float sumf = r1[0], ss = r2[0];
    float inv  = 1.0f / (sqrtf(ss) + 1e-6f);
    float mean = sumf * inv * (1.0f/DIM);
    float et2  = ss * inv * inv * (1.0f/DIM);
    float var  = et2 - mean*mean;
    float rstd = rsqrtf(var + 1e-5f);

    float* tokp = g_tok + (size_t)token*DIM;
    float* qp   = g_q   + (size_t)token*DIM;
#pragma unroll
    for (int i = 0; i < 4; i++) {
        int c = tid + i*128;
        float tvv = v[i] * inv;
        tokp[c] = tvv;                                        /* fp32 */
        qp[c]   = tf32r((tvv - mean) * rstd * lnw[c] + lnb[c]); /* GEMM A */
    }
}

/* ---------------- self-attention: 4 threads per token -------------------- */
__global__ __launch_bounds__(640) void attn_kernel()
{
    int h = blockIdx.x, b = blockIdx.y;
    int tt = threadIdx.x >> 2;            /* token 0..159 */
    int qu = threadIdx.x & 3;             /* channel quarter */
    __shared__ float ksh[64][64];
    __shared__ float vsh[64][64];

    float q[16], acc[16];
    float m = -1e30f, l = 0.f;
    bool act = tt < KTOP;
    const float* qb = g_qkv + (size_t)(b*KTOP + (act ? tt : 0))*1536 + h*HD + qu*16;
#pragma unroll
    for (int c = 0; c < 16; c++) { q[c] = act ? qb[c] : 0.f; acc[c] = 0.f; }

    for (int s0 = 0; s0 < KTOP; s0 += 64) {
        int sc = min(64, KTOP - s0);
        __syncthreads();
        for (int i = threadIdx.x; i < sc*64; i += blockDim.x) {
            int s = i >> 6, c = i & 63;
            const float* kb = g_qkv + (size_t)(b*KTOP + s0 + s)*1536;
            ksh[s][c] = kb[512  + h*HD + c];
            vsh[s][c] = kb[1024 + h*HD + c];
        }
        __syncthreads();
        for (int s = 0; s < sc; s++) {
            float d = 0.f;
#pragma unroll
            for (int c = 0; c < 16; c++) d += q[c]*ksh[s][qu*16 + c];
            d += __shfl_xor_sync(0xffffffffu, d, 1);
            d += __shfl_xor_sync(0xffffffffu, d, 2);
            float sv = d * 0.125f;
            float mn = fmaxf(m, sv);
            float corr = __expf(m - mn);
            float p    = __expf(sv - mn);
            l = l*corr + p;
#pragma unroll
            for (int c = 0; c < 16; c++) acc[c] = acc[c]*corr + p*vsh[s][qu*16 + c];
            m = mn;
        }
    }
    if (act) {
        float invl = 1.0f / l;
        float* outp = g_sa + (size_t)(b*KTOP + tt)*DIM + h*HD + qu*16;
#pragma unroll
        for (int c = 0; c < 16; c++) outp[c] = tf32r(acc[c]*invl);  /* GEMM A */
    }
}

/* --------------------------- BatchNorm (train) --------------------------- */
__global__ void bn_partial()
{
    int col = threadIdx.x;                 /* 512 */
    int r0 = blockIdx.x * 128;
    float s1 = 0.f, s2 = 0.f;
    for (int r = 0; r < 128; r++) {
        float x = g_h[(size_t)(r0 + r)*512 + col];
        s1 += x; s2 += x*x;
    }
    g_p1[blockIdx.x*512 + col] = s1;
    g_p2[blockIdx.x*512 + col] = s2;
}

__global__ void bn_final()
{
    int c = threadIdx.x;                   /* 512 */
    float s1 = 0.f, s2 = 0.f;
    for (int i = 0; i < NBLK_BN; i++) { s1 += g_p1[i*512+c]; s2 += g_p2[i*512+c]; }
    float mean = s1 / (float)BKTOK;
    float var  = s2 / (float)BKTOK - mean*mean;
    g_mu[c]   = mean;
    g_rstd[c] = rsqrtf(var + 1e-5f);
}

__global__ void bn_apply(const float* __restrict__ bnw, const float* __restrict__ bnb)
{
    size_t i = (size_t)blockIdx.x*blockDim.x + threadIdx.x;
    if (i < (size_t)BKTOK*512) {
        int c = (int)(i & 511);
        float x = g_h[i];
        x = (x - g_mu[c]) * g_rstd[c] * bnw[c] + bnb[c];
        g_h[i] = tf32r(fmaxf(x, 0.f));     /* GEMM A */
    }
}

/* ------------------------ variable-length max pool ----------------------- */
__global__ void pool_kernel(float* __restrict__ out)
{
    int b = blockIdx.x;
    int tid = threadIdx.x;                 /* 256 */
    int L = g_lens[b];
    float mx[4] = {-1e30f, -1e30f, -1e30f, -1e30f};
    const float* fp = g_feat + (size_t)b*KTOP*EDIM;
    for (int t = 0; t < L; t++) {
#pragma unroll
        for (int i = 0; i < 4; i++)
            mx[i] = fmaxf(mx[i], fp[(size_t)t*EDIM + tid + i*256]);
    }
#pragma unroll
    for (int i = 0; i < 4; i++)
        out[(size_t)b*EDIM + tid + i*256] = mx[i];
}

/* ------------------------------- launcher -------------------------------- */
extern "C" void kernel_launch(void* const* d_in, const int* in_sizes, int n_in,
                              void* d_out, int out_size)
{
    const float* features = (const float*)d_in[0];
    const int*   text     = (const int*)  d_in[1];
    const float* atten    = (const float*)d_in[2];
    const float* ln_q_w   = (const float*)d_in[3];
    const float* ln_q_b   = (const float*)d_in[4];
    const float* sa_in_w  = (const float*)d_in[5];
    const float* sa_in_b  = (const float*)d_in[6];
    const float* sa_out_w = (const float*)d_in[7];
    const float* sa_out_b = (const float*)d_in[8];
    const float* ref_w1   = (const float*)d_in[9];
    const float* ref_b1   = (const float*)d_in[10];
    const float* ref_w2   = (const float*)d_in[11];
    const float* ref_b2   = (const float*)d_in[12];
    const float* gscal    = (const float*)d_in[13];
    const float* lin_w    = (const float*)d_in[14];
    const float* lin_b    = (const float*)d_in[15];
    const float* mlp_w1   = (const float*)d_in[16];
    const float* mlp_b1   = (const float*)d_in[17];
    const float* bn_w     = (const float*)d_in[18];
    const float* bn_b     = (const float*)d_in[19];
    const float* mlp_w2   = (const float*)d_in[20];
    const float* mlp_b2   = (const float*)d_in[21];
    float* out = (float*)d_out;

    float *p_tok, *p_q, *p_qkv, *p_sa, *p_y1, *p_cap, *p_h, *p_feat;
    float *w_sain, *w_saout, *w_ref1, *w_ref2, *w_lin, *w_mlp1, *w_mlp2;
    cudaGetSymbolAddress((void**)&p_tok,  g_tok);
    cudaGetSymbolAddress((void**)&p_q,    g_q);
    cudaGetSymbolAddress((void**)&p_qkv,  g_qkv);
    cudaGetSymbolAddress((void**)&p_sa,   g_sa);
    cudaGetSymbolAddress((void**)&p_y1,   g_y1);
    cudaGetSymbolAddress((void**)&p_cap,  g_cap);
    cudaGetSymbolAddress((void**)&p_h,    g_h);
    cudaGetSymbolAddress((void**)&p_feat, g_feat);
    cudaGetSymbolAddress((void**)&w_sain,  g_w_sain);
    cudaGetSymbolAddress((void**)&w_saout, g_w_saout);
    cudaGetSymbolAddress((void**)&w_ref1,  g_w_ref1);
    cudaGetSymbolAddress((void**)&w_ref2,  g_w_ref2);
    cudaGetSymbolAddress((void**)&w_lin,   g_w_lin);
    cudaGetSymbolAddress((void**)&w_mlp1,  g_w_mlp1);
    cudaGetSymbolAddress((void**)&w_mlp2,  g_w_mlp2);

    cudaFuncSetAttribute(gemm_cp<0,0>, cudaFuncAttributeMaxDynamicSharedMemorySize, GEMM_SMEM);
    cudaFuncSetAttribute(gemm_cp<0,1>, cudaFuncAttributeMaxDynamicSharedMemorySize, GEMM_SMEM);
    cudaFuncSetAttribute(gemm_cp<1,1>, cudaFuncAttributeMaxDynamicSharedMemorySize, GEMM_SMEM);
    cudaFuncSetAttribute(gemm_cp<2,1>, cudaFuncAttributeMaxDynamicSharedMemorySize, GEMM_SMEM);
    cudaFuncSetAttribute(gemm_cp<3,0>, cudaFuncAttributeMaxDynamicSharedMemorySize, GEMM_SMEM);

    const int MROWS = BKTOK;             /* 39168 = 306*128 */

    /* weights -> tf32 (runs concurrently with topk/gather on same stream order) */
    cvt_tf32_kernel<<<(1536*512+255)/256, 256>>>(sa_in_w,  w_sain,  1536*512);
    cvt_tf32_kernel<<<( 512*512+255)/256, 256>>>(sa_out_w, w_saout,  512*512);
    cvt_tf32_kernel<<<(1024*512+255)/256, 256>>>(ref_w1,   w_ref1,  1024*512);
    cvt_tf32_kernel<<<( 512*1024+255)/256,256>>>(ref_w2,   w_ref2,   512*1024);
    cvt_tf32_kernel<<<(1024*512+255)/256, 256>>>(lin_w,    w_lin,   1024*512);
    cvt_tf32_kernel<<<( 512*512+255)/256, 256>>>(mlp_w1,   w_mlp1,   512*512);
    cvt_tf32_kernel<<<(1024*512+255)/256, 256>>>(mlp_w2,   w_mlp2,  1024*512);

    topk_kernel<<<BATCH, NT>>>(text, atten);
    gather_ln_kernel<<<BKTOK, 128>>>(features, ln_q_w, ln_q_b);

    /* qkv = LN(tok) @ sa_in_w^T + b   (fp32 out, attn consumes) */
    gemm_cp<0,0><<<dim3(1536/128, MROWS/128), 256, GEMM_SMEM>>>(
        p_q, w_sain, sa_in_b, p_qkv, MROWS, 1536, 512, nullptr, nullptr);
    attn_kernel<<<dim3(NHEADS, BATCH), 640>>>();

    /* sa2 = sa @ sa_out_w^T + b  (tf32 out -> GEMM3 A) */
    gemm_cp<0,1><<<dim3(512/128, MROWS/128), 256, GEMM_SMEM>>>(
        p_sa, w_saout, sa_out_b, p_q, MROWS, 512, 512, nullptr, nullptr);
    /* y1 = gelu(sa2 @ ref_w1^T + b)  (tf32 out) */
    gemm_cp<1,1><<<dim3(1024/128, MROWS/128), 256, GEMM_SMEM>>>(
        p_q, w_ref1, ref_b1, p_y1, MROWS, 1024, 512, nullptr, nullptr);
    /* tok = tok + sigmoid(g)*(y1 @ ref_w2^T + b)  (tf32 out) */
    gemm_cp<2,1><<<dim3(512/128, MROWS/128), 256, GEMM_SMEM>>>(
        p_y1, w_ref2, ref_b2, p_tok, MROWS, 512, 1024, p_tok, gscal);
    /* cap = tok @ lin_w^T + b  (fp32 out) */
    gemm_cp<0,0><<<dim3(1024/128, MROWS/128), 256, GEMM_SMEM>>>(
        p_tok, w_lin, lin_b, p_cap, MROWS, 1024, 512, nullptr, nullptr);
    /* h = tok @ mlp_w1^T + b  (fp32 out, BN consumes) */
    gemm_cp<0,0><<<dim3(512/128, MROWS/128), 256, GEMM_SMEM>>>(
        p_tok, w_mlp1, mlp_b1, p_h, MROWS, 512, 512, nullptr, nullptr);
    bn_partial<<<NBLK_BN, 512>>>();
    bn_final<<<1, 512>>>();
    bn_apply<<<(int)(((size_t)BKTOK*512 + 255)/256), 256>>>(bn_w, bn_b);

    /* feat = relu_bn(h) @ mlp_w2^T + b + cap  (fp32 out) */
    gemm_cp<3,0><<<dim3(1024/128, MROWS/128), 256, GEMM_SMEM>>>(
        p_h, w_mlp2, mlp_b2, p_feat, MROWS, 1024, 512, p_cap, nullptr);
    pool_kernel<<<BATCH, 256>>>(out);
}

// round 7
// speedup vs baseline: 2.7283x; 1.2223x over previous
#include <cuda_runtime.h>
#include <cuda_fp16.h>
#include <math.h>
#include <stdint.h>

#define BATCH 256
#define NT 512
#define DIM 512
#define KTOP 153
#define BKTOK (BATCH*KTOP)      /* 39168 = 306*128 */
#define EDIM 1024
#define NHEADS 8
#define HD 64
#define NBLK_BN 306

#define GEMM_SMEM (3*16384)     /* 3 stages x (A 8KB + B 8KB) */

/* ---------------- scratch (device globals; no allocation) ---------------- */
__device__ int    g_idx[BKTOK];
__device__ int    g_lens[BATCH];
__device__ float  g_tok[(size_t)BKTOK*DIM];        /* fp32 residual source */
__device__ __half g_qh[(size_t)BKTOK*DIM];         /* LN out (GEMM A) */
__device__ float  g_qkv[(size_t)BKTOK*3*DIM];      /* fp32 for attn */
__device__ __half g_sa[(size_t)BKTOK*DIM];
__device__ __half g_sa2[(size_t)BKTOK*DIM];
__device__ __half g_y1h[(size_t)BKTOK*2*DIM];
__device__ __half g_tokh[(size_t)BKTOK*DIM];
__device__ float  g_cap[(size_t)BKTOK*EDIM];
__device__ float  g_h[(size_t)BKTOK*DIM];
__device__ __half g_hh[(size_t)BKTOK*DIM];
__device__ float  g_feat[(size_t)BKTOK*EDIM];
__device__ float  g_p1[NBLK_BN*512];
__device__ float  g_p2[NBLK_BN*512];
__device__ float  g_mu[512];
__device__ float  g_rstd[512];
/* half-converted weights */
__device__ __half g_w_sain[1536*512];
__device__ __half g_w_saout[512*512];
__device__ __half g_w_ref1[1024*512];
__device__ __half g_w_ref2[512*1024];
__device__ __half g_w_lin[1024*512];
__device__ __half g_w_mlp1[512*512];
__device__ __half g_w_mlp2[1024*512];

/* ------------------------------ helpers ---------------------------------- */
__device__ __forceinline__ uint32_t smem_u32(const void* p) {
    uint32_t a;
    asm("{ .reg .u64 t; cvta.to.shared.u64 t, %1; cvt.u32.u64 %0, t; }"
        : "=r"(a) : "l"(p));
    return a;
}
#define CP_ASYNC16(dst, src) \
    asm volatile("cp.async.cg.shared.global [%0], [%1], 16;" :: "r"(dst), "l"(src))
#define CP_COMMIT() asm volatile("cp.async.commit_group;" ::: "memory")
#define CP_WAIT1()  asm volatile("cp.async.wait_group 1;" ::: "memory")

__device__ __forceinline__ void ldsm4(uint32_t& r0, uint32_t& r1,
                                      uint32_t& r2, uint32_t& r3, uint32_t addr) {
    asm volatile("ldmatrix.sync.aligned.m8n8.x4.shared.b16 {%0,%1,%2,%3}, [%4];"
                 : "=r"(r0), "=r"(r1), "=r"(r2), "=r"(r3) : "r"(addr));
}
__device__ __forceinline__ void mma_h(float& d0, float& d1, float& d2, float& d3,
                                      uint32_t a0, uint32_t a1, uint32_t a2, uint32_t a3,
                                      uint32_t b0, uint32_t b1)
{
    asm volatile(
        "mma.sync.aligned.m16n8k16.row.col.f32.f16.f16.f32 "
        "{%0,%1,%2,%3}, {%4,%5,%6,%7}, {%8,%9}, {%0,%1,%2,%3};"
        : "+f"(d0), "+f"(d1), "+f"(d2), "+f"(d3)
        : "r"(a0), "r"(a1), "r"(a2), "r"(a3), "r"(b0), "r"(b1));
}

/* ------------------- weight conversion fp32 -> fp16 ---------------------- */
__global__ void cvt_h_kernel(const float* __restrict__ src, __half* __restrict__ dst, int n2)
{
    int i = blockIdx.x * 256 + threadIdx.x;      /* n2 = n/2 */
    if (i < n2) {
        float2 v = ((const float2*)src)[i];
        ((half2*)dst)[i] = __floats2half2_rn(v.x, v.y);
    }
}

/* ---- fp16 tensor-core GEMM (cp.async + ldmatrix): C = A @ W^T + bias ---- */
/* A [M,K], W [N,K] half row-major. BM=BN=128, BK=32, 3 stages.              */
/* EPI: 0=bias 1=gelu(bias) 2=C=aux+sigmoid(g)*(acc+bias) 3=acc+bias+aux     */
/* OUTH: 1 -> store __half (feeds next GEMM as A), 0 -> store float          */
template<int EPI, int OUTH>
__global__ __launch_bounds__(256, 2)
void gemm_h16(const __half* __restrict__ A, const __half* __restrict__ W,
              const float* __restrict__ bias, void* __restrict__ Cout,
              int M, int N, int K,
              const float* __restrict__ aux, const float* __restrict__ gptr)
{
    extern __shared__ __half smh[];
    const int tid  = threadIdx.x;
    const int wid  = tid >> 5;
    const int lane = tid & 31;
    const int gid  = lane >> 2;
    const int tig  = lane & 3;
    const int wm   = (wid & 1) * 64;
    const int wn   = (wid >> 1) * 32;
    const int m0   = blockIdx.y * 128;
    const int n0   = blockIdx.x * 128;

    const uint32_t sbase = smem_u32(smh);

    /* cp.async store pattern: 2 chunks per operand per thread */
    uint32_t sto[2];
    const __half* srcA[2];
    const __half* srcB[2];
#pragma unroll
    for (int q = 0; q < 2; q++) {
        int id  = tid + q * 256;
        int row = id >> 2, cc = id & 3;
        sto[q]  = (uint32_t)(row * 64 + ((cc ^ (row & 3)) << 4));
        srcA[q] = A + (size_t)(m0 + row) * K + cc * 8;
        srcB[q] = W + (size_t)(n0 + row) * K + cc * 8;
    }

    /* ldmatrix fragment addresses (stage-relative, kstep 0) */
    uint32_t aOff[4], bOff[2];
#pragma unroll
    for (int mt = 0; mt < 4; mt++) {
        int r  = wm + mt * 16 + (lane & 15);
        int ch = lane >> 4;
        aOff[mt] = (uint32_t)(r * 64 + ((ch ^ (r & 3)) << 4));
    }
#pragma unroll
    for (int njp = 0; njp < 2; njp++) {
        int r  = wn + njp * 16 + (lane & 7) + ((lane >> 4) << 3);
        int ch = (lane >> 3) & 1;
        bOff[njp] = (uint32_t)(8192 + r * 64 + ((ch ^ (r & 3)) << 4));
    }

    float acc[4][4][4];
#pragma unroll
    for (int i = 0; i < 4; i++)
#pragma unroll
        for (int j = 0; j < 4; j++)
#pragma unroll
            for (int c = 0; c < 4; c++) acc[i][j][c] = 0.f;

    const int nch = K >> 5;

    auto load_chunk = [&](int c) {
        uint32_t sb = sbase + (uint32_t)(c % 3) * 16384u;
        size_t ko = (size_t)c * 32;
#pragma unroll
        for (int q = 0; q < 2; q++) {
            CP_ASYNC16(sb + sto[q],        srcA[q] + ko);
            CP_ASYNC16(sb + 8192 + sto[q], srcB[q] + ko);
        }
    };

    load_chunk(0); CP_COMMIT();
    load_chunk(1); CP_COMMIT();

    for (int c = 0; c < nch; c++) {
        CP_WAIT1();
        __syncthreads();
        if (c + 2 < nch) load_chunk(c + 2);
        CP_COMMIT();

        uint32_t stb = sbase + (uint32_t)(c % 3) * 16384u;
#pragma unroll
        for (int ks = 0; ks < 2; ks++) {
            const uint32_t kx = (uint32_t)(ks << 5);
            uint32_t af[4][4], bf[2][4];
#pragma unroll
            for (int mt = 0; mt < 4; mt++)
                ldsm4(af[mt][0], af[mt][1], af[mt][2], af[mt][3],
                      stb + (aOff[mt] ^ kx));
#pragma unroll
            for (int njp = 0; njp < 2; njp++)
                ldsm4(bf[njp][0], bf[njp][1], bf[njp][2], bf[njp][3],
                      stb + (bOff[njp] ^ kx));
#pragma unroll
            for (int mt = 0; mt < 4; mt++)
#pragma unroll
                for (int nj = 0; nj < 4; nj++) {
                    const int njp = nj >> 1, pr = (nj & 1) << 1;
                    mma_h(acc[mt][nj][0], acc[mt][nj][1], acc[mt][nj][2], acc[mt][nj][3],
                          af[mt][0], af[mt][1], af[mt][2], af[mt][3],
                          bf[njp][pr], bf[njp][pr + 1]);
                }
        }
    }

    /* epilogue */
    float sg = 0.f;
    if (EPI == 2) sg = 1.0f / (1.0f + expf(-gptr[0]));

#pragma unroll
    for (int mt = 0; mt < 4; mt++) {
#pragma unroll
        for (int nj = 0; nj < 4; nj++) {
            int r  = m0 + wm + mt * 16 + gid;
            int cc = n0 + wn + nj * 8 + 2 * tig;
            float b0v = bias[cc], b1v = bias[cc + 1];
            float v[4];
            v[0] = acc[mt][nj][0] + b0v;
            v[1] = acc[mt][nj][1] + b1v;
            v[2] = acc[mt][nj][2] + b0v;
            v[3] = acc[mt][nj][3] + b1v;
            if (EPI == 1) {
#pragma unroll
                for (int c = 0; c < 4; c++)
                    v[c] = 0.5f * v[c] * (1.0f + erff(v[c] * 0.70710678118654752f));
            }
            if (EPI == 2) {
                const float* x0 = aux + (size_t)r * N + cc;
                const float* x1 = aux + (size_t)(r + 8) * N + cc;
                v[0] = x0[0] + sg * v[0]; v[1] = x0[1] + sg * v[1];
                v[2] = x1[0] + sg * v[2]; v[3] = x1[1] + sg * v[3];
            }
            if (EPI == 3) {
                const float* x0 = aux + (size_t)r * N + cc;
                const float* x1 = aux + (size_t)(r + 8) * N + cc;
                v[0] += x0[0]; v[1] += x0[1]; v[2] += x1[0]; v[3] += x1[1];
            }
            if (OUTH) {
                __half* Ch = (__half*)Cout;
                *(half2*)(Ch + (size_t)r * N + cc)       = __floats2half2_rn(v[0], v[1]);
                *(half2*)(Ch + (size_t)(r + 8) * N + cc) = __floats2half2_rn(v[2], v[3]);
            } else {
                float* Cf = (float*)Cout;
                *(float2*)(Cf + (size_t)r * N + cc)       = make_float2(v[0], v[1]);
                *(float2*)(Cf + (size_t)(r + 8) * N + cc) = make_float2(v[2], v[3]);
            }
        }
    }
}

/* ---------------- top-k selection (exact jax.lax.top_k order) ------------ */
__global__ void topk_kernel(const int* __restrict__ text,
                            const float* __restrict__ atten)
{
    int b = blockIdx.x;
    int t = threadIdx.x;            /* 512 threads */
    __shared__ float sval[NT];
    __shared__ int   sidx[NT];
    __shared__ int   red[NT];

    int tv = text[b*NT + t];

    red[t] = (tv << 10) | (NT - 1 - t);
    __syncthreads();
    for (int s = NT/2; s > 0; s >>= 1) {
        if (t < s) red[t] = max(red[t], red[t+s]);
        __syncthreads();
    }
    int eos = NT - 1 - (red[0] & 1023);
    __syncthreads();

    red[t] = (tv != 0) ? 1 : 0;
    __syncthreads();
    for (int s = NT/2; s > 0; s >>= 1) {
        if (t < s) red[t] += red[t+s];
        __syncthreads();
    }
    int nz = red[0];
    __syncthreads();

    float v;
    if (t == 0 || t == eos) v = -1.0f;
    else                    v = atten[((size_t)b*NT + eos)*NT + t];
    if (tv == 0) v = 0.0f;

    sval[t] = v; sidx[t] = t;
    __syncthreads();

    for (int ksz = 2; ksz <= NT; ksz <<= 1) {
        for (int j = ksz >> 1; j > 0; j >>= 1) {
            int ixj = t ^ j;
            if (ixj > t) {
                float va = sval[t], vb = sval[ixj];
                int   ia = sidx[t], ib = sidx[ixj];
                bool aBefore = (va > vb) || (va == vb && ia < ib);
                bool desc = ((t & ksz) == 0);
                if (desc ? !aBefore : aBefore) {
                    sval[t] = vb; sval[ixj] = va;
                    sidx[t] = ib; sidx[ixj] = ia;
                }
            }
            __syncthreads();
        }
    }
    if (t < KTOP) g_idx[b*KTOP + t] = sidx[t];
    if (t == 0) {
        int lnn = nz - 2;
        if (lnn > KTOP) lnn = KTOP;
        if (lnn < 1) lnn = 1;
        g_lens[b] = lnn;
    }
}

/* ---------- gather + L2 normalize + LayerNorm (fused, one pass) ---------- */
__global__ void gather_ln_kernel(const float* __restrict__ features,
                                 const float* __restrict__ lnw,
                                 const float* __restrict__ lnb)
{
    int token = blockIdx.x;
    int b = token / KTOP;
    int src = g_idx[token];
    int tid = threadIdx.x;                /* 128 threads */
    const float* f = features + ((size_t)b*NT + src)*DIM;

    float v[4];
    float s1 = 0.f, s2 = 0.f;
#pragma unroll
    for (int i = 0; i < 4; i++) {
        v[i] = f[tid + i*128];
        s1 += v[i];
        s2 += v[i]*v[i];
    }
    __shared__ float r1[128], r2[128];
    r1[tid] = s1; r2[tid] = s2;
    __syncthreads();
    for (int s = 64; s > 0; s >>= 1) {
        if (tid < s) { r1[tid] += r1[tid+s]; r2[tid] += r2[tid+s]; }
        __syncthreads();
    }
    float sumf = r1[0], ss = r2[0];
    float inv  = 1.0f / (sqrtf(ss) + 1e-6f);
    float mean = sumf * inv * (1.0f/DIM);
    float et2  = ss * inv * inv * (1.0f/DIM);
    float var  = et2 - mean*mean;
    float rstd = rsqrtf(var + 1e-5f);

    float*  tokp = g_tok + (size_t)token*DIM;
    __half* qp   = g_qh  + (size_t)token*DIM;
#pragma unroll
    for (int i = 0; i < 4; i++) {
        int c = tid + i*128;
        float tvv = v[i] * inv;
        tokp[c] = tvv;                                         /* fp32 residual */
        qp[c]   = __float2half_rn((tvv - mean) * rstd * lnw[c] + lnb[c]);
    }
}

/* ---------------- self-attention: 4 threads per token -------------------- */
__global__ __launch_bounds__(640) void attn_kernel()
{
    int h = blockIdx.x, b = blockIdx.y;
    int tt = threadIdx.x >> 2;            /* token 0..159 */
    int qu = threadIdx.x & 3;             /* channel quarter */
    __shared__ float ksh[64][64];
    __shared__ float vsh[64][64];

    float q[16], acc[16];
    float m = -1e30f, l = 0.f;
    bool act = tt < KTOP;
    const float* qb = g_qkv + (size_t)(b*KTOP + (act ? tt : 0))*1536 + h*HD + qu*16;
#pragma unroll
    for (int c = 0; c < 16; c++) { q[c] = act ? qb[c] : 0.f; acc[c] = 0.f; }

    for (int s0 = 0; s0 < KTOP; s0 += 64) {
        int sc = min(64, KTOP - s0);
        __syncthreads();
        for (int i = threadIdx.x; i < sc*64; i += blockDim.x) {
            int s = i >> 6, c = i & 63;
            const float* kb = g_qkv + (size_t)(b*KTOP + s0 + s)*1536;
            ksh[s][c] = kb[512  + h*HD + c];
            vsh[s][c] = kb[1024 + h*HD + c];
        }
        __syncthreads();
        for (int s = 0; s < sc; s++) {
            float d = 0.f;
#pragma unroll
            for (int c = 0; c < 16; c++) d += q[c]*ksh[s][qu*16 + c];
            d += __shfl_xor_sync(0xffffffffu, d, 1);
            d += __shfl_xor_sync(0xffffffffu, d, 2);
            float sv = d * 0.125f;
            float mn = fmaxf(m, sv);
            float corr = __expf(m - mn);
            float p    = __expf(sv - mn);
            l = l*corr + p;
#pragma unroll
            for (int c = 0; c < 16; c++) acc[c] = acc[c]*corr + p*vsh[s][qu*16 + c];
            m = mn;
        }
    }
    if (act) {
        float invl = 1.0f / l;
        __half* outp = g_sa + (size_t)(b*KTOP + tt)*DIM + h*HD + qu*16;
#pragma unroll
        for (int c = 0; c < 16; c += 2)
            *(half2*)(outp + c) = __floats2half2_rn(acc[c]*invl, acc[c+1]*invl);
    }
}

/* --------------------------- BatchNorm (train) --------------------------- */
__global__ void bn_partial()
{
    int col = threadIdx.x;                 /* 512 */
    int r0 = blockIdx.x * 128;
    float s1 = 0.f, s2 = 0.f;
    for (int r = 0; r < 128; r++) {
        float x = g_h[(size_t)(r0 + r)*512 + col];
        s1 += x; s2 += x*x;
    }
    g_p1[blockIdx.x*512 + col] = s1;
    g_p2[blockIdx.x*512 + col] = s2;
}

__global__ void bn_final()
{
    int c = threadIdx.x;                   /* 512 */
    float s1 = 0.f, s2 = 0.f;
    for (int i = 0; i < NBLK_BN; i++) { s1 += g_p1[i*512+c]; s2 += g_p2[i*512+c]; }
    float mean = s1 / (float)BKTOK;
    float var  = s2 / (float)BKTOK - mean*mean;
    g_mu[c]   = mean;
    g_rstd[c] = rsqrtf(var + 1e-5f);
}

__global__ void bn_apply(const float* __restrict__ bnw, const float* __restrict__ bnb)
{
    size_t i = (size_t)blockIdx.x*blockDim.x + threadIdx.x;
    if (i < (size_t)BKTOK*512) {
        int c = (int)(i & 511);
        float x = g_h[i];
        x = (x - g_mu[c]) * g_rstd[c] * bnw[c] + bnb[c];
        g_hh[i] = __float2half_rn(fmaxf(x, 0.f));
    }
}

/* ------------------------ variable-length max pool ----------------------- */
__global__ void pool_kernel(float* __restrict__ out)
{
    int b = blockIdx.x;
    int tid = threadIdx.x;                 /* 256 */
    int L = g_lens[b];
    float mx[4] = {-1e30f, -1e30f, -1e30f, -1e30f};
    const float* fp = g_feat + (size_t)b*KTOP*EDIM;
    for (int t = 0; t < L; t++) {
#pragma unroll
        for (int i = 0; i < 4; i++)
            mx[i] = fmaxf(mx[i], fp[(size_t)t*EDIM + tid + i*256]);
    }
#pragma unroll
    for (int i = 0; i < 4; i++)
        out[(size_t)b*EDIM + tid + i*256] = mx[i];
}

/* ------------------------------- launcher -------------------------------- */
extern "C" void kernel_launch(void* const* d_in, const int* in_sizes, int n_in,
                              void* d_out, int out_size)
{
    const float* features = (const float*)d_in[0];
    const int*   text     = (const int*)  d_in[1];
    const float* atten    = (const float*)d_in[2];
    const float* ln_q_w   = (const float*)d_in[3];
    const float* ln_q_b   = (const float*)d_in[4];
    const float* sa_in_w  = (const float*)d_in[5];
    const float* sa_in_b  = (const float*)d_in[6];
    const float* sa_out_w = (const float*)d_in[7];
    const float* sa_out_b = (const float*)d_in[8];
    const float* ref_w1   = (const float*)d_in[9];
    const float* ref_b1   = (const float*)d_in[10];
    const float* ref_w2   = (const float*)d_in[11];
    const float* ref_b2   = (const float*)d_in[12];
    const float* gscal    = (const float*)d_in[13];
    const float* lin_w    = (const float*)d_in[14];
    const float* lin_b    = (const float*)d_in[15];
    const float* mlp_w1   = (const float*)d_in[16];
    const float* mlp_b1   = (const float*)d_in[17];
    const float* bn_w     = (const float*)d_in[18];
    const float* bn_b     = (const float*)d_in[19];
    const float* mlp_w2   = (const float*)d_in[20];
    const float* mlp_b2   = (const float*)d_in[21];
    float* out = (float*)d_out;

    float *p_tok, *p_qkv, *p_cap, *p_h, *p_feat;
    __half *p_qh, *p_sa, *p_sa2, *p_y1h, *p_tokh, *p_hh;
    __half *w_sain, *w_saout, *w_ref1, *w_ref2, *w_lin, *w_mlp1, *w_mlp2;
    cudaGetSymbolAddress((void**)&p_tok,  g_tok);
    cudaGetSymbolAddress((void**)&p_qh,   g_qh);
    cudaGetSymbolAddress((void**)&p_qkv,  g_qkv);
    cudaGetSymbolAddress((void**)&p_sa,   g_sa);
    cudaGetSymbolAddress((void**)&p_sa2,  g_sa2);
    cudaGetSymbolAddress((void**)&p_y1h,  g_y1h);
    cudaGetSymbolAddress((void**)&p_tokh, g_tokh);
    cudaGetSymbolAddress((void**)&p_cap,  g_cap);
    cudaGetSymbolAddress((void**)&p_h,    g_h);
    cudaGetSymbolAddress((void**)&p_hh,   g_hh);
    cudaGetSymbolAddress((void**)&p_feat, g_feat);
    cudaGetSymbolAddress((void**)&w_sain,  g_w_sain);
    cudaGetSymbolAddress((void**)&w_saout, g_w_saout);
    cudaGetSymbolAddress((void**)&w_ref1,  g_w_ref1);
    cudaGetSymbolAddress((void**)&w_ref2,  g_w_ref2);
    cudaGetSymbolAddress((void**)&w_lin,   g_w_lin);
    cudaGetSymbolAddress((void**)&w_mlp1,  g_w_mlp1);
    cudaGetSymbolAddress((void**)&w_mlp2,  g_w_mlp2);

    cudaFuncSetAttribute(gemm_h16<0,0>, cudaFuncAttributeMaxDynamicSharedMemorySize, GEMM_SMEM);
    cudaFuncSetAttribute(gemm_h16<0,1>, cudaFuncAttributeMaxDynamicSharedMemorySize, GEMM_SMEM);
    cudaFuncSetAttribute(gemm_h16<1,1>, cudaFuncAttributeMaxDynamicSharedMemorySize, GEMM_SMEM);
    cudaFuncSetAttribute(gemm_h16<2,1>, cudaFuncAttributeMaxDynamicSharedMemorySize, GEMM_SMEM);
    cudaFuncSetAttribute(gemm_h16<3,0>, cudaFuncAttributeMaxDynamicSharedMemorySize, GEMM_SMEM);

    const int MROWS = BKTOK;             /* 39168 = 306*128 */

    /* weights -> fp16 */
    cvt_h_kernel<<<(1536*512/2+255)/256, 256>>>(sa_in_w,  w_sain,  1536*512/2);
    cvt_h_kernel<<<( 512*512/2+255)/256, 256>>>(sa_out_w, w_saout,  512*512/2);
    cvt_h_kernel<<<(1024*512/2+255)/256, 256>>>(ref_w1,   w_ref1,  1024*512/2);
    cvt_h_kernel<<<( 512*1024/2+255)/256,256>>>(ref_w2,   w_ref2,   512*1024/2);
    cvt_h_kernel<<<(1024*512/2+255)/256, 256>>>(lin_w,    w_lin,   1024*512/2);
    cvt_h_kernel<<<( 512*512/2+255)/256, 256>>>(mlp_w1,   w_mlp1,   512*512/2);
    cvt_h_kernel<<<(1024*512/2+255)/256, 256>>>(mlp_w2,   w_mlp2,  1024*512/2);

    topk_kernel<<<BATCH, NT>>>(text, atten);
    gather_ln_kernel<<<BKTOK, 128>>>(features, ln_q_w, ln_q_b);

    /* qkv = LN(tok) @ sa_in_w^T + b   (fp32 out, attn consumes) */
    gemm_h16<0,0><<<dim3(1536/128, MROWS/128), 256, GEMM_SMEM>>>(
        p_qh, w_sain, sa_in_b, p_qkv, MROWS, 1536, 512, nullptr, nullptr);
    attn_kernel<<<dim3(NHEADS, BATCH), 640>>>();

    /* sa2 = sa @ sa_out_w^T + b  (half out) */
    gemm_h16<0,1><<<dim3(512/128, MROWS/128), 256, GEMM_SMEM>>>(
        p_sa, w_saout, sa_out_b, p_sa2, MROWS, 512, 512, nullptr, nullptr);
    /* y1 = gelu(sa2 @ ref_w1^T + b)  (half out) */
    gemm_h16<1,1><<<dim3(1024/128, MROWS/128), 256, GEMM_SMEM>>>(
        p_sa2, w_ref1, ref_b1, p_y1h, MROWS, 1024, 512, nullptr, nullptr);
    /* tok_h = tok + sigmoid(g)*(y1 @ ref_w2^T + b)  (half out) */
    gemm_h16<2,1><<<dim3(512/128, MROWS/128), 256, GEMM_SMEM>>>(
        p_y1h, w_ref2, ref_b2, p_tokh, MROWS, 512, 1024, p_tok, gscal);
    /* cap = tok_h @ lin_w^T + b  (fp32 out) */
    gemm_h16<0,0><<<dim3(1024/128, MROWS/128), 256, GEMM_SMEM>>>(
        p_tokh, w_lin, lin_b, p_cap, MROWS, 1024, 512, nullptr, nullptr);
    /* h = tok_h @ mlp_w1^T + b  (fp32 out, BN consumes) */
    gemm_h16<0,0><<<dim3(512/128, MROWS/128), 256, GEMM_SMEM>>>(
        p_tokh, w_mlp1, mlp_b1, p_h, MROWS, 512, 512, nullptr, nullptr);
    bn_partial<<<NBLK_BN, 512>>>();
    bn_final<<<1, 512>>>();
    bn_apply<<<(int)(((size_t)BKTOK*512 + 255)/256), 256>>>(bn_w, bn_b);

    /* feat = relu_bn(h) @ mlp_w2^T + b + cap  (fp32 out) */
    gemm_h16<3,0><<<dim3(1024/128, MROWS/128), 256, GEMM_SMEM>>>(
        p_hh, w_mlp2, mlp_b2, p_feat, MROWS, 1024, 512, p_cap, nullptr);
    pool_kernel<<<BATCH, 256>>>(out);
}

// round 9
// speedup vs baseline: 5.6370x; 2.0661x over previous
#include <cuda_runtime.h>
#include <cuda_fp16.h>
#include <math.h>
#include <stdint.h>

#define BATCH 256
#define NT 512
#define DIM 512
#define KTOP 153
#define BKTOK (BATCH*KTOP)      /* 39168 = 306*128 */
#define EDIM 1024
#define NHEADS 8

#define GEMM_SMEM (4*16384)     /* 4 stages x (A 8KB + B 8KB) */
#define ATT_THREADS 320
#define ATT_ROWS 192            /* padded tile rows (3 chunks of 64) */
#define ATT_SMEM (3*ATT_ROWS*64*2)   /* Q,K,V half tiles: 73728 B */

/* ---------------- scratch (device globals; no allocation) ---------------- */
__device__ int    g_idx[BKTOK];
__device__ int    g_lens[BATCH];
__device__ float  g_tok[(size_t)BKTOK*DIM];        /* fp32 residual source */
__device__ __half g_qh[(size_t)BKTOK*DIM];         /* LN out (GEMM A) */
__device__ __half g_qkvh[(size_t)BKTOK*3*DIM];     /* half qkv */
__device__ __half g_sa[(size_t)BKTOK*DIM];
__device__ __half g_sa2[(size_t)BKTOK*DIM];
__device__ __half g_y1h[(size_t)BKTOK*2*DIM];
__device__ __half g_tokh[(size_t)BKTOK*DIM];
__device__ float  g_cap[(size_t)BKTOK*EDIM];
__device__ float  g_h[(size_t)BKTOK*DIM];
__device__ __half g_hh[(size_t)BKTOK*DIM];
__device__ float  g_feat[(size_t)BKTOK*EDIM];
__device__ float  g_s1[512];
__device__ float  g_s2[512];
__device__ float  g_mu[512];
__device__ float  g_rstd[512];
/* half-converted weights */
__device__ __half g_w_sain[1536*512];
__device__ __half g_w_saout[512*512];
__device__ __half g_w_ref1[1024*512];
__device__ __half g_w_ref2[512*1024];
__device__ __half g_w_lin[1024*512];
__device__ __half g_w_mlp1[512*512];
__device__ __half g_w_mlp2[1024*512];

/* ------------------------------ helpers ---------------------------------- */
__device__ __forceinline__ uint32_t smem_u32(const void* p) {
    uint32_t a;
    asm("{ .reg .u64 t; cvta.to.shared.u64 t, %1; cvt.u32.u64 %0, t; }"
        : "=r"(a) : "l"(p));
    return a;
}
#define CP_ASYNC16(dst, src) \
    asm volatile("cp.async.cg.shared.global [%0], [%1], 16;" :: "r"(dst), "l"(src))
#define CP_COMMIT()  asm volatile("cp.async.commit_group;" ::: "memory")
#define CP_WAIT_2()  asm volatile("cp.async.wait_group 2;" ::: "memory")

__device__ __forceinline__ void ldsm4(uint32_t& r0, uint32_t& r1,
                                      uint32_t& r2, uint32_t& r3, uint32_t addr) {
    asm volatile("ldmatrix.sync.aligned.m8n8.x4.shared.b16 {%0,%1,%2,%3}, [%4];"
                 : "=r"(r0), "=r"(r1), "=r"(r2), "=r"(r3) : "r"(addr));
}
__device__ __forceinline__ void ldsm4t(uint32_t& r0, uint32_t& r1,
                                       uint32_t& r2, uint32_t& r3, uint32_t addr) {
    asm volatile("ldmatrix.sync.aligned.m8n8.x4.trans.shared.b16 {%0,%1,%2,%3}, [%4];"
                 : "=r"(r0), "=r"(r1), "=r"(r2), "=r"(r3) : "r"(addr));
}
__device__ __forceinline__ void mma_h(float& d0, float& d1, float& d2, float& d3,
                                      uint32_t a0, uint32_t a1, uint32_t a2, uint32_t a3,
                                      uint32_t b0, uint32_t b1)
{
    asm volatile(
        "mma.sync.aligned.m16n8k16.row.col.f32.f16.f16.f32 "
        "{%0,%1,%2,%3}, {%4,%5,%6,%7}, {%8,%9}, {%0,%1,%2,%3};"
        : "+f"(d0), "+f"(d1), "+f"(d2), "+f"(d3)
        : "r"(a0), "r"(a1), "r"(a2), "r"(a3), "r"(b0), "r"(b1));
}
__device__ __forceinline__ uint32_t pack_h2(float a, float b) {
    half2 h = __floats2half2_rn(a, b);
    return *(uint32_t*)&h;
}

/* ------------------- weight conversion fp32 -> fp16 (one launch) --------- */
#define CVN0 393216
#define CVN1 (CVN0+131072)
#define CVN2 (CVN1+262144)
#define CVN3 (CVN2+262144)
#define CVN4 (CVN3+262144)
#define CVN5 (CVN4+131072)
#define CVN6 (CVN5+262144)
__global__ void cvt_all_kernel(const float* s0, const float* s1, const float* s2,
                               const float* s3, const float* s4, const float* s5,
                               const float* s6)
{
    int i = blockIdx.x * 256 + threadIdx.x;
    if (i >= CVN6) return;
    const float* s; __half* d; int o;
    if      (i < CVN0) { s = s0; d = g_w_sain;  o = i; }
    else if (i < CVN1) { s = s1; d = g_w_saout; o = i - CVN0; }
    else if (i < CVN2) { s = s2; d = g_w_ref1;  o = i - CVN1; }
    else if (i < CVN3) { s = s3; d = g_w_ref2;  o = i - CVN2; }
    else if (i < CVN4) { s = s4; d = g_w_lin;   o = i - CVN3; }
    else if (i < CVN5) { s = s5; d = g_w_mlp1;  o = i - CVN4; }
    else               { s = s6; d = g_w_mlp2;  o = i - CVN5; }
    float2 v = ((const float2*)s)[o];
    ((half2*)d)[o] = __floats2half2_rn(v.x, v.y);
}

__global__ void zero_stats_kernel()
{
    g_s1[threadIdx.x] = 0.f;
    g_s2[threadIdx.x] = 0.f;
}

/* ---- fp16 tensor-core GEMM (cp.async + ldmatrix): C = A @ W^T + bias ---- */
/* EPI: 0=bias 1=gelu(bias) 2=C=aux+sigmoid(g)*(acc+bias) 3=acc+bias+aux     */
/* OUTH: store half.  STATS: atomicAdd column sums/sumsq (for BN).           */
template<int EPI, int OUTH, int STATS>
__global__ __launch_bounds__(256, 2)
void gemm_h16(const __half* __restrict__ A, const __half* __restrict__ W,
              const float* __restrict__ bias, void* __restrict__ Cout,
              int M, int N, int K,
              const float* __restrict__ aux, const float* __restrict__ gptr)
{
    extern __shared__ __half smh[];
    const int tid  = threadIdx.x;
    const int wid  = tid >> 5;
    const int lane = tid & 31;
    const int gid  = lane >> 2;
    const int tig  = lane & 3;
    const int wm   = (wid & 1) * 64;
    const int wn   = (wid >> 1) * 32;
    const int m0   = blockIdx.y * 128;
    const int n0   = blockIdx.x * 128;

    const uint32_t sbase = smem_u32(smh);

    uint32_t sto[2];
    const __half* srcA[2];
    const __half* srcB[2];
#pragma unroll
    for (int q = 0; q < 2; q++) {
        int id  = tid + q * 256;
        int row = id >> 2, cc = id & 3;
        sto[q]  = (uint32_t)(row * 64 + ((cc ^ (row & 3)) << 4));
        srcA[q] = A + (size_t)(m0 + row) * K + cc * 8;
        srcB[q] = W + (size_t)(n0 + row) * K + cc * 8;
    }

    uint32_t aOff[4], bOff[2];
#pragma unroll
    for (int mt = 0; mt < 4; mt++) {
        int r  = wm + mt * 16 + (lane & 15);
        int ch = lane >> 4;
        aOff[mt] = (uint32_t)(r * 64 + ((ch ^ (r & 3)) << 4));
    }
#pragma unroll
    for (int njp = 0; njp < 2; njp++) {
        int r  = wn + njp * 16 + (lane & 7) + ((lane >> 4) << 3);
        int ch = (lane >> 3) & 1;
        bOff[njp] = (uint32_t)(8192 + r * 64 + ((ch ^ (r & 3)) << 4));
    }

    float acc[4][4][4];
#pragma unroll
    for (int i = 0; i < 4; i++)
#pragma unroll
        for (int j = 0; j < 4; j++)
#pragma unroll
            for (int c = 0; c < 4; c++) acc[i][j][c] = 0.f;

    const int nch = K >> 5;

    auto load_chunk = [&](int c) {
        uint32_t sb = sbase + (uint32_t)(c & 3) * 16384u;
        size_t ko = (size_t)c * 32;
#pragma unroll
        for (int q = 0; q < 2; q++) {
            CP_ASYNC16(sb + sto[q],        srcA[q] + ko);
            CP_ASYNC16(sb + 8192 + sto[q], srcB[q] + ko);
        }
    };

    load_chunk(0); CP_COMMIT();
    load_chunk(1); CP_COMMIT();
    load_chunk(2); CP_COMMIT();

    for (int c = 0; c < nch; c++) {
        CP_WAIT_2();
        __syncthreads();
        if (c + 3 < nch) load_chunk(c + 3);
        CP_COMMIT();

        uint32_t stb = sbase + (uint32_t)(c & 3) * 16384u;
#pragma unroll
        for (int ks = 0; ks < 2; ks++) {
            const uint32_t kx = (uint32_t)(ks << 5);
            uint32_t af[4][4], bf[2][4];
#pragma unroll
            for (int mt = 0; mt < 4; mt++)
                ldsm4(af[mt][0], af[mt][1], af[mt][2], af[mt][3],
                      stb + (aOff[mt] ^ kx));
#pragma unroll
            for (int njp = 0; njp < 2; njp++)
                ldsm4(bf[njp][0], bf[njp][1], bf[njp][2], bf[njp][3],
                      stb + (bOff[njp] ^ kx));
#pragma unroll
            for (int mt = 0; mt < 4; mt++)
#pragma unroll
                for (int nj = 0; nj < 4; nj++) {
                    const int njp = nj >> 1, pr = (nj & 1) << 1;
                    mma_h(acc[mt][nj][0], acc[mt][nj][1], acc[mt][nj][2], acc[mt][nj][3],
                          af[mt][0], af[mt][1], af[mt][2], af[mt][3],
                          bf[njp][pr], bf[njp][pr + 1]);
                }
        }
    }

    /* epilogue */
    float sg = 0.f;
    if (EPI == 2) sg = 1.0f / (1.0f + expf(-gptr[0]));
    float st1[8], st2[8];
    if (STATS) {
#pragma unroll
        for (int i = 0; i < 8; i++) { st1[i] = 0.f; st2[i] = 0.f; }
    }

#pragma unroll
    for (int mt = 0; mt < 4; mt++) {
#pragma unroll
        for (int nj = 0; nj < 4; nj++) {
            int r  = m0 + wm + mt * 16 + gid;
            int cc = n0 + wn + nj * 8 + 2 * tig;
            float b0v = bias[cc], b1v = bias[cc + 1];
            float v[4];
            v[0] = acc[mt][nj][0] + b0v;
            v[1] = acc[mt][nj][1] + b1v;
            v[2] = acc[mt][nj][2] + b0v;
            v[3] = acc[mt][nj][3] + b1v;
            if (EPI == 1) {
#pragma unroll
                for (int c = 0; c < 4; c++)
                    v[c] = 0.5f * v[c] * (1.0f + erff(v[c] * 0.70710678118654752f));
            }
            if (EPI == 2) {
                const float* x0 = aux + (size_t)r * N + cc;
                const float* x1 = aux + (size_t)(r + 8) * N + cc;
                v[0] = x0[0] + sg * v[0]; v[1] = x0[1] + sg * v[1];
                v[2] = x1[0] + sg * v[2]; v[3] = x1[1] + sg * v[3];
            }
            if (EPI == 3) {
                const float* x0 = aux + (size_t)r * N + cc;
                const float* x1 = aux + (size_t)(r + 8) * N + cc;
                v[0] += x0[0]; v[1] += x0[1]; v[2] += x1[0]; v[3] += x1[1];
            }
            if (STATS) {
                st1[nj*2+0] += v[0] + v[2];
                st1[nj*2+1] += v[1] + v[3];
                st2[nj*2+0] += v[0]*v[0] + v[2]*v[2];
                st2[nj*2+1] += v[1]*v[1] + v[3]*v[3];
            }
            if (OUTH) {
                __half* Ch = (__half*)Cout;
                *(half2*)(Ch + (size_t)r * N + cc)       = __floats2half2_rn(v[0], v[1]);
                *(half2*)(Ch + (size_t)(r + 8) * N + cc) = __floats2half2_rn(v[2], v[3]);
            } else {
                float* Cf = (float*)Cout;
                *(float2*)(Cf + (size_t)r * N + cc)       = make_float2(v[0], v[1]);
                *(float2*)(Cf + (size_t)(r + 8) * N + cc) = make_float2(v[2], v[3]);
            }
        }
    }
    if (STATS) {
#pragma unroll
        for (int i = 0; i < 8; i++) {
            float a = st1[i], q = st2[i];
            a += __shfl_xor_sync(0xffffffffu, a, 4);
            a += __shfl_xor_sync(0xffffffffu, a, 8);
            a += __shfl_xor_sync(0xffffffffu, a, 16);
            q += __shfl_xor_sync(0xffffffffu, q, 4);
            q += __shfl_xor_sync(0xffffffffu, q, 8);
            q += __shfl_xor_sync(0xffffffffu, q, 16);
            if (gid == 0) {
                int col = n0 + wn + (i >> 1) * 8 + 2 * tig + (i & 1);
                atomicAdd(&g_s1[col], a);
                atomicAdd(&g_s2[col], q);
            }
        }
    }
}

/* ---------------- top-k selection (exact jax.lax.top_k order) ------------ */
__global__ void topk_kernel(const int* __restrict__ text,
                            const float* __restrict__ atten)
{
    int b = blockIdx.x;
    int t = threadIdx.x;            /* 512 threads */
    __shared__ float sval[NT];
    __shared__ int   sidx[NT];
    __shared__ int   red[NT];

    int tv = text[b*NT + t];

    red[t] = (tv << 10) | (NT - 1 - t);
    __syncthreads();
    for (int s = NT/2; s > 0; s >>= 1) {
        if (t < s) red[t] = max(red[t], red[t+s]);
        __syncthreads();
    }
    int eos = NT - 1 - (red[0] & 1023);
    __syncthreads();

    red[t] = (tv != 0) ? 1 : 0;
    __syncthreads();
    for (int s = NT/2; s > 0; s >>= 1) {
        if (t < s) red[t] += red[t+s];
        __syncthreads();
    }
    int nz = red[0];
    __syncthreads();

    float v;
    if (t == 0 || t == eos) v = -1.0f;
    else                    v = atten[((size_t)b*NT + eos)*NT + t];
    if (tv == 0) v = 0.0f;

    sval[t] = v; sidx[t] = t;
    __syncthreads();

    for (int ksz = 2; ksz <= NT; ksz <<= 1) {
        for (int j = ksz >> 1; j > 0; j >>= 1) {
            int ixj = t ^ j;
            if (ixj > t) {
                float va = sval[t], vb = sval[ixj];
                int   ia = sidx[t], ib = sidx[ixj];
                bool aBefore = (va > vb) || (va == vb && ia < ib);
                bool desc = ((t & ksz) == 0);
                if (desc ? !aBefore : aBefore) {
                    sval[t] = vb; sval[ixj] = va;
                    sidx[t] = ib; sidx[ixj] = ia;
                }
            }
            __syncthreads();
        }
    }
    if (t < KTOP) g_idx[b*KTOP + t] = sidx[t];
    if (t == 0) {
        int lnn = nz - 2;
        if (lnn > KTOP) lnn = KTOP;
        if (lnn < 1) lnn = 1;
        g_lens[b] = lnn;
    }
}

/* ---------- gather + L2 normalize + LayerNorm (fused, one pass) ---------- */
__global__ void gather_ln_kernel(const float* __restrict__ features,
                                 const float* __restrict__ lnw,
                                 const float* __restrict__ lnb)
{
    int token = blockIdx.x;
    int b = token / KTOP;
    int src = g_idx[token];
    int tid = threadIdx.x;                /* 128 threads */
    const float* f = features + ((size_t)b*NT + src)*DIM;

    float v[4];
    float s1 = 0.f, s2 = 0.f;
#pragma unroll
    for (int i = 0; i < 4; i++) {
        v[i] = f[tid + i*128];
        s1 += v[i];
        s2 += v[i]*v[i];
    }
    __shared__ float r1[128], r2[128];
    r1[tid] = s1; r2[tid] = s2;
    __syncthreads();
    for (int s = 64; s > 0; s >>= 1) {
        if (tid < s) { r1[tid] += r1[tid+s]; r2[tid] += r2[tid+s]; }
        __syncthreads();
    }
    float sumf = r1[0], ss = r2[0];
    float inv  = 1.0f / (sqrtf(ss) + 1e-6f);
    float mean = sumf * inv * (1.0f/DIM);
    float et2  = ss * inv * inv * (1.0f/DIM);
    float var  = et2 - mean*mean;
    float rstd = rsqrtf(var + 1e-5f);

    float*  tokp = g_tok + (size_t)token*DIM;
    __half* qp   = g_qh  + (size_t)token*DIM;
#pragma unroll
    for (int i = 0; i < 4; i++) {
        int c = tid + i*128;
        float tvv = v[i] * inv;
        tokp[c] = tvv;
        qp[c]   = __float2half_rn((tvv - mean) * rstd * lnw[c] + lnb[c]);
    }
}

/* ------------- tensor-core flash attention: one block per (b,h) ---------- */
__global__ __launch_bounds__(ATT_THREADS)
void attn_tc()
{
    const int h = blockIdx.x, b = blockIdx.y;
    extern __shared__ __half ash[];
    __half* sQ = ash;
    __half* sK = ash + ATT_ROWS*64;
    __half* sV = ash + 2*ATT_ROWS*64;
    const int tid = threadIdx.x;
    const int wid = tid >> 5, lane = tid & 31;
    const int gid = lane >> 2, tig = lane & 3;
    const size_t tokbase = (size_t)b * KTOP;
    const __half* qkv = g_qkvh;

    /* load Q,K,V rows (swizzled 16B chunks); zero-pad rows >= KTOP */
    for (int i = tid; i < ATT_ROWS*8; i += ATT_THREADS) {
        int r = i >> 3, c = i & 7;
        uint4 zq = make_uint4(0,0,0,0), zk = zq, zv = zq;
        if (r < KTOP) {
            const __half* base = qkv + (tokbase + r)*1536 + h*64 + c*8;
            zq = *(const uint4*)(base);
            zk = *(const uint4*)(base + 512);
            zv = *(const uint4*)(base + 1024);
        }
        int off = r*64 + ((c ^ (r & 7)) << 3);
        *(uint4*)(sQ + off) = zq;
        *(uint4*)(sK + off) = zk;
        *(uint4*)(sV + off) = zv;
    }
    __syncthreads();

    const uint32_t uQ = smem_u32(sQ), uK = smem_u32(sK), uV = smem_u32(sV);
    const int wm = wid * 16;
    const int mrow = lane & 7, msel = lane >> 3;

    /* Q A-frags (reused across all chunks) */
    uint32_t aq[4][4];
    {
        int row = wm + mrow + ((msel & 1) << 3);
        int chalf = msel >> 1;
#pragma unroll
        for (int ks = 0; ks < 4; ks++) {
            int ch = 2*ks + chalf;
            ldsm4(aq[ks][0], aq[ks][1], aq[ks][2], aq[ks][3],
                  uQ + (uint32_t)(row*128 + ((ch ^ (row & 7)) << 4)));
        }
    }

    float mr0 = -1e30f, mr1 = -1e30f, l0 = 0.f, l1 = 0.f;
    float o[8][4];
#pragma unroll
    for (int i = 0; i < 8; i++)
#pragma unroll
        for (int c = 0; c < 4; c++) o[i][c] = 0.f;

#pragma unroll 1
    for (int kc = 0; kc < 3; kc++) {
        /* ---- S = Q @ K^T ---- */
        float sS[8][4];
#pragma unroll
        for (int i = 0; i < 8; i++)
#pragma unroll
            for (int c = 0; c < 4; c++) sS[i][c] = 0.f;

#pragma unroll
        for (int ks = 0; ks < 4; ks++) {
            int chalf = msel >> 1;
            int ch = 2*ks + chalf;
            int nro = mrow + ((msel & 1) << 3);
#pragma unroll
            for (int p = 0; p < 4; p++) {
                int nr = kc*64 + p*16 + nro;
                uint32_t r0, r1, r2, r3;
                ldsm4(r0, r1, r2, r3,
                      uK + (uint32_t)(nr*128 + ((ch ^ (nr & 7)) << 4)));
                mma_h(sS[2*p][0], sS[2*p][1], sS[2*p][2], sS[2*p][3],
                      aq[ks][0], aq[ks][1], aq[ks][2], aq[ks][3], r0, r2);
                mma_h(sS[2*p+1][0], sS[2*p+1][1], sS[2*p+1][2], sS[2*p+1][3],
                      aq[ks][0], aq[ks][1], aq[ks][2], aq[ks][3], r1, r3);
            }
        }

        /* scale + mask */
#pragma unroll
        for (int nf = 0; nf < 8; nf++)
#pragma unroll
            for (int c = 0; c < 4; c++) sS[nf][c] *= 0.125f;
        if (kc == 2) {
#pragma unroll
            for (int nf = 0; nf < 8; nf++) {
                int col = 128 + nf*8 + 2*tig;
                if (col     >= KTOP) { sS[nf][0] = -1e30f; sS[nf][2] = -1e30f; }
                if (col + 1 >= KTOP) { sS[nf][1] = -1e30f; sS[nf][3] = -1e30f; }
            }
        }

        /* online softmax */
        float cm0 = -1e30f, cm1 = -1e30f;
#pragma unroll
        for (int nf = 0; nf < 8; nf++) {
            cm0 = fmaxf(cm0, fmaxf(sS[nf][0], sS[nf][1]));
            cm1 = fmaxf(cm1, fmaxf(sS[nf][2], sS[nf][3]));
        }
        cm0 = fmaxf(cm0, __shfl_xor_sync(0xffffffffu, cm0, 1));
        cm0 = fmaxf(cm0, __shfl_xor_sync(0xffffffffu, cm0, 2));
        cm1 = fmaxf(cm1, __shfl_xor_sync(0xffffffffu, cm1, 1));
        cm1 = fmaxf(cm1, __shfl_xor_sync(0xffffffffu, cm1, 2));
        float nm0 = fmaxf(mr0, cm0), nm1 = fmaxf(mr1, cm1);
        float f0 = __expf(mr0 - nm0), f1 = __expf(mr1 - nm1);
        mr0 = nm0; mr1 = nm1;

        float ls0 = 0.f, ls1 = 0.f;
#pragma unroll
        for (int nf = 0; nf < 8; nf++) {
            sS[nf][0] = __expf(sS[nf][0] - nm0);
            sS[nf][1] = __expf(sS[nf][1] - nm0);
            sS[nf][2] = __expf(sS[nf][2] - nm1);
            sS[nf][3] = __expf(sS[nf][3] - nm1);
            ls0 += sS[nf][0] + sS[nf][1];
            ls1 += sS[nf][2] + sS[nf][3];
        }
        ls0 += __shfl_xor_sync(0xffffffffu, ls0, 1);
        ls0 += __shfl_xor_sync(0xffffffffu, ls0, 2);
        ls1 += __shfl_xor_sync(0xffffffffu, ls1, 1);
        ls1 += __shfl_xor_sync(0xffffffffu, ls1, 2);
        l0 = l0*f0 + ls0;
        l1 = l1*f1 + ls1;
#pragma unroll
        for (int df = 0; df < 8; df++) {
            o[df][0] *= f0; o[df][1] *= f0;
            o[df][2] *= f1; o[df][3] *= f1;
        }

        /* P (half A-frags) */
        uint32_t ap[4][4];
#pragma unroll
        for (int j = 0; j < 4; j++) {
            ap[j][0] = pack_h2(sS[2*j][0],   sS[2*j][1]);
            ap[j][1] = pack_h2(sS[2*j][2],   sS[2*j][3]);
            ap[j][2] = pack_h2(sS[2*j+1][0], sS[2*j+1][1]);
            ap[j][3] = pack_h2(sS[2*j+1][2], sS[2*j+1][3]);
        }

        /* ---- O += P @ V ---- */
#pragma unroll
        for (int j = 0; j < 4; j++) {
            int kr = kc*64 + j*16 + mrow + ((msel & 1) << 3);
            int chalf = msel >> 1;
#pragma unroll
            for (int p = 0; p < 4; p++) {
                int ch = 2*p + chalf;
                uint32_t r0, r1, r2, r3;
                ldsm4t(r0, r1, r2, r3,
                       uV + (uint32_t)(kr*128 + ((ch ^ (kr & 7)) << 4)));
                mma_h(o[2*p][0], o[2*p][1], o[2*p][2], o[2*p][3],
                      ap[j][0], ap[j][1], ap[j][2], ap[j][3], r0, r1);
                mma_h(o[2*p+1][0], o[2*p+1][1], o[2*p+1][2], o[2*p+1][3],
                      ap[j][0], ap[j][1], ap[j][2], ap[j][3], r2, r3);
            }
        }
    }

    /* store */
    float inv0 = 1.0f / l0, inv1 = 1.0f / l1;
    int r0g = wm + gid, r1g = wm + gid + 8;
#pragma unroll
    for (int df = 0; df < 8; df++) {
        int d = df*8 + 2*tig;
        if (r0g < KTOP)
            *(half2*)(g_sa + (tokbase + r0g)*512 + h*64 + d) =
                __floats2half2_rn(o[df][0]*inv0, o[df][1]*inv0);
        if (r1g < KTOP)
            *(half2*)(g_sa + (tokbase + r1g)*512 + h*64 + d) =
                __floats2half2_rn(o[df][2]*inv1, o[df][3]*inv1);
    }
}

/* --------------------------- BatchNorm (train) --------------------------- */
__global__ void bn_final()
{
    int c = threadIdx.x;                   /* 512 */
    float mean = g_s1[c] / (float)BKTOK;
    float var  = g_s2[c] / (float)BKTOK - mean*mean;
    g_mu[c]   = mean;
    g_rstd[c] = rsqrtf(var + 1e-5f);
}

__global__ void bn_apply(const float* __restrict__ bnw, const float* __restrict__ bnb)
{
    size_t i = (size_t)blockIdx.x*blockDim.x + threadIdx.x;
    if (i < (size_t)BKTOK*512) {
        int c = (int)(i & 511);
        float x = g_h[i];
        x = (x - g_mu[c]) * g_rstd[c] * bnw[c] + bnb[c];
        g_hh[i] = __float2half_rn(fmaxf(x, 0.f));
    }
}

/* ------------------------ variable-length max pool ----------------------- */
__global__ void pool_kernel(float* __restrict__ out)
{
    int b = blockIdx.x;
    int tid = threadIdx.x;                 /* 256 */
    int L = g_lens[b];
    float mx[4] = {-1e30f, -1e30f, -1e30f, -1e30f};
    const float* fp = g_feat + (size_t)b*KTOP*EDIM;
    int t = 0;
    for (; t + 1 < L; t += 2) {
#pragma unroll
        for (int i = 0; i < 4; i++) {
            float a = fp[(size_t)t*EDIM + tid + i*256];
            float c = fp[(size_t)(t+1)*EDIM + tid + i*256];
            mx[i] = fmaxf(mx[i], fmaxf(a, c));
        }
    }
    if (t < L) {
#pragma unroll
        for (int i = 0; i < 4; i++)
            mx[i] = fmaxf(mx[i], fp[(size_t)t*EDIM + tid + i*256]);
    }
#pragma unroll
    for (int i = 0; i < 4; i++)
        out[(size_t)b*EDIM + tid + i*256] = mx[i];
}

/* ------------------------------- launcher -------------------------------- */
extern "C" void kernel_launch(void* const* d_in, const int* in_sizes, int n_in,
                              void* d_out, int out_size)
{
    const float* features = (const float*)d_in[0];
    const int*   text     = (const int*)  d_in[1];
    const float* atten    = (const float*)d_in[2];
    const float* ln_q_w   = (const float*)d_in[3];
    const float* ln_q_b   = (const float*)d_in[4];
    const float* sa_in_w  = (const float*)d_in[5];
    const float* sa_in_b  = (const float*)d_in[6];
    const float* sa_out_w = (const float*)d_in[7];
    const float* sa_out_b = (const float*)d_in[8];
    const float* ref_w1   = (const float*)d_in[9];
    const float* ref_b1   = (const float*)d_in[10];
    const float* ref_w2   = (const float*)d_in[11];
    const float* ref_b2   = (const float*)d_in[12];
    const float* gscal    = (const float*)d_in[13];
    const float* lin_w    = (const float*)d_in[14];
    const float* lin_b    = (const float*)d_in[15];
    const float* mlp_w1   = (const float*)d_in[16];
    const float* mlp_b1   = (const float*)d_in[17];
    const float* bn_w     = (const float*)d_in[18];
    const float* bn_b     = (const float*)d_in[19];
    const float* mlp_w2   = (const float*)d_in[20];
    const float* mlp_b2   = (const float*)d_in[21];
    float* out = (float*)d_out;

    float *p_tok, *p_cap, *p_h, *p_feat;
    __half *p_qh, *p_qkvh, *p_sa, *p_sa2, *p_y1h, *p_tokh, *p_hh;
    __half *w_sain, *w_saout, *w_ref1, *w_ref2, *w_lin, *w_mlp1, *w_mlp2;
    cudaGetSymbolAddress((void**)&p_tok,  g_tok);
    cudaGetSymbolAddress((void**)&p_qh,   g_qh);
    cudaGetSymbolAddress((void**)&p_qkvh, g_qkvh);
    cudaGetSymbolAddress((void**)&p_sa,   g_sa);
    cudaGetSymbolAddress((void**)&p_sa2,  g_sa2);
    cudaGetSymbolAddress((void**)&p_y1h,  g_y1h);
    cudaGetSymbolAddress((void**)&p_tokh, g_tokh);
    cudaGetSymbolAddress((void**)&p_cap,  g_cap);
    cudaGetSymbolAddress((void**)&p_h,    g_h);
    cudaGetSymbolAddress((void**)&p_hh,   g_hh);
    cudaGetSymbolAddress((void**)&p_feat, g_feat);
    cudaGetSymbolAddress((void**)&w_sain,  g_w_sain);
    cudaGetSymbolAddress((void**)&w_saout, g_w_saout);
    cudaGetSymbolAddress((void**)&w_ref1,  g_w_ref1);
    cudaGetSymbolAddress((void**)&w_ref2,  g_w_ref2);
    cudaGetSymbolAddress((void**)&w_lin,   g_w_lin);
    cudaGetSymbolAddress((void**)&w_mlp1,  g_w_mlp1);
    cudaGetSymbolAddress((void**)&w_mlp2,  g_w_mlp2);

    cudaFuncSetAttribute(gemm_h16<0,0,0>, cudaFuncAttributeMaxDynamicSharedMemorySize, GEMM_SMEM);
    cudaFuncSetAttribute(gemm_h16<0,0,1>, cudaFuncAttributeMaxDynamicSharedMemorySize, GEMM_SMEM);
    cudaFuncSetAttribute(gemm_h16<0,1,0>, cudaFuncAttributeMaxDynamicSharedMemorySize, GEMM_SMEM);
    cudaFuncSetAttribute(gemm_h16<1,1,0>, cudaFuncAttributeMaxDynamicSharedMemorySize, GEMM_SMEM);
    cudaFuncSetAttribute(gemm_h16<2,1,0>, cudaFuncAttributeMaxDynamicSharedMemorySize, GEMM_SMEM);
    cudaFuncSetAttribute(gemm_h16<3,0,0>, cudaFuncAttributeMaxDynamicSharedMemorySize, GEMM_SMEM);
    cudaFuncSetAttribute(attn_tc, cudaFuncAttributeMaxDynamicSharedMemorySize, ATT_SMEM);

    const int MROWS = BKTOK;             /* 39168 = 306*128 */

    cvt_all_kernel<<<(CVN6+255)/256, 256>>>(sa_in_w, sa_out_w, ref_w1, ref_w2,
                                            lin_w, mlp_w1, mlp_w2);
    zero_stats_kernel<<<1, 512>>>();
    topk_kernel<<<BATCH, NT>>>(text, atten);
    gather_ln_kernel<<<BKTOK, 128>>>(features, ln_q_w, ln_q_b);

    /* qkv = LN(tok) @ sa_in_w^T + b  (half out) */
    gemm_h16<0,1,0><<<dim3(1536/128, MROWS/128), 256, GEMM_SMEM>>>(
        p_qh, w_sain, sa_in_b, p_qkvh, MROWS, 1536, 512, nullptr, nullptr);
    attn_tc<<<dim3(NHEADS, BATCH), ATT_THREADS, ATT_SMEM>>>();

    /* sa2 = sa @ sa_out_w^T + b  (half out) */
    gemm_h16<0,1,0><<<dim3(512/128, MROWS/128), 256, GEMM_SMEM>>>(
        p_sa, w_saout, sa_out_b, p_sa2, MROWS, 512, 512, nullptr, nullptr);
    /* y1 = gelu(sa2 @ ref_w1^T + b)  (half out) */
    gemm_h16<1,1,0><<<dim3(1024/128, MROWS/128), 256, GEMM_SMEM>>>(
        p_sa2, w_ref1, ref_b1, p_y1h, MROWS, 1024, 512, nullptr, nullptr);
    /* tok_h = tok + sigmoid(g)*(y1 @ ref_w2^T + b)  (half out) */
    gemm_h16<2,1,0><<<dim3(512/128, MROWS/128), 256, GEMM_SMEM>>>(
        p_y1h, w_ref2, ref_b2, p_tokh, MROWS, 512, 1024, p_tok, gscal);
    /* cap = tok_h @ lin_w^T + b  (fp32 out) */
    gemm_h16<0,0,0><<<dim3(1024/128, MROWS/128), 256, GEMM_SMEM>>>(
        p_tokh, w_lin, lin_b, p_cap, MROWS, 1024, 512, nullptr, nullptr);
    /* h = tok_h @ mlp_w1^T + b  (fp32 out + fused BN stats) */
    gemm_h16<0,0,1><<<dim3(512/128, MROWS/128), 256, GEMM_SMEM>>>(
        p_tokh, w_mlp1, mlp_b1, p_h, MROWS, 512, 512, nullptr, nullptr);
    bn_final<<<1, 512>>>();
    bn_apply<<<(int)(((size_t)BKTOK*512 + 255)/256), 256>>>(bn_w, bn_b);

    /* feat = relu_bn(h) @ mlp_w2^T + b + cap  (fp32 out) */
    gemm_h16<3,0,0><<<dim3(1024/128, MROWS/128), 256, GEMM_SMEM>>>(
        p_hh, w_mlp2, mlp_b2, p_feat, MROWS, 1024, 512, p_cap, nullptr);
    pool_kernel<<<BATCH, 256>>>(out);
}

// round 10
// speedup vs baseline: 6.0346x; 1.0705x over previous
#include <cuda_runtime.h>
#include <cuda_fp16.h>
#include <math.h>
#include <stdint.h>

#define BATCH 256
#define NT 512
#define DIM 512
#define KTOP 153
#define BKTOK (BATCH*KTOP)      /* 39168 = 306*128 */
#define EDIM 1024
#define NHEADS 8

#define GEMM_SMEM (4*16384)     /* 4 stages x (A 8KB + B 8KB) */
#define ATT_THREADS 320
#define ATT_ROWS 192            /* padded tile rows (3 chunks of 64) */
#define ATT_SMEM (3*ATT_ROWS*64*2)   /* Q,K,V half tiles: 73728 B */

/* ---------------- scratch (device globals; no allocation) ---------------- */
__device__ int    g_idx[BKTOK];
__device__ int    g_lens[BATCH];
__device__ float  g_tok[(size_t)BKTOK*DIM];        /* fp32 residual source */
__device__ __half g_qh[(size_t)BKTOK*DIM];         /* LN out (GEMM A) */
__device__ __half g_qkvh[(size_t)BKTOK*3*DIM];     /* half qkv */
__device__ __half g_sa[(size_t)BKTOK*DIM];
__device__ __half g_sa2[(size_t)BKTOK*DIM];
__device__ __half g_y1h[(size_t)BKTOK*2*DIM];
__device__ __half g_comb[(size_t)BKTOK*1024];      /* [tok_h | relu_bn_h] */
__device__ float  g_h[(size_t)BKTOK*DIM];
__device__ float  g_feat[(size_t)BKTOK*EDIM];
__device__ float  g_s1[512];
__device__ float  g_s2[512];
__device__ float  g_mu[512];
__device__ float  g_rstd[512];
/* half-converted weights */
__device__ __half g_w_sain[1536*512];
__device__ __half g_w_saout[512*512];
__device__ __half g_w_ref1[1024*512];
__device__ __half g_w_ref2[512*1024];
__device__ __half g_w_mlp1[512*512];
__device__ __half g_w_fin[1024*1024];              /* [lin_w | mlp_w2] */
__device__ float  g_bias_fin[1024];                /* lin_b + mlp_b2 */

/* ------------------------------ helpers ---------------------------------- */
__device__ __forceinline__ uint32_t smem_u32(const void* p) {
    uint32_t a;
    asm("{ .reg .u64 t; cvta.to.shared.u64 t, %1; cvt.u32.u64 %0, t; }"
        : "=r"(a) : "l"(p));
    return a;
}
#define CP_ASYNC16(dst, src) \
    asm volatile("cp.async.cg.shared.global [%0], [%1], 16;" :: "r"(dst), "l"(src))
#define CP_COMMIT()  asm volatile("cp.async.commit_group;" ::: "memory")
#define CP_WAIT_2()  asm volatile("cp.async.wait_group 2;" ::: "memory")

__device__ __forceinline__ void ldsm4(uint32_t& r0, uint32_t& r1,
                                      uint32_t& r2, uint32_t& r3, uint32_t addr) {
    asm volatile("ldmatrix.sync.aligned.m8n8.x4.shared.b16 {%0,%1,%2,%3}, [%4];"
                 : "=r"(r0), "=r"(r1), "=r"(r2), "=r"(r3) : "r"(addr));
}
__device__ __forceinline__ void ldsm4t(uint32_t& r0, uint32_t& r1,
                                       uint32_t& r2, uint32_t& r3, uint32_t addr) {
    asm volatile("ldmatrix.sync.aligned.m8n8.x4.trans.shared.b16 {%0,%1,%2,%3}, [%4];"
                 : "=r"(r0), "=r"(r1), "=r"(r2), "=r"(r3) : "r"(addr));
}
__device__ __forceinline__ void mma_h(float& d0, float& d1, float& d2, float& d3,
                                      uint32_t a0, uint32_t a1, uint32_t a2, uint32_t a3,
                                      uint32_t b0, uint32_t b1)
{
    asm volatile(
        "mma.sync.aligned.m16n8k16.row.col.f32.f16.f16.f32 "
        "{%0,%1,%2,%3}, {%4,%5,%6,%7}, {%8,%9}, {%0,%1,%2,%3};"
        : "+f"(d0), "+f"(d1), "+f"(d2), "+f"(d3)
        : "r"(a0), "r"(a1), "r"(a2), "r"(a3), "r"(b0), "r"(b1));
}
__device__ __forceinline__ uint32_t pack_h2(float a, float b) {
    half2 h = __floats2half2_rn(a, b);
    return *(uint32_t*)&h;
}

/* -------- weight conversion fp32 -> fp16 + stats zero + bias sum --------- */
/* counts in half2 units */
#define P0 393216                 /* sain  1536x512 */
#define P1 (P0+131072)            /* saout  512x512 */
#define P2 (P1+262144)            /* ref1  1024x512 */
#define P3 (P2+262144)            /* ref2   512x1024 */
#define P4 (P3+262144)            /* lin   1024x512 -> fin cols 0..511 */
#define P5 (P4+131072)            /* mlp1   512x512 */
#define P6 (P5+262144)            /* mlp2  1024x512 -> fin cols 512..1023 */
__global__ void cvt_all_kernel(const float* s_sain, const float* s_saout,
                               const float* s_ref1, const float* s_ref2,
                               const float* s_lin,  const float* s_mlp1,
                               const float* s_mlp2,
                               const float* lin_b,  const float* mlp_b2)
{
    int t = threadIdx.x;
    if (blockIdx.x == 0) {
        g_s1[t] = 0.f; g_s1[t+256] = 0.f;
        g_s2[t] = 0.f; g_s2[t+256] = 0.f;
    }
    if (blockIdx.x == 1) {
#pragma unroll
        for (int q = 0; q < 4; q++)
            g_bias_fin[t + q*256] = lin_b[t + q*256] + mlp_b2[t + q*256];
    }
    int i = blockIdx.x * 256 + t;
    if (i >= P6) return;
    if (i < P0) {
        float2 v = ((const float2*)s_sain)[i];
        ((half2*)g_w_sain)[i] = __floats2half2_rn(v.x, v.y);
    } else if (i < P1) {
        int o = i - P0;
        float2 v = ((const float2*)s_saout)[o];
        ((half2*)g_w_saout)[o] = __floats2half2_rn(v.x, v.y);
    } else if (i < P2) {
        int o = i - P1;
        float2 v = ((const float2*)s_ref1)[o];
        ((half2*)g_w_ref1)[o] = __floats2half2_rn(v.x, v.y);
    } else if (i < P3) {
        int o = i - P2;
        float2 v = ((const float2*)s_ref2)[o];
        ((half2*)g_w_ref2)[o] = __floats2half2_rn(v.x, v.y);
    } else if (i < P4) {
        int o = i - P3;                 /* lin: n = o/256, kk = o%256 */
        int n = o >> 8, kk = o & 255;
        float2 v = ((const float2*)s_lin)[o];
        ((half2*)g_w_fin)[n*512 + kk] = __floats2half2_rn(v.x, v.y);
    } else if (i < P5) {
        int o = i - P4;
        float2 v = ((const float2*)s_mlp1)[o];
        ((half2*)g_w_mlp1)[o] = __floats2half2_rn(v.x, v.y);
    } else {
        int o = i - P5;                 /* mlp2 -> right half of fin rows */
        int n = o >> 8, kk = o & 255;
        float2 v = ((const float2*)s_mlp2)[o];
        ((half2*)g_w_fin)[n*512 + 256 + kk] = __floats2half2_rn(v.x, v.y);
    }
}

/* ---- fp16 tensor-core GEMM (cp.async + ldmatrix): C = A @ W^T + bias ---- */
/* EPI: 0=bias 1=gelu(bias) 2=C=aux+sigmoid(g)*(acc+bias)                    */
/* OUTH: store half.  STATS: atomicAdd column sums/sumsq (for BN).           */
template<int EPI, int OUTH, int STATS>
__global__ __launch_bounds__(256, 2)
void gemm_h16(const __half* __restrict__ A, int lda,
              const __half* __restrict__ W,
              const float* __restrict__ bias, void* __restrict__ Cout, int ldc,
              int M, int N, int K,
              const float* __restrict__ aux, const float* __restrict__ gptr)
{
    extern __shared__ __half smh[];
    const int tid  = threadIdx.x;
    const int wid  = tid >> 5;
    const int lane = tid & 31;
    const int gid  = lane >> 2;
    const int tig  = lane & 3;
    const int wm   = (wid & 1) * 64;
    const int wn   = (wid >> 1) * 32;
    const int m0   = blockIdx.y * 128;
    const int n0   = blockIdx.x * 128;

    const uint32_t sbase = smem_u32(smh);

    uint32_t sto[2];
    const __half* srcA[2];
    const __half* srcB[2];
#pragma unroll
    for (int q = 0; q < 2; q++) {
        int id  = tid + q * 256;
        int row = id >> 2, cc = id & 3;
        sto[q]  = (uint32_t)(row * 64 + ((cc ^ (row & 3)) << 4));
        srcA[q] = A + (size_t)(m0 + row) * lda + cc * 8;
        srcB[q] = W + (size_t)(n0 + row) * K + cc * 8;
    }

    uint32_t aOff[4], bOff[2];
#pragma unroll
    for (int mt = 0; mt < 4; mt++) {
        int r  = wm + mt * 16 + (lane & 15);
        int ch = lane >> 4;
        aOff[mt] = (uint32_t)(r * 64 + ((ch ^ (r & 3)) << 4));
    }
#pragma unroll
    for (int njp = 0; njp < 2; njp++) {
        int r  = wn + njp * 16 + (lane & 7) + ((lane >> 4) << 3);
        int ch = (lane >> 3) & 1;
        bOff[njp] = (uint32_t)(8192 + r * 64 + ((ch ^ (r & 3)) << 4));
    }

    float acc[4][4][4];
#pragma unroll
    for (int i = 0; i < 4; i++)
#pragma unroll
        for (int j = 0; j < 4; j++)
#pragma unroll
            for (int c = 0; c < 4; c++) acc[i][j][c] = 0.f;

    const int nch = K >> 5;

    auto load_chunk = [&](int c) {
        uint32_t sb = sbase + (uint32_t)(c & 3) * 16384u;
        size_t ko = (size_t)c * 32;
#pragma unroll
        for (int q = 0; q < 2; q++) {
            CP_ASYNC16(sb + sto[q],        srcA[q] + ko);
            CP_ASYNC16(sb + 8192 + sto[q], srcB[q] + ko);
        }
    };

    load_chunk(0); CP_COMMIT();
    load_chunk(1); CP_COMMIT();
    load_chunk(2); CP_COMMIT();

    for (int c = 0; c < nch; c++) {
        CP_WAIT_2();
        __syncthreads();
        if (c + 3 < nch) load_chunk(c + 3);
        CP_COMMIT();

        uint32_t stb = sbase + (uint32_t)(c & 3) * 16384u;
#pragma unroll
        for (int ks = 0; ks < 2; ks++) {
            const uint32_t kx = (uint32_t)(ks << 5);
            uint32_t af[4][4], bf[2][4];
#pragma unroll
            for (int mt = 0; mt < 4; mt++)
                ldsm4(af[mt][0], af[mt][1], af[mt][2], af[mt][3],
                      stb + (aOff[mt] ^ kx));
#pragma unroll
            for (int njp = 0; njp < 2; njp++)
                ldsm4(bf[njp][0], bf[njp][1], bf[njp][2], bf[njp][3],
                      stb + (bOff[njp] ^ kx));
#pragma unroll
            for (int mt = 0; mt < 4; mt++)
#pragma unroll
                for (int nj = 0; nj < 4; nj++) {
                    const int njp = nj >> 1, pr = (nj & 1) << 1;
                    mma_h(acc[mt][nj][0], acc[mt][nj][1], acc[mt][nj][2], acc[mt][nj][3],
                          af[mt][0], af[mt][1], af[mt][2], af[mt][3],
                          bf[njp][pr], bf[njp][pr + 1]);
                }
        }
    }

    /* epilogue */
    float sg = 0.f;
    if (EPI == 2) sg = 1.0f / (1.0f + expf(-gptr[0]));
    float st1[8], st2[8];
    if (STATS) {
#pragma unroll
        for (int i = 0; i < 8; i++) { st1[i] = 0.f; st2[i] = 0.f; }
    }

#pragma unroll
    for (int mt = 0; mt < 4; mt++) {
#pragma unroll
        for (int nj = 0; nj < 4; nj++) {
            int r  = m0 + wm + mt * 16 + gid;
            int cc = n0 + wn + nj * 8 + 2 * tig;
            float b0v = bias[cc], b1v = bias[cc + 1];
            float v[4];
            v[0] = acc[mt][nj][0] + b0v;
            v[1] = acc[mt][nj][1] + b1v;
            v[2] = acc[mt][nj][2] + b0v;
            v[3] = acc[mt][nj][3] + b1v;
            if (EPI == 1) {
#pragma unroll
                for (int c = 0; c < 4; c++)
                    v[c] = 0.5f * v[c] * (1.0f + erff(v[c] * 0.70710678118654752f));
            }
            if (EPI == 2) {
                const float* x0 = aux + (size_t)r * N + cc;
                const float* x1 = aux + (size_t)(r + 8) * N + cc;
                v[0] = x0[0] + sg * v[0]; v[1] = x0[1] + sg * v[1];
                v[2] = x1[0] + sg * v[2]; v[3] = x1[1] + sg * v[3];
            }
            if (STATS) {
                st1[nj*2+0] += v[0] + v[2];
                st1[nj*2+1] += v[1] + v[3];
                st2[nj*2+0] += v[0]*v[0] + v[2]*v[2];
                st2[nj*2+1] += v[1]*v[1] + v[3]*v[3];
            }
            if (OUTH) {
                __half* Ch = (__half*)Cout;
                *(half2*)(Ch + (size_t)r * ldc + cc)       = __floats2half2_rn(v[0], v[1]);
                *(half2*)(Ch + (size_t)(r + 8) * ldc + cc) = __floats2half2_rn(v[2], v[3]);
            } else {
                float* Cf = (float*)Cout;
                *(float2*)(Cf + (size_t)r * ldc + cc)       = make_float2(v[0], v[1]);
                *(float2*)(Cf + (size_t)(r + 8) * ldc + cc) = make_float2(v[2], v[3]);
            }
        }
    }
    if (STATS) {
#pragma unroll
        for (int i = 0; i < 8; i++) {
            float a = st1[i], q = st2[i];
            a += __shfl_xor_sync(0xffffffffu, a, 4);
            a += __shfl_xor_sync(0xffffffffu, a, 8);
            a += __shfl_xor_sync(0xffffffffu, a, 16);
            q += __shfl_xor_sync(0xffffffffu, q, 4);
            q += __shfl_xor_sync(0xffffffffu, q, 8);
            q += __shfl_xor_sync(0xffffffffu, q, 16);
            if (gid == 0) {
                int col = n0 + wn + (i >> 1) * 8 + 2 * tig + (i & 1);
                atomicAdd(&g_s1[col], a);
                atomicAdd(&g_s2[col], q);
            }
        }
    }
}

/* ---------------- top-k selection (exact jax.lax.top_k order) ------------ */
__global__ void topk_kernel(const int* __restrict__ text,
                            const float* __restrict__ atten)
{
    int b = blockIdx.x;
    int t = threadIdx.x;            /* 512 threads */
    __shared__ float sval[NT];
    __shared__ int   sidx[NT];
    __shared__ int   red[NT];

    int tv = text[b*NT + t];

    red[t] = (tv << 10) | (NT - 1 - t);
    __syncthreads();
    for (int s = NT/2; s > 0; s >>= 1) {
        if (t < s) red[t] = max(red[t], red[t+s]);
        __syncthreads();
    }
    int eos = NT - 1 - (red[0] & 1023);
    __syncthreads();

    red[t] = (tv != 0) ? 1 : 0;
    __syncthreads();
    for (int s = NT/2; s > 0; s >>= 1) {
        if (t < s) red[t] += red[t+s];
        __syncthreads();
    }
    int nz = red[0];
    __syncthreads();

    float v;
    if (t == 0 || t == eos) v = -1.0f;
    else                    v = atten[((size_t)b*NT + eos)*NT + t];
    if (tv == 0) v = 0.0f;

    sval[t] = v; sidx[t] = t;
    __syncthreads();

    for (int ksz = 2; ksz <= NT; ksz <<= 1) {
        for (int j = ksz >> 1; j > 0; j >>= 1) {
            int ixj = t ^ j;
            if (ixj > t) {
                float va = sval[t], vb = sval[ixj];
                int   ia = sidx[t], ib = sidx[ixj];
                bool aBefore = (va > vb) || (va == vb && ia < ib);
                bool desc = ((t & ksz) == 0);
                if (desc ? !aBefore : aBefore) {
                    sval[t] = vb; sval[ixj] = va;
                    sidx[t] = ib; sidx[ixj] = ia;
                }
            }
            __syncthreads();
        }
    }
    if (t < KTOP) g_idx[b*KTOP + t] = sidx[t];
    if (t == 0) {
        int lnn = nz - 2;
        if (lnn > KTOP) lnn = KTOP;
        if (lnn < 1) lnn = 1;
        g_lens[b] = lnn;
    }
}

/* ---------- gather + L2 normalize + LayerNorm (fused, one pass) ---------- */
__global__ void gather_ln_kernel(const float* __restrict__ features,
                                 const float* __restrict__ lnw,
                                 const float* __restrict__ lnb)
{
    int token = blockIdx.x;
    int b = token / KTOP;
    int src = g_idx[token];
    int tid = threadIdx.x;                /* 128 threads */
    const float* f = features + ((size_t)b*NT + src)*DIM;

    float v[4];
    float s1 = 0.f, s2 = 0.f;
#pragma unroll
    for (int i = 0; i < 4; i++) {
        v[i] = f[tid + i*128];
        s1 += v[i];
        s2 += v[i]*v[i];
    }
    __shared__ float r1[128], r2[128];
    r1[tid] = s1; r2[tid] = s2;
    __syncthreads();
    for (int s = 64; s > 0; s >>= 1) {
        if (tid < s) { r1[tid] += r1[tid+s]; r2[tid] += r2[tid+s]; }
        __syncthreads();
    }
    float sumf = r1[0], ss = r2[0];
    float inv  = 1.0f / (sqrtf(ss) + 1e-6f);
    float mean = sumf * inv * (1.0f/DIM);
    float et2  = ss * inv * inv * (1.0f/DIM);
    float var  = et2 - mean*mean;
    float rstd = rsqrtf(var + 1e-5f);

    float*  tokp = g_tok + (size_t)token*DIM;
    __half* qp   = g_qh  + (size_t)token*DIM;
#pragma unroll
    for (int i = 0; i < 4; i++) {
        int c = tid + i*128;
        float tvv = v[i] * inv;
        tokp[c] = tvv;
        qp[c]   = __float2half_rn((tvv - mean) * rstd * lnw[c] + lnb[c]);
    }
}

/* ------------- tensor-core flash attention: one block per (b,h) ---------- */
__global__ __launch_bounds__(ATT_THREADS)
void attn_tc()
{
    const int h = blockIdx.x, b = blockIdx.y;
    extern __shared__ __half ash[];
    __half* sQ = ash;
    __half* sK = ash + ATT_ROWS*64;
    __half* sV = ash + 2*ATT_ROWS*64;
    const int tid = threadIdx.x;
    const int wid = tid >> 5, lane = tid & 31;
    const int gid = lane >> 2, tig = lane & 3;
    const size_t tokbase = (size_t)b * KTOP;
    const __half* qkv = g_qkvh;

    /* load Q,K,V rows (swizzled 16B chunks); zero-pad rows >= KTOP */
    for (int i = tid; i < ATT_ROWS*8; i += ATT_THREADS) {
        int r = i >> 3, c = i & 7;
        uint4 zq = make_uint4(0,0,0,0), zk = zq, zv = zq;
        if (r < KTOP) {
            const __half* base = qkv + (tokbase + r)*1536 + h*64 + c*8;
            zq = *(const uint4*)(base);
            zk = *(const uint4*)(base + 512);
            zv = *(const uint4*)(base + 1024);
        }
        int off = r*64 + ((c ^ (r & 7)) << 3);
        *(uint4*)(sQ + off) = zq;
        *(uint4*)(sK + off) = zk;
        *(uint4*)(sV + off) = zv;
    }
    __syncthreads();

    const uint32_t uQ = smem_u32(sQ), uK = smem_u32(sK), uV = smem_u32(sV);
    const int wm = wid * 16;
    const int mrow = lane & 7, msel = lane >> 3;

    /* Q A-frags (reused across all chunks) */
    uint32_t aq[4][4];
    {
        int row = wm + mrow + ((msel & 1) << 3);
        int chalf = msel >> 1;
#pragma unroll
        for (int ks = 0; ks < 4; ks++) {
            int ch = 2*ks + chalf;
            ldsm4(aq[ks][0], aq[ks][1], aq[ks][2], aq[ks][3],
                  uQ + (uint32_t)(row*128 + ((ch ^ (row & 7)) << 4)));
        }
    }

    float mr0 = -1e30f, mr1 = -1e30f, l0 = 0.f, l1 = 0.f;
    float o[8][4];
#pragma unroll
    for (int i = 0; i < 8; i++)
#pragma unroll
        for (int c = 0; c < 4; c++) o[i][c] = 0.f;

#pragma unroll 1
    for (int kc = 0; kc < 3; kc++) {
        /* ---- S = Q @ K^T ---- */
        float sS[8][4];
#pragma unroll
        for (int i = 0; i < 8; i++)
#pragma unroll
            for (int c = 0; c < 4; c++) sS[i][c] = 0.f;

#pragma unroll
        for (int ks = 0; ks < 4; ks++) {
            int chalf = msel >> 1;
            int ch = 2*ks + chalf;
            int nro = mrow + ((msel & 1) << 3);
#pragma unroll
            for (int p = 0; p < 4; p++) {
                int nr = kc*64 + p*16 + nro;
                uint32_t r0, r1, r2, r3;
                ldsm4(r0, r1, r2, r3,
                      uK + (uint32_t)(nr*128 + ((ch ^ (nr & 7)) << 4)));
                mma_h(sS[2*p][0], sS[2*p][1], sS[2*p][2], sS[2*p][3],
                      aq[ks][0], aq[ks][1], aq[ks][2], aq[ks][3], r0, r2);
                mma_h(sS[2*p+1][0], sS[2*p+1][1], sS[2*p+1][2], sS[2*p+1][3],
                      aq[ks][0], aq[ks][1], aq[ks][2], aq[ks][3], r1, r3);
            }
        }

        /* scale + mask */
#pragma unroll
        for (int nf = 0; nf < 8; nf++)
#pragma unroll
            for (int c = 0; c < 4; c++) sS[nf][c] *= 0.125f;
        if (kc == 2) {
#pragma unroll
            for (int nf = 0; nf < 8; nf++) {
                int col = 128 + nf*8 + 2*tig;
                if (col     >= KTOP) { sS[nf][0] = -1e30f; sS[nf][2] = -1e30f; }
                if (col + 1 >= KTOP) { sS[nf][1] = -1e30f; sS[nf][3] = -1e30f; }
            }
        }

        /* online softmax */
        float cm0 = -1e30f, cm1 = -1e30f;
#pragma unroll
        for (int nf = 0; nf < 8; nf++) {
            cm0 = fmaxf(cm0, fmaxf(sS[nf][0], sS[nf][1]));
            cm1 = fmaxf(cm1, fmaxf(sS[nf][2], sS[nf][3]));
        }
        cm0 = fmaxf(cm0, __shfl_xor_sync(0xffffffffu, cm0, 1));
        cm0 = fmaxf(cm0, __shfl_xor_sync(0xffffffffu, cm0, 2));
        cm1 = fmaxf(cm1, __shfl_xor_sync(0xffffffffu, cm1, 1));
        cm1 = fmaxf(cm1, __shfl_xor_sync(0xffffffffu, cm1, 2));
        float nm0 = fmaxf(mr0, cm0), nm1 = fmaxf(mr1, cm1);
        float f0 = __expf(mr0 - nm0), f1 = __expf(mr1 - nm1);
        mr0 = nm0; mr1 = nm1;

        float ls0 = 0.f, ls1 = 0.f;
#pragma unroll
        for (int nf = 0; nf < 8; nf++) {
            sS[nf][0] = __expf(sS[nf][0] - nm0);
            sS[nf][1] = __expf(sS[nf][1] - nm0);
            sS[nf][2] = __expf(sS[nf][2] - nm1);
            sS[nf][3] = __expf(sS[nf][3] - nm1);
            ls0 += sS[nf][0] + sS[nf][1];
            ls1 += sS[nf][2] + sS[nf][3];
        }
        ls0 += __shfl_xor_sync(0xffffffffu, ls0, 1);
        ls0 += __shfl_xor_sync(0xffffffffu, ls0, 2);
        ls1 += __shfl_xor_sync(0xffffffffu, ls1, 1);
        ls1 += __shfl_xor_sync(0xffffffffu, ls1, 2);
        l0 = l0*f0 + ls0;
        l1 = l1*f1 + ls1;
#pragma unroll
        for (int df = 0; df < 8; df++) {
            o[df][0] *= f0; o[df][1] *= f0;
            o[df][2] *= f1; o[df][3] *= f1;
        }

        /* P (half A-frags) */
        uint32_t ap[4][4];
#pragma unroll
        for (int j = 0; j < 4; j++) {
            ap[j][0] = pack_h2(sS[2*j][0],   sS[2*j][1]);
            ap[j][1] = pack_h2(sS[2*j][2],   sS[2*j][3]);
            ap[j][2] = pack_h2(sS[2*j+1][0], sS[2*j+1][1]);
            ap[j][3] = pack_h2(sS[2*j+1][2], sS[2*j+1][3]);
        }

        /* ---- O += P @ V ---- */
#pragma unroll
        for (int j = 0; j < 4; j++) {
            int kr = kc*64 + j*16 + mrow + ((msel & 1) << 3);
            int chalf = msel >> 1;
#pragma unroll
            for (int p = 0; p < 4; p++) {
                int ch = 2*p + chalf;
                uint32_t r0, r1, r2, r3;
                ldsm4t(r0, r1, r2, r3,
                       uV + (uint32_t)(kr*128 + ((ch ^ (kr & 7)) << 4)));
                mma_h(o[2*p][0], o[2*p][1], o[2*p][2], o[2*p][3],
                      ap[j][0], ap[j][1], ap[j][2], ap[j][3], r0, r1);
                mma_h(o[2*p+1][0], o[2*p+1][1], o[2*p+1][2], o[2*p+1][3],
                      ap[j][0], ap[j][1], ap[j][2], ap[j][3], r2, r3);
            }
        }
    }

    /* store */
    float inv0 = 1.0f / l0, inv1 = 1.0f / l1;
    int r0g = wm + gid, r1g = wm + gid + 8;
#pragma unroll
    for (int df = 0; df < 8; df++) {
        int d = df*8 + 2*tig;
        if (r0g < KTOP)
            *(half2*)(g_sa + (tokbase + r0g)*512 + h*64 + d) =
                __floats2half2_rn(o[df][0]*inv0, o[df][1]*inv0);
        if (r1g < KTOP)
            *(half2*)(g_sa + (tokbase + r1g)*512 + h*64 + d) =
                __floats2half2_rn(o[df][2]*inv1, o[df][3]*inv1);
    }
}

/* --------------------------- BatchNorm (train) --------------------------- */
__global__ void bn_final()
{
    int c = threadIdx.x;                   /* 512 */
    float mean = g_s1[c] / (float)BKTOK;
    float var  = g_s2[c] / (float)BKTOK - mean*mean;
    g_mu[c]   = mean;
    g_rstd[c] = rsqrtf(var + 1e-5f);
}

__global__ void bn_apply(const float* __restrict__ bnw, const float* __restrict__ bnb)
{
    size_t i = (size_t)blockIdx.x*blockDim.x + threadIdx.x;
    if (i < (size_t)BKTOK*512) {
        int c = (int)(i & 511);
        size_t row = i >> 9;
        float x = g_h[i];
        x = (x - g_mu[c]) * g_rstd[c] * bnw[c] + bnb[c];
        g_comb[row*1024 + 512 + c] = __float2half_rn(fmaxf(x, 0.f));
    }
}

/* ------------------------ variable-length max pool ----------------------- */
__global__ void pool_kernel(float* __restrict__ out)
{
    int b = blockIdx.x;
    int col = blockIdx.y * 256 + threadIdx.x;
    int L = g_lens[b];
    const float* fp = g_feat + (size_t)b*KTOP*EDIM + col;
    float mx = -1e30f;
    int t = 0;
    for (; t + 1 < L; t += 2)
        mx = fmaxf(mx, fmaxf(fp[(size_t)t*EDIM], fp[(size_t)(t+1)*EDIM]));
    if (t < L) mx = fmaxf(mx, fp[(size_t)t*EDIM]);
    out[(size_t)b*EDIM + col] = mx;
}

/* ------------------------------- launcher -------------------------------- */
extern "C" void kernel_launch(void* const* d_in, const int* in_sizes, int n_in,
                              void* d_out, int out_size)
{
    const float* features = (const float*)d_in[0];
    const int*   text     = (const int*)  d_in[1];
    const float* atten    = (const float*)d_in[2];
    const float* ln_q_w   = (const float*)d_in[3];
    const float* ln_q_b   = (const float*)d_in[4];
    const float* sa_in_w  = (const float*)d_in[5];
    const float* sa_in_b  = (const float*)d_in[6];
    const float* sa_out_w = (const float*)d_in[7];
    const float* sa_out_b = (const float*)d_in[8];
    const float* ref_w1   = (const float*)d_in[9];
    const float* ref_b1   = (const float*)d_in[10];
    const float* ref_w2   = (const float*)d_in[11];
    const float* ref_b2   = (const float*)d_in[12];
    const float* gscal    = (const float*)d_in[13];
    const float* lin_w    = (const float*)d_in[14];
    const float* lin_b    = (const float*)d_in[15];
    const float* mlp_w1   = (const float*)d_in[16];
    const float* mlp_b1   = (const float*)d_in[17];
    const float* bn_w     = (const float*)d_in[18];
    const float* bn_b     = (const float*)d_in[19];
    const float* mlp_w2   = (const float*)d_in[20];
    const float* mlp_b2   = (const float*)d_in[21];
    float* out = (float*)d_out;

    float *p_tok, *p_h, *p_feat, *p_bfin;
    __half *p_qh, *p_qkvh, *p_sa, *p_sa2, *p_y1h, *p_comb;
    __half *w_sain, *w_saout, *w_ref1, *w_ref2, *w_mlp1, *w_fin;
    cudaGetSymbolAddress((void**)&p_tok,  g_tok);
    cudaGetSymbolAddress((void**)&p_qh,   g_qh);
    cudaGetSymbolAddress((void**)&p_qkvh, g_qkvh);
    cudaGetSymbolAddress((void**)&p_sa,   g_sa);
    cudaGetSymbolAddress((void**)&p_sa2,  g_sa2);
    cudaGetSymbolAddress((void**)&p_y1h,  g_y1h);
    cudaGetSymbolAddress((void**)&p_comb, g_comb);
    cudaGetSymbolAddress((void**)&p_h,    g_h);
    cudaGetSymbolAddress((void**)&p_feat, g_feat);
    cudaGetSymbolAddress((void**)&p_bfin, g_bias_fin);
    cudaGetSymbolAddress((void**)&w_sain,  g_w_sain);
    cudaGetSymbolAddress((void**)&w_saout, g_w_saout);
    cudaGetSymbolAddress((void**)&w_ref1,  g_w_ref1);
    cudaGetSymbolAddress((void**)&w_ref2,  g_w_ref2);
    cudaGetSymbolAddress((void**)&w_mlp1,  g_w_mlp1);
    cudaGetSymbolAddress((void**)&w_fin,   g_w_fin);

    cudaFuncSetAttribute(gemm_h16<0,0,0>, cudaFuncAttributeMaxDynamicSharedMemorySize, GEMM_SMEM);
    cudaFuncSetAttribute(gemm_h16<0,0,1>, cudaFuncAttributeMaxDynamicSharedMemorySize, GEMM_SMEM);
    cudaFuncSetAttribute(gemm_h16<0,1,0>, cudaFuncAttributeMaxDynamicSharedMemorySize, GEMM_SMEM);
    cudaFuncSetAttribute(gemm_h16<1,1,0>, cudaFuncAttributeMaxDynamicSharedMemorySize, GEMM_SMEM);
    cudaFuncSetAttribute(gemm_h16<2,1,0>, cudaFuncAttributeMaxDynamicSharedMemorySize, GEMM_SMEM);
    cudaFuncSetAttribute(attn_tc, cudaFuncAttributeMaxDynamicSharedMemorySize, ATT_SMEM);

    const int MROWS = BKTOK;             /* 39168 = 306*128 */

    cvt_all_kernel<<<(P6+255)/256, 256>>>(sa_in_w, sa_out_w, ref_w1, ref_w2,
                                          lin_w, mlp_w1, mlp_w2, lin_b, mlp_b2);
    topk_kernel<<<BATCH, NT>>>(text, atten);
    gather_ln_kernel<<<BKTOK, 128>>>(features, ln_q_w, ln_q_b);

    /* qkv = LN(tok) @ sa_in_w^T + b  (half out) */
    gemm_h16<0,1,0><<<dim3(1536/128, MROWS/128), 256, GEMM_SMEM>>>(
        p_qh, 512, w_sain, sa_in_b, p_qkvh, 1536, MROWS, 1536, 512, nullptr, nullptr);
    attn_tc<<<dim3(NHEADS, BATCH), ATT_THREADS, ATT_SMEM>>>();

    /* sa2 = sa @ sa_out_w^T + b  (half out) */
    gemm_h16<0,1,0><<<dim3(512/128, MROWS/128), 256, GEMM_SMEM>>>(
        p_sa, 512, w_saout, sa_out_b, p_sa2, 512, MROWS, 512, 512, nullptr, nullptr);
    /* y1 = gelu(sa2 @ ref_w1^T + b)  (half out) */
    gemm_h16<1,1,0><<<dim3(1024/128, MROWS/128), 256, GEMM_SMEM>>>(
        p_sa2, 512, w_ref1, ref_b1, p_y1h, 1024, MROWS, 1024, 512, nullptr, nullptr);
    /* comb[:,0:512] = tok + sigmoid(g)*(y1 @ ref_w2^T + b)  (half out, ldc=1024) */
    gemm_h16<2,1,0><<<dim3(512/128, MROWS/128), 256, GEMM_SMEM>>>(
        p_y1h, 1024, w_ref2, ref_b2, p_comb, 1024, MROWS, 512, 1024, p_tok, gscal);
    /* h = tok_h @ mlp_w1^T + b  (fp32 out + fused BN stats; A = comb cols 0..511) */
    gemm_h16<0,0,1><<<dim3(512/128, MROWS/128), 256, GEMM_SMEM>>>(
        p_comb, 1024, w_mlp1, mlp_b1, p_h, 512, MROWS, 512, 512, nullptr, nullptr);
    bn_final<<<1, 512>>>();
    bn_apply<<<(int)(((size_t)BKTOK*512 + 255)/256), 256>>>(bn_w, bn_b);

    /* feat = [tok_h | relu_bn_h] @ [lin_w | mlp_w2]^T + (lin_b + mlp_b2) */
    gemm_h16<0,0,0><<<dim3(1024/128, MROWS/128), 256, GEMM_SMEM>>>(
        p_comb, 1024, w_fin, p_bfin, p_feat, 1024, MROWS, 1024, 1024, nullptr, nullptr);
    pool_kernel<<<dim3(BATCH, 4), 256>>>(out);
}

// round 11
// speedup vs baseline: 6.7831x; 1.1240x over previous
#include <cuda_runtime.h>
#include <cuda_fp16.h>
#include <math.h>
#include <stdint.h>

#define BATCH 256
#define NT 512
#define DIM 512
#define KTOP 153
#define BKTOK (BATCH*KTOP)      /* 39168 = 306*128 */
#define EDIM 1024
#define NHEADS 8

#define GEMM_SMEM (4*16384)     /* 4 stages x (A 8KB + B 8KB) */
#define ATT_THREADS 320
#define ATT_ROWS 192            /* padded tile rows (3 chunks of 64) */
#define ATT_SMEM (3*ATT_ROWS*64*2)   /* Q,K,V half tiles: 73728 B */

/* ---------------- scratch (device globals; no allocation) ---------------- */
__device__ int    g_idx[BKTOK];
__device__ int    g_lens[BATCH];
__device__ float  g_tok[(size_t)BKTOK*DIM];        /* fp32 residual source */
__device__ __half g_qh[(size_t)BKTOK*DIM];         /* LN out (GEMM A) */
__device__ __half g_qkvh[(size_t)BKTOK*3*DIM];     /* half qkv */
__device__ __half g_sa[(size_t)BKTOK*DIM];
__device__ __half g_sa2[(size_t)BKTOK*DIM];
__device__ __half g_y1h[(size_t)BKTOK*2*DIM];
__device__ __half g_comb[(size_t)BKTOK*1024];      /* [tok_h | relu_bn_h] */
__device__ float  g_h[(size_t)BKTOK*DIM];
__device__ float  g_feat[(size_t)BKTOK*EDIM];
__device__ float  g_s1[512];
__device__ float  g_s2[512];
__device__ float  g_mu[512];
__device__ float  g_rstd[512];
/* half-converted weights */
__device__ __half g_w_sain[1536*512];
__device__ __half g_w_saout[512*512];
__device__ __half g_w_ref1[1024*512];
__device__ __half g_w_ref2[512*1024];
__device__ __half g_w_mlp1[512*512];
__device__ __half g_w_fin[1024*1024];              /* [lin_w | mlp_w2] */
__device__ float  g_bias_fin[1024];                /* lin_b + mlp_b2 */

/* ------------------------------ helpers ---------------------------------- */
__device__ __forceinline__ uint32_t smem_u32(const void* p) {
    uint32_t a;
    asm("{ .reg .u64 t; cvta.to.shared.u64 t, %1; cvt.u32.u64 %0, t; }"
        : "=r"(a) : "l"(p));
    return a;
}
#define CP_ASYNC16(dst, src) \
    asm volatile("cp.async.cg.shared.global [%0], [%1], 16;" :: "r"(dst), "l"(src))
#define CP_COMMIT()  asm volatile("cp.async.commit_group;" ::: "memory")
#define CP_WAIT_2()  asm volatile("cp.async.wait_group 2;" ::: "memory")

__device__ __forceinline__ void ldsm4(uint32_t& r0, uint32_t& r1,
                                      uint32_t& r2, uint32_t& r3, uint32_t addr) {
    asm volatile("ldmatrix.sync.aligned.m8n8.x4.shared.b16 {%0,%1,%2,%3}, [%4];"
                 : "=r"(r0), "=r"(r1), "=r"(r2), "=r"(r3) : "r"(addr));
}
__device__ __forceinline__ void ldsm4t(uint32_t& r0, uint32_t& r1,
                                       uint32_t& r2, uint32_t& r3, uint32_t addr) {
    asm volatile("ldmatrix.sync.aligned.m8n8.x4.trans.shared.b16 {%0,%1,%2,%3}, [%4];"
                 : "=r"(r0), "=r"(r1), "=r"(r2), "=r"(r3) : "r"(addr));
}
__device__ __forceinline__ void mma_h(float& d0, float& d1, float& d2, float& d3,
                                      uint32_t a0, uint32_t a1, uint32_t a2, uint32_t a3,
                                      uint32_t b0, uint32_t b1)
{
    asm volatile(
        "mma.sync.aligned.m16n8k16.row.col.f32.f16.f16.f32 "
        "{%0,%1,%2,%3}, {%4,%5,%6,%7}, {%8,%9}, {%0,%1,%2,%3};"
        : "+f"(d0), "+f"(d1), "+f"(d2), "+f"(d3)
        : "r"(a0), "r"(a1), "r"(a2), "r"(a3), "r"(b0), "r"(b1));
}
__device__ __forceinline__ uint32_t pack_h2(float a, float b) {
    half2 h = __floats2half2_rn(a, b);
    return *(uint32_t*)&h;
}

/* -------- weight conversion fp32 -> fp16 + stats zero + bias sum --------- */
/* counts in half2 units */
#define P0 393216                 /* sain  1536x512 */
#define P1 (P0+131072)            /* saout  512x512 */
#define P2 (P1+262144)            /* ref1  1024x512 */
#define P3 (P2+262144)            /* ref2   512x1024 */
#define P4 (P3+262144)            /* lin   1024x512 -> fin cols 0..511 */
#define P5 (P4+131072)            /* mlp1   512x512 */
#define P6 (P5+262144)            /* mlp2  1024x512 -> fin cols 512..1023 */
__global__ void cvt_all_kernel(const float* s_sain, const float* s_saout,
                               const float* s_ref1, const float* s_ref2,
                               const float* s_lin,  const float* s_mlp1,
                               const float* s_mlp2,
                               const float* lin_b,  const float* mlp_b2)
{
    int t = threadIdx.x;
    if (blockIdx.x == 0) {
        g_s1[t] = 0.f; g_s1[t+256] = 0.f;
        g_s2[t] = 0.f; g_s2[t+256] = 0.f;
    }
    if (blockIdx.x == 1) {
#pragma unroll
        for (int q = 0; q < 4; q++)
            g_bias_fin[t + q*256] = lin_b[t + q*256] + mlp_b2[t + q*256];
    }
    int i = blockIdx.x * 256 + t;
    if (i >= P6) return;
    if (i < P0) {
        float2 v = ((const float2*)s_sain)[i];
        ((half2*)g_w_sain)[i] = __floats2half2_rn(v.x, v.y);
    } else if (i < P1) {
        int o = i - P0;
        float2 v = ((const float2*)s_saout)[o];
        ((half2*)g_w_saout)[o] = __floats2half2_rn(v.x, v.y);
    } else if (i < P2) {
        int o = i - P1;
        float2 v = ((const float2*)s_ref1)[o];
        ((half2*)g_w_ref1)[o] = __floats2half2_rn(v.x, v.y);
    } else if (i < P3) {
        int o = i - P2;
        float2 v = ((const float2*)s_ref2)[o];
        ((half2*)g_w_ref2)[o] = __floats2half2_rn(v.x, v.y);
    } else if (i < P4) {
        int o = i - P3;                 /* lin: n = o/256, kk = o%256 */
        int n = o >> 8, kk = o & 255;
        float2 v = ((const float2*)s_lin)[o];
        ((half2*)g_w_fin)[n*512 + kk] = __floats2half2_rn(v.x, v.y);
    } else if (i < P5) {
        int o = i - P4;
        float2 v = ((const float2*)s_mlp1)[o];
        ((half2*)g_w_mlp1)[o] = __floats2half2_rn(v.x, v.y);
    } else {
        int o = i - P5;                 /* mlp2 -> right half of fin rows */
        int n = o >> 8, kk = o & 255;
        float2 v = ((const float2*)s_mlp2)[o];
        ((half2*)g_w_fin)[n*512 + 256 + kk] = __floats2half2_rn(v.x, v.y);
    }
}

/* ---- fp16 tensor-core GEMM (cp.async + ldmatrix): C = A @ W^T + bias ---- */
/* 128 threads, 4 warps, warp tile 64x64 (2x2 warp grid over 128x128 tile).  */
/* EPI: 0=bias 1=gelu(bias) 2=C=aux+sigmoid(g)*(acc+bias)                    */
/* OUTH: store half.  STATS: atomicAdd column sums/sumsq (for BN).           */
template<int EPI, int OUTH, int STATS>
__global__ __launch_bounds__(128, 2)
void gemm_h16(const __half* __restrict__ A, int lda,
              const __half* __restrict__ W,
              const float* __restrict__ bias, void* __restrict__ Cout, int ldc,
              int M, int N, int K,
              const float* __restrict__ aux, const float* __restrict__ gptr)
{
    extern __shared__ __half smh[];
    const int tid  = threadIdx.x;
    const int wid  = tid >> 5;           /* 0..3 */
    const int lane = tid & 31;
    const int gid  = lane >> 2;
    const int tig  = lane & 3;
    const int wm   = (wid & 1) * 64;
    const int wn   = (wid >> 1) * 64;
    const int m0   = blockIdx.y * 128;
    const int n0   = blockIdx.x * 128;

    const uint32_t sbase = smem_u32(smh);

    /* cp.async: 4 chunks per operand per thread (128 threads cover 128 rows x 4) */
    uint32_t sto[4];
    const __half* srcA[4];
    const __half* srcB[4];
#pragma unroll
    for (int q = 0; q < 4; q++) {
        int id  = tid + q * 128;
        int row = id >> 2, cc = id & 3;
        sto[q]  = (uint32_t)(row * 64 + ((cc ^ (row & 3)) << 4));
        srcA[q] = A + (size_t)(m0 + row) * lda + cc * 8;
        srcB[q] = W + (size_t)(n0 + row) * K + cc * 8;
    }

    uint32_t aOff[4], bOff[4];
#pragma unroll
    for (int mt = 0; mt < 4; mt++) {
        int r  = wm + mt * 16 + (lane & 15);
        int ch = lane >> 4;
        aOff[mt] = (uint32_t)(r * 64 + ((ch ^ (r & 3)) << 4));
    }
#pragma unroll
    for (int njp = 0; njp < 4; njp++) {
        int r  = wn + njp * 16 + (lane & 7) + ((lane >> 4) << 3);
        int ch = (lane >> 3) & 1;
        bOff[njp] = (uint32_t)(8192 + r * 64 + ((ch ^ (r & 3)) << 4));
    }

    float acc[4][8][4];
#pragma unroll
    for (int i = 0; i < 4; i++)
#pragma unroll
        for (int j = 0; j < 8; j++)
#pragma unroll
            for (int c = 0; c < 4; c++) acc[i][j][c] = 0.f;

    const int nch = K >> 5;

    auto load_chunk = [&](int c) {
        uint32_t sb = sbase + (uint32_t)(c & 3) * 16384u;
        size_t ko = (size_t)c * 32;
#pragma unroll
        for (int q = 0; q < 4; q++) {
            CP_ASYNC16(sb + sto[q],        srcA[q] + ko);
            CP_ASYNC16(sb + 8192 + sto[q], srcB[q] + ko);
        }
    };

    load_chunk(0); CP_COMMIT();
    load_chunk(1); CP_COMMIT();
    load_chunk(2); CP_COMMIT();

    for (int c = 0; c < nch; c++) {
        CP_WAIT_2();
        __syncthreads();
        if (c + 3 < nch) load_chunk(c + 3);
        CP_COMMIT();

        uint32_t stb = sbase + (uint32_t)(c & 3) * 16384u;
#pragma unroll
        for (int ks = 0; ks < 2; ks++) {
            const uint32_t kx = (uint32_t)(ks << 5);
            uint32_t af[4][4], bf[4][4];
#pragma unroll
            for (int mt = 0; mt < 4; mt++)
                ldsm4(af[mt][0], af[mt][1], af[mt][2], af[mt][3],
                      stb + (aOff[mt] ^ kx));
#pragma unroll
            for (int njp = 0; njp < 4; njp++)
                ldsm4(bf[njp][0], bf[njp][1], bf[njp][2], bf[njp][3],
                      stb + (bOff[njp] ^ kx));
#pragma unroll
            for (int mt = 0; mt < 4; mt++)
#pragma unroll
                for (int nj = 0; nj < 8; nj++) {
                    const int njp = nj >> 1, pr = (nj & 1) << 1;
                    mma_h(acc[mt][nj][0], acc[mt][nj][1], acc[mt][nj][2], acc[mt][nj][3],
                          af[mt][0], af[mt][1], af[mt][2], af[mt][3],
                          bf[njp][pr], bf[njp][pr + 1]);
                }
        }
    }

    /* epilogue */
    float sg = 0.f;
    if (EPI == 2) sg = 1.0f / (1.0f + expf(-gptr[0]));
    float st1[16], st2[16];
    if (STATS) {
#pragma unroll
        for (int i = 0; i < 16; i++) { st1[i] = 0.f; st2[i] = 0.f; }
    }

#pragma unroll
    for (int mt = 0; mt < 4; mt++) {
#pragma unroll
        for (int nj = 0; nj < 8; nj++) {
            int r  = m0 + wm + mt * 16 + gid;
            int cc = n0 + wn + nj * 8 + 2 * tig;
            float b0v = bias[cc], b1v = bias[cc + 1];
            float v[4];
            v[0] = acc[mt][nj][0] + b0v;
            v[1] = acc[mt][nj][1] + b1v;
            v[2] = acc[mt][nj][2] + b0v;
            v[3] = acc[mt][nj][3] + b1v;
            if (EPI == 1) {
#pragma unroll
                for (int c = 0; c < 4; c++)
                    v[c] = 0.5f * v[c] * (1.0f + erff(v[c] * 0.70710678118654752f));
            }
            if (EPI == 2) {
                const float* x0 = aux + (size_t)r * N + cc;
                const float* x1 = aux + (size_t)(r + 8) * N + cc;
                v[0] = x0[0] + sg * v[0]; v[1] = x0[1] + sg * v[1];
                v[2] = x1[0] + sg * v[2]; v[3] = x1[1] + sg * v[3];
            }
            if (STATS) {
                st1[nj*2+0] += v[0] + v[2];
                st1[nj*2+1] += v[1] + v[3];
                st2[nj*2+0] += v[0]*v[0] + v[2]*v[2];
                st2[nj*2+1] += v[1]*v[1] + v[3]*v[3];
            }
            if (OUTH) {
                __half* Ch = (__half*)Cout;
                *(half2*)(Ch + (size_t)r * ldc + cc)       = __floats2half2_rn(v[0], v[1]);
                *(half2*)(Ch + (size_t)(r + 8) * ldc + cc) = __floats2half2_rn(v[2], v[3]);
            } else {
                float* Cf = (float*)Cout;
                *(float2*)(Cf + (size_t)r * ldc + cc)       = make_float2(v[0], v[1]);
                *(float2*)(Cf + (size_t)(r + 8) * ldc + cc) = make_float2(v[2], v[3]);
            }
        }
    }
    if (STATS) {
#pragma unroll
        for (int i = 0; i < 16; i++) {
            float a = st1[i], q = st2[i];
            a += __shfl_xor_sync(0xffffffffu, a, 4);
            a += __shfl_xor_sync(0xffffffffu, a, 8);
            a += __shfl_xor_sync(0xffffffffu, a, 16);
            q += __shfl_xor_sync(0xffffffffu, q, 4);
            q += __shfl_xor_sync(0xffffffffu, q, 8);
            q += __shfl_xor_sync(0xffffffffu, q, 16);
            if (gid == 0) {
                int col = n0 + wn + (i >> 1) * 8 + 2 * tig + (i & 1);
                atomicAdd(&g_s1[col], a);
                atomicAdd(&g_s2[col], q);
            }
        }
    }
}

/* ---------------- top-k selection (exact jax.lax.top_k order) ------------ */
__global__ void topk_kernel(const int* __restrict__ text,
                            const float* __restrict__ atten)
{
    int b = blockIdx.x;
    int t = threadIdx.x;            /* 512 threads */
    __shared__ float sval[NT];
    __shared__ int   sidx[NT];
    __shared__ int   red[NT];

    int tv = text[b*NT + t];

    red[t] = (tv << 10) | (NT - 1 - t);
    __syncthreads();
    for (int s = NT/2; s > 0; s >>= 1) {
        if (t < s) red[t] = max(red[t], red[t+s]);
        __syncthreads();
    }
    int eos = NT - 1 - (red[0] & 1023);
    __syncthreads();

    red[t] = (tv != 0) ? 1 : 0;
    __syncthreads();
    for (int s = NT/2; s > 0; s >>= 1) {
        if (t < s) red[t] += red[t+s];
        __syncthreads();
    }
    int nz = red[0];
    __syncthreads();

    float v;
    if (t == 0 || t == eos) v = -1.0f;
    else                    v = atten[((size_t)b*NT + eos)*NT + t];
    if (tv == 0) v = 0.0f;

    sval[t] = v; sidx[t] = t;
    __syncthreads();

    for (int ksz = 2; ksz <= NT; ksz <<= 1) {
        for (int j = ksz >> 1; j > 0; j >>= 1) {
            int ixj = t ^ j;
            if (ixj > t) {
                float va = sval[t], vb = sval[ixj];
                int   ia = sidx[t], ib = sidx[ixj];
                bool aBefore = (va > vb) || (va == vb && ia < ib);
                bool desc = ((t & ksz) == 0);
                if (desc ? !aBefore : aBefore) {
                    sval[t] = vb; sval[ixj] = va;
                    sidx[t] = ib; sidx[ixj] = ia;
                }
            }
            __syncthreads();
        }
    }
    if (t < KTOP) g_idx[b*KTOP + t] = sidx[t];
    if (t == 0) {
        int lnn = nz - 2;
        if (lnn > KTOP) lnn = KTOP;
        if (lnn < 1) lnn = 1;
        g_lens[b] = lnn;
    }
}

/* ---------- gather + L2 normalize + LayerNorm (fused, one pass) ---------- */
__global__ void gather_ln_kernel(const float* __restrict__ features,
                                 const float* __restrict__ lnw,
                                 const float* __restrict__ lnb)
{
    int token = blockIdx.x;
    int b = token / KTOP;
    int src = g_idx[token];
    int tid = threadIdx.x;                /* 128 threads */
    const float* f = features + ((size_t)b*NT + src)*DIM;

    float v[4];
    float s1 = 0.f, s2 = 0.f;
#pragma unroll
    for (int i = 0; i < 4; i++) {
        v[i] = f[tid + i*128];
        s1 += v[i];
        s2 += v[i]*v[i];
    }
    __shared__ float r1[128], r2[128];
    r1[tid] = s1; r2[tid] = s2;
    __syncthreads();
    for (int s = 64; s > 0; s >>= 1) {
        if (tid < s) { r1[tid] += r1[tid+s]; r2[tid] += r2[tid+s]; }
        __syncthreads();
    }
    float sumf = r1[0], ss = r2[0];
    float inv  = 1.0f / (sqrtf(ss) + 1e-6f);
    float mean = sumf * inv * (1.0f/DIM);
    float et2  = ss * inv * inv * (1.0f/DIM);
    float var  = et2 - mean*mean;
    float rstd = rsqrtf(var + 1e-5f);

    float*  tokp = g_tok + (size_t)token*DIM;
    __half* qp   = g_qh  + (size_t)token*DIM;
#pragma unroll
    for (int i = 0; i < 4; i++) {
        int c = tid + i*128;
        float tvv = v[i] * inv;
        tokp[c] = tvv;
        qp[c]   = __float2half_rn((tvv - mean) * rstd * lnw[c] + lnb[c]);
    }
}

/* ------------- tensor-core flash attention: one block per (b,h) ---------- */
__global__ __launch_bounds__(ATT_THREADS)
void attn_tc()
{
    const int h = blockIdx.x, b = blockIdx.y;
    extern __shared__ __half ash[];
    __half* sQ = ash;
    __half* sK = ash + ATT_ROWS*64;
    __half* sV = ash + 2*ATT_ROWS*64;
    const int tid = threadIdx.x;
    const int wid = tid >> 5, lane = tid & 31;
    const int gid = lane >> 2, tig = lane & 3;
    const size_t tokbase = (size_t)b * KTOP;
    const __half* qkv = g_qkvh;

    /* load Q,K,V rows (swizzled 16B chunks); zero-pad rows >= KTOP */
    for (int i = tid; i < ATT_ROWS*8; i += ATT_THREADS) {
        int r = i >> 3, c = i & 7;
        uint4 zq = make_uint4(0,0,0,0), zk = zq, zv = zq;
        if (r < KTOP) {
            const __half* base = qkv + (tokbase + r)*1536 + h*64 + c*8;
            zq = *(const uint4*)(base);
            zk = *(const uint4*)(base + 512);
            zv = *(const uint4*)(base + 1024);
        }
        int off = r*64 + ((c ^ (r & 7)) << 3);
        *(uint4*)(sQ + off) = zq;
        *(uint4*)(sK + off) = zk;
        *(uint4*)(sV + off) = zv;
    }
    __syncthreads();

    const uint32_t uQ = smem_u32(sQ), uK = smem_u32(sK), uV = smem_u32(sV);
    const int wm = wid * 16;
    const int mrow = lane & 7, msel = lane >> 3;

    /* Q A-frags (reused across all chunks) */
    uint32_t aq[4][4];
    {
        int row = wm + mrow + ((msel & 1) << 3);
        int chalf = msel >> 1;
#pragma unroll
        for (int ks = 0; ks < 4; ks++) {
            int ch = 2*ks + chalf;
            ldsm4(aq[ks][0], aq[ks][1], aq[ks][2], aq[ks][3],
                  uQ + (uint32_t)(row*128 + ((ch ^ (row & 7)) << 4)));
        }
    }

    float mr0 = -1e30f, mr1 = -1e30f, l0 = 0.f, l1 = 0.f;
    float o[8][4];
#pragma unroll
    for (int i = 0; i < 8; i++)
#pragma unroll
        for (int c = 0; c < 4; c++) o[i][c] = 0.f;

#pragma unroll 1
    for (int kc = 0; kc < 3; kc++) {
        /* ---- S = Q @ K^T ---- */
        float sS[8][4];
#pragma unroll
        for (int i = 0; i < 8; i++)
#pragma unroll
            for (int c = 0; c < 4; c++) sS[i][c] = 0.f;

#pragma unroll
        for (int ks = 0; ks < 4; ks++) {
            int chalf = msel >> 1;
            int ch = 2*ks + chalf;
            int nro = mrow + ((msel & 1) << 3);
#pragma unroll
            for (int p = 0; p < 4; p++) {
                int nr = kc*64 + p*16 + nro;
                uint32_t r0, r1, r2, r3;
                ldsm4(r0, r1, r2, r3,
                      uK + (uint32_t)(nr*128 + ((ch ^ (nr & 7)) << 4)));
                mma_h(sS[2*p][0], sS[2*p][1], sS[2*p][2], sS[2*p][3],
                      aq[ks][0], aq[ks][1], aq[ks][2], aq[ks][3], r0, r2);
                mma_h(sS[2*p+1][0], sS[2*p+1][1], sS[2*p+1][2], sS[2*p+1][3],
                      aq[ks][0], aq[ks][1], aq[ks][2], aq[ks][3], r1, r3);
            }
        }

        /* scale + mask */
#pragma unroll
        for (int nf = 0; nf < 8; nf++)
#pragma unroll
            for (int c = 0; c < 4; c++) sS[nf][c] *= 0.125f;
        if (kc == 2) {
#pragma unroll
            for (int nf = 0; nf < 8; nf++) {
                int col = 128 + nf*8 + 2*tig;
                if (col     >= KTOP) { sS[nf][0] = -1e30f; sS[nf][2] = -1e30f; }
                if (col + 1 >= KTOP) { sS[nf][1] = -1e30f; sS[nf][3] = -1e30f; }
            }
        }

        /* online softmax */
        float cm0 = -1e30f, cm1 = -1e30f;
#pragma unroll
        for (int nf = 0; nf < 8; nf++) {
            cm0 = fmaxf(cm0, fmaxf(sS[nf][0], sS[nf][1]));
            cm1 = fmaxf(cm1, fmaxf(sS[nf][2], sS[nf][3]));
        }
        cm0 = fmaxf(cm0, __shfl_xor_sync(0xffffffffu, cm0, 1));
        cm0 = fmaxf(cm0, __shfl_xor_sync(0xffffffffu, cm0, 2));
        cm1 = fmaxf(cm1, __shfl_xor_sync(0xffffffffu, cm1, 1));
        cm1 = fmaxf(cm1, __shfl_xor_sync(0xffffffffu, cm1, 2));
        float nm0 = fmaxf(mr0, cm0), nm1 = fmaxf(mr1, cm1);
        float f0 = __expf(mr0 - nm0), f1 = __expf(mr1 - nm1);
        mr0 = nm0; mr1 = nm1;

        float ls0 = 0.f, ls1 = 0.f;
#pragma unroll
        for (int nf = 0; nf < 8; nf++) {
            sS[nf][0] = __expf(sS[nf][0] - nm0);
            sS[nf][1] = __expf(sS[nf][1] - nm0);
            sS[nf][2] = __expf(sS[nf][2] - nm1);
            sS[nf][3] = __expf(sS[nf][3] - nm1);
            ls0 += sS[nf][0] + sS[nf][1];
            ls1 += sS[nf][2] + sS[nf][3];
        }
        ls0 += __shfl_xor_sync(0xffffffffu, ls0, 1);
        ls0 += __shfl_xor_sync(0xffffffffu, ls0, 2);
        ls1 += __shfl_xor_sync(0xffffffffu, ls1, 1);
        ls1 += __shfl_xor_sync(0xffffffffu, ls1, 2);
        l0 = l0*f0 + ls0;
        l1 = l1*f1 + ls1;
#pragma unroll
        for (int df = 0; df < 8; df++) {
            o[df][0] *= f0; o[df][1] *= f0;
            o[df][2] *= f1; o[df][3] *= f1;
        }

        /* P (half A-frags) */
        uint32_t ap[4][4];
#pragma unroll
        for (int j = 0; j < 4; j++) {
            ap[j][0] = pack_h2(sS[2*j][0],   sS[2*j][1]);
            ap[j][1] = pack_h2(sS[2*j][2],   sS[2*j][3]);
            ap[j][2] = pack_h2(sS[2*j+1][0], sS[2*j+1][1]);
            ap[j][3] = pack_h2(sS[2*j+1][2], sS[2*j+1][3]);
        }

        /* ---- O += P @ V ---- */
#pragma unroll
        for (int j = 0; j < 4; j++) {
            int kr = kc*64 + j*16 + mrow + ((msel & 1) << 3);
            int chalf = msel >> 1;
#pragma unroll
            for (int p = 0; p < 4; p++) {
                int ch = 2*p + chalf;
                uint32_t r0, r1, r2, r3;
                ldsm4t(r0, r1, r2, r3,
                       uV + (uint32_t)(kr*128 + ((ch ^ (kr & 7)) << 4)));
                mma_h(o[2*p][0], o[2*p][1], o[2*p][2], o[2*p][3],
                      ap[j][0], ap[j][1], ap[j][2], ap[j][3], r0, r1);
                mma_h(o[2*p+1][0], o[2*p+1][1], o[2*p+1][2], o[2*p+1][3],
                      ap[j][0], ap[j][1], ap[j][2], ap[j][3], r2, r3);
            }
        }
    }

    /* store */
    float inv0 = 1.0f / l0, inv1 = 1.0f / l1;
    int r0g = wm + gid, r1g = wm + gid + 8;
#pragma unroll
    for (int df = 0; df < 8; df++) {
        int d = df*8 + 2*tig;
        if (r0g < KTOP)
            *(half2*)(g_sa + (tokbase + r0g)*512 + h*64 + d) =
                __floats2half2_rn(o[df][0]*inv0, o[df][1]*inv0);
        if (r1g < KTOP)
            *(half2*)(g_sa + (tokbase + r1g)*512 + h*64 + d) =
                __floats2half2_rn(o[df][2]*inv1, o[df][3]*inv1);
    }
}

/* --------------------------- BatchNorm (train) --------------------------- */
__global__ void bn_final()
{
    int c = threadIdx.x;                   /* 512 */
    float mean = g_s1[c] / (float)BKTOK;
    float var  = g_s2[c] / (float)BKTOK - mean*mean;
    g_mu[c]   = mean;
    g_rstd[c] = rsqrtf(var + 1e-5f);
}

__global__ void bn_apply(const float* __restrict__ bnw, const float* __restrict__ bnb)
{
    size_t i = (size_t)blockIdx.x*blockDim.x + threadIdx.x;
    if (i < (size_t)BKTOK*512) {
        int c = (int)(i & 511);
        size_t row = i >> 9;
        float x = g_h[i];
        x = (x - g_mu[c]) * g_rstd[c] * bnw[c] + bnb[c];
        g_comb[row*1024 + 512 + c] = __float2half_rn(fmaxf(x, 0.f));
    }
}

/* ------------------------ variable-length max pool ----------------------- */
__global__ void pool_kernel(float* __restrict__ out)
{
    int b = blockIdx.x;
    int col = blockIdx.y * 256 + threadIdx.x;
    int L = g_lens[b];
    const float* fp = g_feat + (size_t)b*KTOP*EDIM + col;
    float mx = -1e30f;
    int t = 0;
    for (; t + 1 < L; t += 2)
        mx = fmaxf(mx, fmaxf(fp[(size_t)t*EDIM], fp[(size_t)(t+1)*EDIM]));
    if (t < L) mx = fmaxf(mx, fp[(size_t)t*EDIM]);
    out[(size_t)b*EDIM + col] = mx;
}

/* ------------------------------- launcher -------------------------------- */
extern "C" void kernel_launch(void* const* d_in, const int* in_sizes, int n_in,
                              void* d_out, int out_size)
{
    const float* features = (const float*)d_in[0];
    const int*   text     = (const int*)  d_in[1];
    const float* atten    = (const float*)d_in[2];
    const float* ln_q_w   = (const float*)d_in[3];
    const float* ln_q_b   = (const float*)d_in[4];
    const float* sa_in_w  = (const float*)d_in[5];
    const float* sa_in_b  = (const float*)d_in[6];
    const float* sa_out_w = (const float*)d_in[7];
    const float* sa_out_b = (const float*)d_in[8];
    const float* ref_w1   = (const float*)d_in[9];
    const float* ref_b1   = (const float*)d_in[10];
    const float* ref_w2   = (const float*)d_in[11];
    const float* ref_b2   = (const float*)d_in[12];
    const float* gscal    = (const float*)d_in[13];
    const float* lin_w    = (const float*)d_in[14];
    const float* lin_b    = (const float*)d_in[15];
    const float* mlp_w1   = (const float*)d_in[16];
    const float* mlp_b1   = (const float*)d_in[17];
    const float* bn_w     = (const float*)d_in[18];
    const float* bn_b     = (const float*)d_in[19];
    const float* mlp_w2   = (const float*)d_in[20];
    const float* mlp_b2   = (const float*)d_in[21];
    float* out = (float*)d_out;

    float *p_tok, *p_h, *p_feat, *p_bfin;
    __half *p_qh, *p_qkvh, *p_sa, *p_sa2, *p_y1h, *p_comb;
    __half *w_sain, *w_saout, *w_ref1, *w_ref2, *w_mlp1, *w_fin;
    cudaGetSymbolAddress((void**)&p_tok,  g_tok);
    cudaGetSymbolAddress((void**)&p_qh,   g_qh);
    cudaGetSymbolAddress((void**)&p_qkvh, g_qkvh);
    cudaGetSymbolAddress((void**)&p_sa,   g_sa);
    cudaGetSymbolAddress((void**)&p_sa2,  g_sa2);
    cudaGetSymbolAddress((void**)&p_y1h,  g_y1h);
    cudaGetSymbolAddress((void**)&p_comb, g_comb);
    cudaGetSymbolAddress((void**)&p_h,    g_h);
    cudaGetSymbolAddress((void**)&p_feat, g_feat);
    cudaGetSymbolAddress((void**)&p_bfin, g_bias_fin);
    cudaGetSymbolAddress((void**)&w_sain,  g_w_sain);
    cudaGetSymbolAddress((void**)&w_saout, g_w_saout);
    cudaGetSymbolAddress((void**)&w_ref1,  g_w_ref1);
    cudaGetSymbolAddress((void**)&w_ref2,  g_w_ref2);
    cudaGetSymbolAddress((void**)&w_mlp1,  g_w_mlp1);
    cudaGetSymbolAddress((void**)&w_fin,   g_w_fin);

    cudaFuncSetAttribute(gemm_h16<0,0,0>, cudaFuncAttributeMaxDynamicSharedMemorySize, GEMM_SMEM);
    cudaFuncSetAttribute(gemm_h16<0,0,1>, cudaFuncAttributeMaxDynamicSharedMemorySize, GEMM_SMEM);
    cudaFuncSetAttribute(gemm_h16<0,1,0>, cudaFuncAttributeMaxDynamicSharedMemorySize, GEMM_SMEM);
    cudaFuncSetAttribute(gemm_h16<1,1,0>, cudaFuncAttributeMaxDynamicSharedMemorySize, GEMM_SMEM);
    cudaFuncSetAttribute(gemm_h16<2,1,0>, cudaFuncAttributeMaxDynamicSharedMemorySize, GEMM_SMEM);
    cudaFuncSetAttribute(attn_tc, cudaFuncAttributeMaxDynamicSharedMemorySize, ATT_SMEM);

    const int MROWS = BKTOK;             /* 39168 = 306*128 */

    cvt_all_kernel<<<(P6+255)/256, 256>>>(sa_in_w, sa_out_w, ref_w1, ref_w2,
                                          lin_w, mlp_w1, mlp_w2, lin_b, mlp_b2);
    topk_kernel<<<BATCH, NT>>>(text, atten);
    gather_ln_kernel<<<BKTOK, 128>>>(features, ln_q_w, ln_q_b);

    /* qkv = LN(tok) @ sa_in_w^T + b  (half out) */
    gemm_h16<0,1,0><<<dim3(1536/128, MROWS/128), 128, GEMM_SMEM>>>(
        p_qh, 512, w_sain, sa_in_b, p_qkvh, 1536, MROWS, 1536, 512, nullptr, nullptr);
    attn_tc<<<dim3(NHEADS, BATCH), ATT_THREADS, ATT_SMEM>>>();

    /* sa2 = sa @ sa_out_w^T + b  (half out) */
    gemm_h16<0,1,0><<<dim3(512/128, MROWS/128), 128, GEMM_SMEM>>>(
        p_sa, 512, w_saout, sa_out_b, p_sa2, 512, MROWS, 512, 512, nullptr, nullptr);
    /* y1 = gelu(sa2 @ ref_w1^T + b)  (half out) */
    gemm_h16<1,1,0><<<dim3(1024/128, MROWS/128), 128, GEMM_SMEM>>>(
        p_sa2, 512, w_ref1, ref_b1, p_y1h, 1024, MROWS, 1024, 512, nullptr, nullptr);
    /* comb[:,0:512] = tok + sigmoid(g)*(y1 @ ref_w2^T + b)  (half out, ldc=1024) */
    gemm_h16<2,1,0><<<dim3(512/128, MROWS/128), 128, GEMM_SMEM>>>(
        p_y1h, 1024, w_ref2, ref_b2, p_comb, 1024, MROWS, 512, 1024, p_tok, gscal);
    /* h = tok_h @ mlp_w1^T + b  (fp32 out + fused BN stats; A = comb cols 0..511) */
    gemm_h16<0,0,1><<<dim3(512/128, MROWS/128), 128, GEMM_SMEM>>>(
        p_comb, 1024, w_mlp1, mlp_b1, p_h, 512, MROWS, 512, 512, nullptr, nullptr);
    bn_final<<<1, 512>>>();
    bn_apply<<<(int)(((size_t)BKTOK*512 + 255)/256), 256>>>(bn_w, bn_b);

    /* feat = [tok_h | relu_bn_h] @ [lin_w | mlp_w2]^T + (lin_b + mlp_b2) */
    gemm_h16<0,0,0><<<dim3(1024/128, MROWS/128), 128, GEMM_SMEM>>>(
        p_comb, 1024, w_fin, p_bfin, p_feat, 1024, MROWS, 1024, 1024, nullptr, nullptr);
    pool_kernel<<<dim3(BATCH, 4), 256>>>(out);
}

// round 12
// speedup vs baseline: 7.1687x; 1.0568x over previous
#include <cuda_runtime.h>
#include <cuda_fp16.h>
#include <math.h>
#include <stdint.h>

#define BATCH 256
#define NT 512
#define DIM 512
#define KTOP 153
#define BKTOK (BATCH*KTOP)      /* 39168 = 306*128 */
#define EDIM 1024
#define NHEADS 8

#define GEMM_SMEM (4*16384)     /* 4 stages x (A 8KB + B 8KB) */
#define ATT_THREADS 320
#define ATT_ROWS 192            /* padded tile rows (3 chunks of 64) */
#define ATT_SMEM (3*ATT_ROWS*64*2)   /* Q,K,V half tiles: 73728 B */

/* ---------------- scratch (device globals; no allocation) ---------------- */
__device__ int    g_idx[BKTOK];
__device__ int    g_lens[BATCH];
__device__ float  g_tok[(size_t)BKTOK*DIM];        /* fp32 residual source */
__device__ __half g_qh[(size_t)BKTOK*DIM];         /* LN out (GEMM A) */
__device__ __half g_qkvh[(size_t)BKTOK*3*DIM];     /* half qkv */
__device__ __half g_sa[(size_t)BKTOK*DIM];
__device__ __half g_y1h[(size_t)BKTOK*2*DIM];
__device__ __half g_comb[(size_t)BKTOK*1024];      /* [tok_h | relu_bn_h] */
__device__ __half g_hh[(size_t)BKTOK*DIM];         /* pre-BN h (half) */
__device__ float  g_feat[(size_t)BKTOK*EDIM];
__device__ float  g_s1[512];
__device__ float  g_s2[512];
__device__ float  g_mu[512];
__device__ float  g_rstd[512];
/* half-converted weights */
__device__ __half g_w_sain[1536*512];
__device__ __half g_w_soT[512*512];                /* sa_out_w transposed */
__device__ __half g_w_ref1[1024*512];
__device__ __half g_w_ref2[512*1024];
__device__ __half g_w_mlp1[512*512];
__device__ __half g_w_fin[1024*1024];              /* [lin_w | mlp_w2] */
__device__ __half g_w_fuse[1024*512];              /* W_r1 @ W_so */
__device__ float  g_bias_fin[1024];                /* lin_b + mlp_b2 */
__device__ float  g_bfuse[1024];                   /* W_r1 @ b_so + b_r1 */
__device__ float  g_zero512[512];

/* ------------------------------ helpers ---------------------------------- */
__device__ __forceinline__ uint32_t smem_u32(const void* p) {
    uint32_t a;
    asm("{ .reg .u64 t; cvta.to.shared.u64 t, %1; cvt.u32.u64 %0, t; }"
        : "=r"(a) : "l"(p));
    return a;
}
#define CP_ASYNC16(dst, src) \
    asm volatile("cp.async.cg.shared.global [%0], [%1], 16;" :: "r"(dst), "l"(src))
#define CP_COMMIT()  asm volatile("cp.async.commit_group;" ::: "memory")
#define CP_WAIT_2()  asm volatile("cp.async.wait_group 2;" ::: "memory")

__device__ __forceinline__ void ldsm4(uint32_t& r0, uint32_t& r1,
                                      uint32_t& r2, uint32_t& r3, uint32_t addr) {
    asm volatile("ldmatrix.sync.aligned.m8n8.x4.shared.b16 {%0,%1,%2,%3}, [%4];"
                 : "=r"(r0), "=r"(r1), "=r"(r2), "=r"(r3) : "r"(addr));
}
__device__ __forceinline__ void ldsm4t(uint32_t& r0, uint32_t& r1,
                                       uint32_t& r2, uint32_t& r3, uint32_t addr) {
    asm volatile("ldmatrix.sync.aligned.m8n8.x4.trans.shared.b16 {%0,%1,%2,%3}, [%4];"
                 : "=r"(r0), "=r"(r1), "=r"(r2), "=r"(r3) : "r"(addr));
}
__device__ __forceinline__ void mma_h(float& d0, float& d1, float& d2, float& d3,
                                      uint32_t a0, uint32_t a1, uint32_t a2, uint32_t a3,
                                      uint32_t b0, uint32_t b1)
{
    asm volatile(
        "mma.sync.aligned.m16n8k16.row.col.f32.f16.f16.f32 "
        "{%0,%1,%2,%3}, {%4,%5,%6,%7}, {%8,%9}, {%0,%1,%2,%3};"
        : "+f"(d0), "+f"(d1), "+f"(d2), "+f"(d3)
        : "r"(a0), "r"(a1), "r"(a2), "r"(a3), "r"(b0), "r"(b1));
}
__device__ __forceinline__ uint32_t pack_h2(float a, float b) {
    half2 h = __floats2half2_rn(a, b);
    return *(uint32_t*)&h;
}

/* -------- weight conversion fp32 -> fp16 + stats zero + bias sum --------- */
/* counts in half2 units */
#define P0 393216                 /* sain  1536x512 */
#define P1 (P0+131072)            /* saout  512x512 -> TRANSPOSED g_w_soT */
#define P2 (P1+262144)            /* ref1  1024x512 */
#define P3 (P2+262144)            /* ref2   512x1024 */
#define P4 (P3+262144)            /* lin   1024x512 -> fin cols 0..511 */
#define P5 (P4+131072)            /* mlp1   512x512 */
#define P6 (P5+262144)            /* mlp2  1024x512 -> fin cols 512..1023 */
__global__ void cvt_all_kernel(const float* s_sain, const float* s_saout,
                               const float* s_ref1, const float* s_ref2,
                               const float* s_lin,  const float* s_mlp1,
                               const float* s_mlp2,
                               const float* lin_b,  const float* mlp_b2)
{
    int t = threadIdx.x;
    if (blockIdx.x == 0) {
        g_s1[t] = 0.f; g_s1[t+256] = 0.f;
        g_s2[t] = 0.f; g_s2[t+256] = 0.f;
        g_zero512[t] = 0.f; g_zero512[t+256] = 0.f;
    }
    if (blockIdx.x == 1) {
#pragma unroll
        for (int q = 0; q < 4; q++)
            g_bias_fin[t + q*256] = lin_b[t + q*256] + mlp_b2[t + q*256];
    }
    int i = blockIdx.x * 256 + t;
    if (i >= P6) return;
    if (i < P0) {
        float2 v = ((const float2*)s_sain)[i];
        ((half2*)g_w_sain)[i] = __floats2half2_rn(v.x, v.y);
    } else if (i < P1) {
        int o = i - P0;                 /* saout row-major [512 out, 512 in] */
        int k = o >> 8, c2 = o & 255;   /* k = out row, in cols 2c2, 2c2+1 */
        float2 v = ((const float2*)s_saout)[o];
        g_w_soT[(2*c2  )*512 + k] = __float2half_rn(v.x);
        g_w_soT[(2*c2+1)*512 + k] = __float2half_rn(v.y);
    } else if (i < P2) {
        int o = i - P1;
        float2 v = ((const float2*)s_ref1)[o];
        ((half2*)g_w_ref1)[o] = __floats2half2_rn(v.x, v.y);
    } else if (i < P3) {
        int o = i - P2;
        float2 v = ((const float2*)s_ref2)[o];
        ((half2*)g_w_ref2)[o] = __floats2half2_rn(v.x, v.y);
    } else if (i < P4) {
        int o = i - P3;                 /* lin: n = o/256, kk = o%256 */
        int n = o >> 8, kk = o & 255;
        float2 v = ((const float2*)s_lin)[o];
        ((half2*)g_w_fin)[n*512 + kk] = __floats2half2_rn(v.x, v.y);
    } else if (i < P5) {
        int o = i - P4;
        float2 v = ((const float2*)s_mlp1)[o];
        ((half2*)g_w_mlp1)[o] = __floats2half2_rn(v.x, v.y);
    } else {
        int o = i - P5;                 /* mlp2 -> right half of fin rows */
        int n = o >> 8, kk = o & 255;
        float2 v = ((const float2*)s_mlp2)[o];
        ((half2*)g_w_fin)[n*512 + 256 + kk] = __floats2half2_rn(v.x, v.y);
    }
}

/* ---- fused bias: b_fuse[i] = dot(ref_w1[i,:], sa_out_b) + ref_b1[i] ----- */
__global__ void fuse_bias_kernel(const float* __restrict__ ref_w1,
                                 const float* __restrict__ sa_out_b,
                                 const float* __restrict__ ref_b1)
{
    int row = blockIdx.x;                /* 1024 */
    int t = threadIdx.x;                 /* 128 */
    const float* wr = ref_w1 + (size_t)row * 512;
    float s = 0.f;
#pragma unroll
    for (int q = 0; q < 4; q++) s += wr[t + q*128] * sa_out_b[t + q*128];
    __shared__ float red[128];
    red[t] = s;
    __syncthreads();
    for (int st = 64; st > 0; st >>= 1) {
        if (t < st) red[t] += red[t+st];
        __syncthreads();
    }
    if (t == 0) g_bfuse[row] = red[0] + ref_b1[row];
}

/* ---- fp16 tensor-core GEMM (cp.async + ldmatrix): C = A @ W^T + bias ---- */
/* 128 threads, 4 warps, warp tile 64x64 (2x2 warp grid over 128x128 tile).  */
/* EPI: 0=bias 1=gelu(bias) 2=C=aux+sigmoid(g)*(acc+bias)                    */
/* OUTH: store half.  STATS: atomicAdd column sums/sumsq (for BN).           */
template<int EPI, int OUTH, int STATS>
__global__ __launch_bounds__(128, 2)
void gemm_h16(const __half* __restrict__ A, int lda,
              const __half* __restrict__ W,
              const float* __restrict__ bias, void* __restrict__ Cout, int ldc,
              int M, int N, int K,
              const float* __restrict__ aux, const float* __restrict__ gptr)
{
    extern __shared__ __half smh[];
    const int tid  = threadIdx.x;
    const int wid  = tid >> 5;           /* 0..3 */
    const int lane = tid & 31;
    const int gid  = lane >> 2;
    const int tig  = lane & 3;
    const int wm   = (wid & 1) * 64;
    const int wn   = (wid >> 1) * 64;
    const int m0   = blockIdx.y * 128;
    const int n0   = blockIdx.x * 128;

    const uint32_t sbase = smem_u32(smh);

    uint32_t sto[4];
    const __half* srcA[4];
    const __half* srcB[4];
#pragma unroll
    for (int q = 0; q < 4; q++) {
        int id  = tid + q * 128;
        int row = id >> 2, cc = id & 3;
        sto[q]  = (uint32_t)(row * 64 + ((cc ^ (row & 3)) << 4));
        srcA[q] = A + (size_t)(m0 + row) * lda + cc * 8;
        srcB[q] = W + (size_t)(n0 + row) * K + cc * 8;
    }

    uint32_t aOff[4], bOff[4];
#pragma unroll
    for (int mt = 0; mt < 4; mt++) {
        int r  = wm + mt * 16 + (lane & 15);
        int ch = lane >> 4;
        aOff[mt] = (uint32_t)(r * 64 + ((ch ^ (r & 3)) << 4));
    }
#pragma unroll
    for (int njp = 0; njp < 4; njp++) {
        int r  = wn + njp * 16 + (lane & 7) + ((lane >> 4) << 3);
        int ch = (lane >> 3) & 1;
        bOff[njp] = (uint32_t)(8192 + r * 64 + ((ch ^ (r & 3)) << 4));
    }

    float acc[4][8][4];
#pragma unroll
    for (int i = 0; i < 4; i++)
#pragma unroll
        for (int j = 0; j < 8; j++)
#pragma unroll
            for (int c = 0; c < 4; c++) acc[i][j][c] = 0.f;

    const int nch = K >> 5;

    auto load_chunk = [&](int c) {
        uint32_t sb = sbase + (uint32_t)(c & 3) * 16384u;
        size_t ko = (size_t)c * 32;
#pragma unroll
        for (int q = 0; q < 4; q++) {
            CP_ASYNC16(sb + sto[q],        srcA[q] + ko);
            CP_ASYNC16(sb + 8192 + sto[q], srcB[q] + ko);
        }
    };

    load_chunk(0); CP_COMMIT();
    load_chunk(1); CP_COMMIT();
    load_chunk(2); CP_COMMIT();

    for (int c = 0; c < nch; c++) {
        CP_WAIT_2();
        __syncthreads();
        if (c + 3 < nch) load_chunk(c + 3);
        CP_COMMIT();

        uint32_t stb = sbase + (uint32_t)(c & 3) * 16384u;
#pragma unroll
        for (int ks = 0; ks < 2; ks++) {
            const uint32_t kx = (uint32_t)(ks << 5);
            uint32_t af[4][4], bf[4][4];
#pragma unroll
            for (int mt = 0; mt < 4; mt++)
                ldsm4(af[mt][0], af[mt][1], af[mt][2], af[mt][3],
                      stb + (aOff[mt] ^ kx));
#pragma unroll
            for (int njp = 0; njp < 4; njp++)
                ldsm4(bf[njp][0], bf[njp][1], bf[njp][2], bf[njp][3],
                      stb + (bOff[njp] ^ kx));
#pragma unroll
            for (int mt = 0; mt < 4; mt++)
#pragma unroll
                for (int nj = 0; nj < 8; nj++) {
                    const int njp = nj >> 1, pr = (nj & 1) << 1;
                    mma_h(acc[mt][nj][0], acc[mt][nj][1], acc[mt][nj][2], acc[mt][nj][3],
                          af[mt][0], af[mt][1], af[mt][2], af[mt][3],
                          bf[njp][pr], bf[njp][pr + 1]);
                }
        }
    }

    /* epilogue */
    float sg = 0.f;
    if (EPI == 2) sg = 1.0f / (1.0f + expf(-gptr[0]));
    float st1[16], st2[16];
    if (STATS) {
#pragma unroll
        for (int i = 0; i < 16; i++) { st1[i] = 0.f; st2[i] = 0.f; }
    }

#pragma unroll
    for (int mt = 0; mt < 4; mt++) {
#pragma unroll
        for (int nj = 0; nj < 8; nj++) {
            int r  = m0 + wm + mt * 16 + gid;
            int cc = n0 + wn + nj * 8 + 2 * tig;
            float b0v = bias[cc], b1v = bias[cc + 1];
            float v[4];
            v[0] = acc[mt][nj][0] + b0v;
            v[1] = acc[mt][nj][1] + b1v;
            v[2] = acc[mt][nj][2] + b0v;
            v[3] = acc[mt][nj][3] + b1v;
            if (EPI == 1) {
#pragma unroll
                for (int c = 0; c < 4; c++)
                    v[c] = 0.5f * v[c] * (1.0f + erff(v[c] * 0.70710678118654752f));
            }
            if (EPI == 2) {
                const float* x0 = aux + (size_t)r * N + cc;
                const float* x1 = aux + (size_t)(r + 8) * N + cc;
                v[0] = x0[0] + sg * v[0]; v[1] = x0[1] + sg * v[1];
                v[2] = x1[0] + sg * v[2]; v[3] = x1[1] + sg * v[3];
            }
            if (STATS) {
                st1[nj*2+0] += v[0] + v[2];
                st1[nj*2+1] += v[1] + v[3];
                st2[nj*2+0] += v[0]*v[0] + v[2]*v[2];
                st2[nj*2+1] += v[1]*v[1] + v[3]*v[3];
            }
            if (OUTH) {
                __half* Ch = (__half*)Cout;
                *(half2*)(Ch + (size_t)r * ldc + cc)       = __floats2half2_rn(v[0], v[1]);
                *(half2*)(Ch + (size_t)(r + 8) * ldc + cc) = __floats2half2_rn(v[2], v[3]);
            } else {
                float* Cf = (float*)Cout;
                *(float2*)(Cf + (size_t)r * ldc + cc)       = make_float2(v[0], v[1]);
                *(float2*)(Cf + (size_t)(r + 8) * ldc + cc) = make_float2(v[2], v[3]);
            }
        }
    }
    if (STATS) {
#pragma unroll
        for (int i = 0; i < 16; i++) {
            float a = st1[i], q = st2[i];
            a += __shfl_xor_sync(0xffffffffu, a, 4);
            a += __shfl_xor_sync(0xffffffffu, a, 8);
            a += __shfl_xor_sync(0xffffffffu, a, 16);
            q += __shfl_xor_sync(0xffffffffu, q, 4);
            q += __shfl_xor_sync(0xffffffffu, q, 8);
            q += __shfl_xor_sync(0xffffffffu, q, 16);
            if (gid == 0) {
                int col = n0 + wn + (i >> 1) * 8 + 2 * tig + (i & 1);
                atomicAdd(&g_s1[col], a);
                atomicAdd(&g_s2[col], q);
            }
        }
    }
}

/* ---------------- top-k selection (exact jax.lax.top_k order) ------------ */
__global__ void topk_kernel(const int* __restrict__ text,
                            const float* __restrict__ atten)
{
    int b = blockIdx.x;
    int t = threadIdx.x;            /* 512 threads */
    __shared__ float sval[NT];
    __shared__ int   sidx[NT];
    __shared__ int   red[NT];

    int tv = text[b*NT + t];

    red[t] = (tv << 10) | (NT - 1 - t);
    __syncthreads();
    for (int s = NT/2; s > 0; s >>= 1) {
        if (t < s) red[t] = max(red[t], red[t+s]);
        __syncthreads();
    }
    int eos = NT - 1 - (red[0] & 1023);
    __syncthreads();

    red[t] = (tv != 0) ? 1 : 0;
    __syncthreads();
    for (int s = NT/2; s > 0; s >>= 1) {
        if (t < s) red[t] += red[t+s];
        __syncthreads();
    }
    int nz = red[0];
    __syncthreads();

    float v;
    if (t == 0 || t == eos) v = -1.0f;
    else                    v = atten[((size_t)b*NT + eos)*NT + t];
    if (tv == 0) v = 0.0f;

    sval[t] = v; sidx[t] = t;
    __syncthreads();

    for (int ksz = 2; ksz <= NT; ksz <<= 1) {
        for (int j = ksz >> 1; j > 0; j >>= 1) {
            int ixj = t ^ j;
            if (ixj > t) {
                float va = sval[t], vb = sval[ixj];
                int   ia = sidx[t], ib = sidx[ixj];
                bool aBefore = (va > vb) || (va == vb && ia < ib);
                bool desc = ((t & ksz) == 0);
                if (desc ? !aBefore : aBefore) {
                    sval[t] = vb; sval[ixj] = va;
                    sidx[t] = ib; sidx[ixj] = ia;
                }
            }
            __syncthreads();
        }
    }
    if (t < KTOP) g_idx[b*KTOP + t] = sidx[t];
    if (t == 0) {
        int lnn = nz - 2;
        if (lnn > KTOP) lnn = KTOP;
        if (lnn < 1) lnn = 1;
        g_lens[b] = lnn;
    }
}

/* ---------- gather + L2 normalize + LayerNorm (fused, one pass) ---------- */
__global__ void gather_ln_kernel(const float* __restrict__ features,
                                 const float* __restrict__ lnw,
                                 const float* __restrict__ lnb)
{
    int token = blockIdx.x;
    int b = token / KTOP;
    int src = g_idx[token];
    int tid = threadIdx.x;                /* 128 threads */
    const float* f = features + ((size_t)b*NT + src)*DIM;

    float v[4];
    float s1 = 0.f, s2 = 0.f;
#pragma unroll
    for (int i = 0; i < 4; i++) {
        v[i] = f[tid + i*128];
        s1 += v[i];
        s2 += v[i]*v[i];
    }
    __shared__ float r1[128], r2[128];
    r1[tid] = s1; r2[tid] = s2;
    __syncthreads();
    for (int s = 64; s > 0; s >>= 1) {
        if (tid < s) { r1[tid] += r1[tid+s]; r2[tid] += r2[tid+s]; }
        __syncthreads();
    }
    float sumf = r1[0], ss = r2[0];
    float inv  = 1.0f / (sqrtf(ss) + 1e-6f);
    float mean = sumf * inv * (1.0f/DIM);
    float et2  = ss * inv * inv * (1.0f/DIM);
    float var  = et2 - mean*mean;
    float rstd = rsqrtf(var + 1e-5f);

    float*  tokp = g_tok + (size_t)token*DIM;
    __half* qp   = g_qh  + (size_t)token*DIM;
#pragma unroll
    for (int i = 0; i < 4; i++) {
        int c = tid + i*128;
        float tvv = v[i] * inv;
        tokp[c] = tvv;
        qp[c]   = __float2half_rn((tvv - mean) * rstd * lnw[c] + lnb[c]);
    }
}

/* ------------- tensor-core flash attention: one block per (b,h) ---------- */
__global__ __launch_bounds__(ATT_THREADS)
void attn_tc()
{
    const int h = blockIdx.x, b = blockIdx.y;
    extern __shared__ __half ash[];
    __half* sQ = ash;
    __half* sK = ash + ATT_ROWS*64;
    __half* sV = ash + 2*ATT_ROWS*64;
    const int tid = threadIdx.x;
    const int wid = tid >> 5, lane = tid & 31;
    const int gid = lane >> 2, tig = lane & 3;
    const size_t tokbase = (size_t)b * KTOP;
    const __half* qkv = g_qkvh;

    for (int i = tid; i < ATT_ROWS*8; i += ATT_THREADS) {
        int r = i >> 3, c = i & 7;
        uint4 zq = make_uint4(0,0,0,0), zk = zq, zv = zq;
        if (r < KTOP) {
            const __half* base = qkv + (tokbase + r)*1536 + h*64 + c*8;
            zq = *(const uint4*)(base);
            zk = *(const uint4*)(base + 512);
            zv = *(const uint4*)(base + 1024);
        }
        int off = r*64 + ((c ^ (r & 7)) << 3);
        *(uint4*)(sQ + off) = zq;
        *(uint4*)(sK + off) = zk;
        *(uint4*)(sV + off) = zv;
    }
    __syncthreads();

    const uint32_t uQ = smem_u32(sQ), uK = smem_u32(sK), uV = smem_u32(sV);
    const int wm = wid * 16;
    const int mrow = lane & 7, msel = lane >> 3;

    uint32_t aq[4][4];
    {
        int row = wm + mrow + ((msel & 1) << 3);
        int chalf = msel >> 1;
#pragma unroll
        for (int ks = 0; ks < 4; ks++) {
            int ch = 2*ks + chalf;
            ldsm4(aq[ks][0], aq[ks][1], aq[ks][2], aq[ks][3],
                  uQ + (uint32_t)(row*128 + ((ch ^ (row & 7)) << 4)));
        }
    }

    float mr0 = -1e30f, mr1 = -1e30f, l0 = 0.f, l1 = 0.f;
    float o[8][4];
#pragma unroll
    for (int i = 0; i < 8; i++)
#pragma unroll
        for (int c = 0; c < 4; c++) o[i][c] = 0.f;

#pragma unroll 1
    for (int kc = 0; kc < 3; kc++) {
        float sS[8][4];
#pragma unroll
        for (int i = 0; i < 8; i++)
#pragma unroll
            for (int c = 0; c < 4; c++) sS[i][c] = 0.f;

#pragma unroll
        for (int ks = 0; ks < 4; ks++) {
            int chalf = msel >> 1;
            int ch = 2*ks + chalf;
            int nro = mrow + ((msel & 1) << 3);
#pragma unroll
            for (int p = 0; p < 4; p++) {
                int nr = kc*64 + p*16 + nro;
                uint32_t r0, r1, r2, r3;
                ldsm4(r0, r1, r2, r3,
                      uK + (uint32_t)(nr*128 + ((ch ^ (nr & 7)) << 4)));
                mma_h(sS[2*p][0], sS[2*p][1], sS[2*p][2], sS[2*p][3],
                      aq[ks][0], aq[ks][1], aq[ks][2], aq[ks][3], r0, r2);
                mma_h(sS[2*p+1][0], sS[2*p+1][1], sS[2*p+1][2], sS[2*p+1][3],
                      aq[ks][0], aq[ks][1], aq[ks][2], aq[ks][3], r1, r3);
            }
        }

#pragma unroll
        for (int nf = 0; nf < 8; nf++)
#pragma unroll
            for (int c = 0; c < 4; c++) sS[nf][c] *= 0.125f;
        if (kc == 2) {
#pragma unroll
            for (int nf = 0; nf < 8; nf++) {
                int col = 128 + nf*8 + 2*tig;
                if (col     >= KTOP) { sS[nf][0] = -1e30f; sS[nf][2] = -1e30f; }
                if (col + 1 >= KTOP) { sS[nf][1] = -1e30f; sS[nf][3] = -1e30f; }
            }
        }

        float cm0 = -1e30f, cm1 = -1e30f;
#pragma unroll
        for (int nf = 0; nf < 8; nf++) {
            cm0 = fmaxf(cm0, fmaxf(sS[nf][0], sS[nf][1]));
            cm1 = fmaxf(cm1, fmaxf(sS[nf][2], sS[nf][3]));
        }
        cm0 = fmaxf(cm0, __shfl_xor_sync(0xffffffffu, cm0, 1));
        cm0 = fmaxf(cm0, __shfl_xor_sync(0xffffffffu, cm0, 2));
        cm1 = fmaxf(cm1, __shfl_xor_sync(0xffffffffu, cm1, 1));
        cm1 = fmaxf(cm1, __shfl_xor_sync(0xffffffffu, cm1, 2));
        float nm0 = fmaxf(mr0, cm0), nm1 = fmaxf(mr1, cm1);
        float f0 = __expf(mr0 - nm0), f1 = __expf(mr1 - nm1);
        mr0 = nm0; mr1 = nm1;

        float ls0 = 0.f, ls1 = 0.f;
#pragma unroll
        for (int nf = 0; nf < 8; nf++) {
            sS[nf][0] = __expf(sS[nf][0] - nm0);
            sS[nf][1] = __expf(sS[nf][1] - nm0);
            sS[nf][2] = __expf(sS[nf][2] - nm1);
            sS[nf][3] = __expf(sS[nf][3] - nm1);
            ls0 += sS[nf][0] + sS[nf][1];
            ls1 += sS[nf][2] + sS[nf][3];
        }
        ls0 += __shfl_xor_sync(0xffffffffu, ls0, 1);
        ls0 += __shfl_xor_sync(0xffffffffu, ls0, 2);
        ls1 += __shfl_xor_sync(0xffffffffu, ls1, 1);
        ls1 += __shfl_xor_sync(0xffffffffu, ls1, 2);
        l0 = l0*f0 + ls0;
        l1 = l1*f1 + ls1;
#pragma unroll
        for (int df = 0; df < 8; df++) {
            o[df][0] *= f0; o[df][1] *= f0;
            o[df][2] *= f1; o[df][3] *= f1;
        }

        uint32_t ap[4][4];
#pragma unroll
        for (int j = 0; j < 4; j++) {
            ap[j][0] = pack_h2(sS[2*j][0],   sS[2*j][1]);
            ap[j][1] = pack_h2(sS[2*j][2],   sS[2*j][3]);
            ap[j][2] = pack_h2(sS[2*j+1][0], sS[2*j+1][1]);
            ap[j][3] = pack_h2(sS[2*j+1][2], sS[2*j+1][3]);
        }

#pragma unroll
        for (int j = 0; j < 4; j++) {
            int kr = kc*64 + j*16 + mrow + ((msel & 1) << 3);
            int chalf = msel >> 1;
#pragma unroll
            for (int p = 0; p < 4; p++) {
                int ch = 2*p + chalf;
                uint32_t r0, r1, r2, r3;
                ldsm4t(r0, r1, r2, r3,
                       uV + (uint32_t)(kr*128 + ((ch ^ (kr & 7)) << 4)));
                mma_h(o[2*p][0], o[2*p][1], o[2*p][2], o[2*p][3],
                      ap[j][0], ap[j][1], ap[j][2], ap[j][3], r0, r1);
                mma_h(o[2*p+1][0], o[2*p+1][1], o[2*p+1][2], o[2*p+1][3],
                      ap[j][0], ap[j][1], ap[j][2], ap[j][3], r2, r3);
            }
        }
    }

    float inv0 = 1.0f / l0, inv1 = 1.0f / l1;
    int r0g = wm + gid, r1g = wm + gid + 8;
#pragma unroll
    for (int df = 0; df < 8; df++) {
        int d = df*8 + 2*tig;
        if (r0g < KTOP)
            *(half2*)(g_sa + (tokbase + r0g)*512 + h*64 + d) =
                __floats2half2_rn(o[df][0]*inv0, o[df][1]*inv0);
        if (r1g < KTOP)
            *(half2*)(g_sa + (tokbase + r1g)*512 + h*64 + d) =
                __floats2half2_rn(o[df][2]*inv1, o[df][3]*inv1);
    }
}

/* --------------------------- BatchNorm (train) --------------------------- */
__global__ void bn_final()
{
    int c = threadIdx.x;                   /* 512 */
    float mean = g_s1[c] / (float)BKTOK;
    float var  = g_s2[c] / (float)BKTOK - mean*mean;
    g_mu[c]   = mean;
    g_rstd[c] = rsqrtf(var + 1e-5f);
}

__global__ void bn_apply(const float* __restrict__ bnw, const float* __restrict__ bnb)
{
    size_t i = (size_t)blockIdx.x*blockDim.x + threadIdx.x;
    if (i < (size_t)BKTOK*512) {
        int c = (int)(i & 511);
        size_t row = i >> 9;
        float x = __half2float(g_hh[i]);
        x = (x - g_mu[c]) * g_rstd[c] * bnw[c] + bnb[c];
        g_comb[row*1024 + 512 + c] = __float2half_rn(fmaxf(x, 0.f));
    }
}

/* ------------------------ variable-length max pool ----------------------- */
__global__ void pool_kernel(float* __restrict__ out)
{
    int b = blockIdx.x;
    int col = blockIdx.y * 256 + threadIdx.x;
    int L = g_lens[b];
    const float* fp = g_feat + (size_t)b*KTOP*EDIM + col;
    float mx = -1e30f;
    int t = 0;
    for (; t + 1 < L; t += 2)
        mx = fmaxf(mx, fmaxf(fp[(size_t)t*EDIM], fp[(size_t)(t+1)*EDIM]));
    if (t < L) mx = fmaxf(mx, fp[(size_t)t*EDIM]);
    out[(size_t)b*EDIM + col] = mx;
}

/* ------------------------------- launcher -------------------------------- */
extern "C" void kernel_launch(void* const* d_in, const int* in_sizes, int n_in,
                              void* d_out, int out_size)
{
    const float* features = (const float*)d_in[0];
    const int*   text     = (const int*)  d_in[1];
    const float* atten    = (const float*)d_in[2];
    const float* ln_q_w   = (const float*)d_in[3];
    const float* ln_q_b   = (const float*)d_in[4];
    const float* sa_in_w  = (const float*)d_in[5];
    const float* sa_in_b  = (const float*)d_in[6];
    const float* sa_out_w = (const float*)d_in[7];
    const float* sa_out_b = (const float*)d_in[8];
    const float* ref_w1   = (const float*)d_in[9];
    const float* ref_b1   = (const float*)d_in[10];
    const float* ref_w2   = (const float*)d_in[11];
    const float* ref_b2   = (const float*)d_in[12];
    const float* gscal    = (const float*)d_in[13];
    const float* lin_w    = (const float*)d_in[14];
    const float* lin_b    = (const float*)d_in[15];
    const float* mlp_w1   = (const float*)d_in[16];
    const float* mlp_b1   = (const float*)d_in[17];
    const float* bn_w     = (const float*)d_in[18];
    const float* bn_b     = (const float*)d_in[19];
    const float* mlp_w2   = (const float*)d_in[20];
    const float* mlp_b2   = (const float*)d_in[21];
    float* out = (float*)d_out;

    float *p_tok, *p_feat, *p_bfin, *p_bfuse, *p_zero;
    __half *p_qh, *p_qkvh, *p_sa, *p_y1h, *p_comb, *p_hh;
    __half *w_sain, *w_soT, *w_ref1, *w_ref2, *w_mlp1, *w_fin, *w_fuse;
    cudaGetSymbolAddress((void**)&p_tok,  g_tok);
    cudaGetSymbolAddress((void**)&p_qh,   g_qh);
    cudaGetSymbolAddress((void**)&p_qkvh, g_qkvh);
    cudaGetSymbolAddress((void**)&p_sa,   g_sa);
    cudaGetSymbolAddress((void**)&p_y1h,  g_y1h);
    cudaGetSymbolAddress((void**)&p_comb, g_comb);
    cudaGetSymbolAddress((void**)&p_hh,   g_hh);
    cudaGetSymbolAddress((void**)&p_feat, g_feat);
    cudaGetSymbolAddress((void**)&p_bfin, g_bias_fin);
    cudaGetSymbolAddress((void**)&p_bfuse, g_bfuse);
    cudaGetSymbolAddress((void**)&p_zero, g_zero512);
    cudaGetSymbolAddress((void**)&w_sain,  g_w_sain);
    cudaGetSymbolAddress((void**)&w_soT,   g_w_soT);
    cudaGetSymbolAddress((void**)&w_ref1,  g_w_ref1);
    cudaGetSymbolAddress((void**)&w_ref2,  g_w_ref2);
    cudaGetSymbolAddress((void**)&w_mlp1,  g_w_mlp1);
    cudaGetSymbolAddress((void**)&w_fin,   g_w_fin);
    cudaGetSymbolAddress((void**)&w_fuse,  g_w_fuse);

    cudaFuncSetAttribute(gemm_h16<0,0,0>, cudaFuncAttributeMaxDynamicSharedMemorySize, GEMM_SMEM);
    cudaFuncSetAttribute(gemm_h16<0,1,0>, cudaFuncAttributeMaxDynamicSharedMemorySize, GEMM_SMEM);
    cudaFuncSetAttribute(gemm_h16<0,1,1>, cudaFuncAttributeMaxDynamicSharedMemorySize, GEMM_SMEM);
    cudaFuncSetAttribute(gemm_h16<1,1,0>, cudaFuncAttributeMaxDynamicSharedMemorySize, GEMM_SMEM);
    cudaFuncSetAttribute(gemm_h16<2,1,0>, cudaFuncAttributeMaxDynamicSharedMemorySize, GEMM_SMEM);
    cudaFuncSetAttribute(attn_tc, cudaFuncAttributeMaxDynamicSharedMemorySize, ATT_SMEM);

    const int MROWS = BKTOK;             /* 39168 = 306*128 */

    cvt_all_kernel<<<(P6+255)/256, 256>>>(sa_in_w, sa_out_w, ref_w1, ref_w2,
                                          lin_w, mlp_w1, mlp_w2, lin_b, mlp_b2);
    /* W_fuse = W_r1 @ W_so   (C[m,n] = sum_k ref1h[m,k] * soT[n,k]) */
    gemm_h16<0,1,0><<<dim3(512/128, 1024/128), 128, GEMM_SMEM>>>(
        w_ref1, 512, w_soT, p_zero, w_fuse, 512, 1024, 512, 512, nullptr, nullptr);
    fuse_bias_kernel<<<1024, 128>>>(ref_w1, sa_out_b, ref_b1);

    topk_kernel<<<BATCH, NT>>>(text, atten);
    gather_ln_kernel<<<BKTOK, 128>>>(features, ln_q_w, ln_q_b);

    /* qkv = LN(tok) @ sa_in_w^T + b  (half out) */
    gemm_h16<0,1,0><<<dim3(1536/128, MROWS/128), 128, GEMM_SMEM>>>(
        p_qh, 512, w_sain, sa_in_b, p_qkvh, 1536, MROWS, 1536, 512, nullptr, nullptr);
    attn_tc<<<dim3(NHEADS, BATCH), ATT_THREADS, ATT_SMEM>>>();

    /* y1 = gelu(sa @ W_fuse^T + b_fuse)  (half out) — sa_out GEMM fused away */
    gemm_h16<1,1,0><<<dim3(1024/128, MROWS/128), 128, GEMM_SMEM>>>(
        p_sa, 512, w_fuse, p_bfuse, p_y1h, 1024, MROWS, 1024, 512, nullptr, nullptr);
    /* comb[:,0:512] = tok + sigmoid(g)*(y1 @ ref_w2^T + b)  (half out, ldc=1024) */
    gemm_h16<2,1,0><<<dim3(512/128, MROWS/128), 128, GEMM_SMEM>>>(
        p_y1h, 1024, w_ref2, ref_b2, p_comb, 1024, MROWS, 512, 1024, p_tok, gscal);
    /* h = tok_h @ mlp_w1^T + b  (half out + fused BN stats from fp32 acc) */
    gemm_h16<0,1,1><<<dim3(512/128, MROWS/128), 128, GEMM_SMEM>>>(
        p_comb, 1024, w_mlp1, mlp_b1, p_hh, 512, MROWS, 512, 512, nullptr, nullptr);
    bn_final<<<1, 512>>>();
    bn_apply<<<(int)(((size_t)BKTOK*512 + 255)/256), 256>>>(bn_w, bn_b);

    /* feat = [tok_h | relu_bn_h] @ [lin_w | mlp_w2]^T + (lin_b + mlp_b2) */
    gemm_h16<0,0,0><<<dim3(1024/128, MROWS/128), 128, GEMM_SMEM>>>(
        p_comb, 1024, w_fin, p_bfin, p_feat, 1024, MROWS, 1024, 1024, nullptr, nullptr);
    pool_kernel<<<dim3(BATCH, 4), 256>>>(out);
}

// round 13
// speedup vs baseline: 7.6495x; 1.0671x over previous
#include <cuda_runtime.h>
#include <cuda_fp16.h>
#include <math.h>
#include <stdint.h>

#define BATCH 256
#define NT 512
#define DIM 512
#define KTOP 153
#define BKTOK (BATCH*KTOP)      /* 39168 = 306*128 */
#define EDIM 1024
#define NHEADS 8

#define GEMM_SMEM (4*16384)     /* 4 stages x (A 8KB + B 8KB) */
#define ATT_THREADS 320
#define ATT_ROWS 192            /* padded tile rows (3 chunks of 64) */
#define ATT_SMEM (3*ATT_ROWS*64*2)   /* Q,K,V half tiles: 73728 B */

/* ---------------- scratch (device globals; no allocation) ---------------- */
__device__ int    g_idx[BKTOK];
__device__ int    g_lens[BATCH];
__device__ float  g_tok[(size_t)BKTOK*DIM];        /* fp32 residual source */
__device__ __half g_qh[(size_t)BKTOK*DIM];         /* LN out (GEMM A) */
__device__ __half g_qkvh[(size_t)BKTOK*3*DIM];     /* half qkv */
__device__ __half g_sa[(size_t)BKTOK*DIM];
__device__ __half g_y1h[(size_t)BKTOK*2*DIM];
__device__ __half g_comb[(size_t)BKTOK*1024];      /* [tok_h | relu_bn_h] */
__device__ __half g_hh[(size_t)BKTOK*DIM];         /* pre-BN h (half) */
__device__ float  g_s1[512];
__device__ float  g_s2[512];
__device__ float  g_mu[512];
__device__ float  g_rstd[512];
/* half-converted weights */
__device__ __half g_w_sain[1536*512];
__device__ __half g_w_soT[512*512];                /* sa_out_w transposed */
__device__ __half g_w_ref1[1024*512];
__device__ __half g_w_ref2[512*1024];
__device__ __half g_w_mlp1[512*512];
__device__ __half g_w_fin[1024*1024];              /* [lin_w | mlp_w2] */
__device__ __half g_w_fuse[1024*512];              /* W_r1 @ W_so */
__device__ float  g_bias_fin[1024];                /* lin_b + mlp_b2 */
__device__ float  g_bfuse[1024];                   /* W_r1 @ b_so + b_r1 */
__device__ float  g_zero512[512];

/* ------------------------------ helpers ---------------------------------- */
__device__ __forceinline__ uint32_t smem_u32(const void* p) {
    uint32_t a;
    asm("{ .reg .u64 t; cvta.to.shared.u64 t, %1; cvt.u32.u64 %0, t; }"
        : "=r"(a) : "l"(p));
    return a;
}
#define CP_ASYNC16(dst, src) \
    asm volatile("cp.async.cg.shared.global [%0], [%1], 16;" :: "r"(dst), "l"(src))
#define CP_COMMIT()  asm volatile("cp.async.commit_group;" ::: "memory")
#define CP_WAIT_2()  asm volatile("cp.async.wait_group 2;" ::: "memory")

__device__ __forceinline__ void ldsm4(uint32_t& r0, uint32_t& r1,
                                      uint32_t& r2, uint32_t& r3, uint32_t addr) {
    asm volatile("ldmatrix.sync.aligned.m8n8.x4.shared.b16 {%0,%1,%2,%3}, [%4];"
                 : "=r"(r0), "=r"(r1), "=r"(r2), "=r"(r3) : "r"(addr));
}
__device__ __forceinline__ void ldsm4t(uint32_t& r0, uint32_t& r1,
                                       uint32_t& r2, uint32_t& r3, uint32_t addr) {
    asm volatile("ldmatrix.sync.aligned.m8n8.x4.trans.shared.b16 {%0,%1,%2,%3}, [%4];"
                 : "=r"(r0), "=r"(r1), "=r"(r2), "=r"(r3) : "r"(addr));
}
__device__ __forceinline__ void mma_h(float& d0, float& d1, float& d2, float& d3,
                                      uint32_t a0, uint32_t a1, uint32_t a2, uint32_t a3,
                                      uint32_t b0, uint32_t b1)
{
    asm volatile(
        "mma.sync.aligned.m16n8k16.row.col.f32.f16.f16.f32 "
        "{%0,%1,%2,%3}, {%4,%5,%6,%7}, {%8,%9}, {%0,%1,%2,%3};"
        : "+f"(d0), "+f"(d1), "+f"(d2), "+f"(d3)
        : "r"(a0), "r"(a1), "r"(a2), "r"(a3), "r"(b0), "r"(b1));
}
__device__ __forceinline__ uint32_t pack_h2(float a, float b) {
    half2 h = __floats2half2_rn(a, b);
    return *(uint32_t*)&h;
}
/* exact order-independent float atomic max (sign-split trick) */
__device__ __forceinline__ void atomicMaxF(float* a, float v) {
    if (v >= 0.f) atomicMax((int*)a, __float_as_int(v));
    else          atomicMin((unsigned int*)a, __float_as_uint(v));
}

/* -------- weight conversion fp32 -> fp16 + stats zero + bias sum --------- */
/* counts in half2 units */
#define P0 393216                 /* sain  1536x512 */
#define P1 (P0+131072)            /* saout  512x512 -> TRANSPOSED g_w_soT */
#define P2 (P1+262144)            /* ref1  1024x512 */
#define P3 (P2+262144)            /* ref2   512x1024 */
#define P4 (P3+262144)            /* lin   1024x512 -> fin cols 0..511 */
#define P5 (P4+131072)            /* mlp1   512x512 */
#define P6 (P5+262144)            /* mlp2  1024x512 -> fin cols 512..1023 */
__global__ void cvt_all_kernel(const float* s_sain, const float* s_saout,
                               const float* s_ref1, const float* s_ref2,
                               const float* s_lin,  const float* s_mlp1,
                               const float* s_mlp2,
                               const float* lin_b,  const float* mlp_b2)
{
    int t = threadIdx.x;
    if (blockIdx.x == 0) {
        g_s1[t] = 0.f; g_s1[t+256] = 0.f;
        g_s2[t] = 0.f; g_s2[t+256] = 0.f;
        g_zero512[t] = 0.f; g_zero512[t+256] = 0.f;
    }
    if (blockIdx.x == 1) {
#pragma unroll
        for (int q = 0; q < 4; q++)
            g_bias_fin[t + q*256] = lin_b[t + q*256] + mlp_b2[t + q*256];
    }
    int i = blockIdx.x * 256 + t;
    if (i >= P6) return;
    if (i < P0) {
        float2 v = ((const float2*)s_sain)[i];
        ((half2*)g_w_sain)[i] = __floats2half2_rn(v.x, v.y);
    } else if (i < P1) {
        int o = i - P0;
        int k = o >> 8, c2 = o & 255;
        float2 v = ((const float2*)s_saout)[o];
        g_w_soT[(2*c2  )*512 + k] = __float2half_rn(v.x);
        g_w_soT[(2*c2+1)*512 + k] = __float2half_rn(v.y);
    } else if (i < P2) {
        int o = i - P1;
        float2 v = ((const float2*)s_ref1)[o];
        ((half2*)g_w_ref1)[o] = __floats2half2_rn(v.x, v.y);
    } else if (i < P3) {
        int o = i - P2;
        float2 v = ((const float2*)s_ref2)[o];
        ((half2*)g_w_ref2)[o] = __floats2half2_rn(v.x, v.y);
    } else if (i < P4) {
        int o = i - P3;
        int n = o >> 8, kk = o & 255;
        float2 v = ((const float2*)s_lin)[o];
        ((half2*)g_w_fin)[n*512 + kk] = __floats2half2_rn(v.x, v.y);
    } else if (i < P5) {
        int o = i - P4;
        float2 v = ((const float2*)s_mlp1)[o];
        ((half2*)g_w_mlp1)[o] = __floats2half2_rn(v.x, v.y);
    } else {
        int o = i - P5;
        int n = o >> 8, kk = o & 255;
        float2 v = ((const float2*)s_mlp2)[o];
        ((half2*)g_w_fin)[n*512 + 256 + kk] = __floats2half2_rn(v.x, v.y);
    }
}

/* ---- fused bias: b_fuse[i] = dot(ref_w1[i,:], sa_out_b) + ref_b1[i] ----- */
__global__ void fuse_bias_kernel(const float* __restrict__ ref_w1,
                                 const float* __restrict__ sa_out_b,
                                 const float* __restrict__ ref_b1)
{
    int row = blockIdx.x;                /* 1024 */
    int t = threadIdx.x;                 /* 128 */
    const float* wr = ref_w1 + (size_t)row * 512;
    float s = 0.f;
#pragma unroll
    for (int q = 0; q < 4; q++) s += wr[t + q*128] * sa_out_b[t + q*128];
    __shared__ float red[128];
    red[t] = s;
    __syncthreads();
    for (int st = 64; st > 0; st >>= 1) {
        if (t < st) red[t] += red[t+st];
        __syncthreads();
    }
    if (t == 0) g_bfuse[row] = red[0] + ref_b1[row];
}

/* ---------------- output init to -inf (for fused max-pool) --------------- */
__global__ void out_init_kernel(float* __restrict__ out)
{
    out[blockIdx.x * 256 + threadIdx.x] = __int_as_float(0xff800000);
}

/* ---- fp16 tensor-core GEMM (cp.async + ldmatrix): C = A @ W^T + bias ---- */
/* 128 threads, 4 warps, warp tile 64x64 (2x2 warp grid over 128x128 tile).  */
/* EPI: 0=bias 1=gelu(bias) 2=C=aux+sigmoid(g)*(acc+bias)                    */
/* OUTH: store half.  STATS: BN column sums.  POOL: fused masked max-pool.   */
template<int EPI, int OUTH, int STATS, int POOL>
__global__ __launch_bounds__(128, 2)
void gemm_h16(const __half* __restrict__ A, int lda,
              const __half* __restrict__ W,
              const float* __restrict__ bias, void* __restrict__ Cout, int ldc,
              int M, int N, int K,
              const float* __restrict__ aux, const float* __restrict__ gptr)
{
    extern __shared__ __half smh[];
    const int tid  = threadIdx.x;
    const int wid  = tid >> 5;           /* 0..3 */
    const int lane = tid & 31;
    const int gid  = lane >> 2;
    const int tig  = lane & 3;
    const int wm   = (wid & 1) * 64;
    const int wn   = (wid >> 1) * 64;
    const int m0   = blockIdx.y * 128;
    const int n0   = blockIdx.x * 128;

    const uint32_t sbase = smem_u32(smh);

    uint32_t sto[4];
    const __half* srcA[4];
    const __half* srcB[4];
#pragma unroll
    for (int q = 0; q < 4; q++) {
        int id  = tid + q * 128;
        int row = id >> 2, cc = id & 3;
        sto[q]  = (uint32_t)(row * 64 + ((cc ^ (row & 3)) << 4));
        srcA[q] = A + (size_t)(m0 + row) * lda + cc * 8;
        srcB[q] = W + (size_t)(n0 + row) * K + cc * 8;
    }

    uint32_t aOff[4], bOff[4];
#pragma unroll
    for (int mt = 0; mt < 4; mt++) {
        int r  = wm + mt * 16 + (lane & 15);
        int ch = lane >> 4;
        aOff[mt] = (uint32_t)(r * 64 + ((ch ^ (r & 3)) << 4));
    }
#pragma unroll
    for (int njp = 0; njp < 4; njp++) {
        int r  = wn + njp * 16 + (lane & 7) + ((lane >> 4) << 3);
        int ch = (lane >> 3) & 1;
        bOff[njp] = (uint32_t)(8192 + r * 64 + ((ch ^ (r & 3)) << 4));
    }

    float acc[4][8][4];
#pragma unroll
    for (int i = 0; i < 4; i++)
#pragma unroll
        for (int j = 0; j < 8; j++)
#pragma unroll
            for (int c = 0; c < 4; c++) acc[i][j][c] = 0.f;

    const int nch = K >> 5;

    auto load_chunk = [&](int c) {
        uint32_t sb = sbase + (uint32_t)(c & 3) * 16384u;
        size_t ko = (size_t)c * 32;
#pragma unroll
        for (int q = 0; q < 4; q++) {
            CP_ASYNC16(sb + sto[q],        srcA[q] + ko);
            CP_ASYNC16(sb + 8192 + sto[q], srcB[q] + ko);
        }
    };

    load_chunk(0); CP_COMMIT();
    load_chunk(1); CP_COMMIT();
    load_chunk(2); CP_COMMIT();

    for (int c = 0; c < nch; c++) {
        CP_WAIT_2();
        __syncthreads();
        if (c + 3 < nch) load_chunk(c + 3);
        CP_COMMIT();

        uint32_t stb = sbase + (uint32_t)(c & 3) * 16384u;
#pragma unroll
        for (int ks = 0; ks < 2; ks++) {
            const uint32_t kx = (uint32_t)(ks << 5);
            uint32_t af[4][4], bf[4][4];
#pragma unroll
            for (int mt = 0; mt < 4; mt++)
                ldsm4(af[mt][0], af[mt][1], af[mt][2], af[mt][3],
                      stb + (aOff[mt] ^ kx));
#pragma unroll
            for (int njp = 0; njp < 4; njp++)
                ldsm4(bf[njp][0], bf[njp][1], bf[njp][2], bf[njp][3],
                      stb + (bOff[njp] ^ kx));
#pragma unroll
            for (int mt = 0; mt < 4; mt++)
#pragma unroll
                for (int nj = 0; nj < 8; nj++) {
                    const int njp = nj >> 1, pr = (nj & 1) << 1;
                    mma_h(acc[mt][nj][0], acc[mt][nj][1], acc[mt][nj][2], acc[mt][nj][3],
                          af[mt][0], af[mt][1], af[mt][2], af[mt][3],
                          bf[njp][pr], bf[njp][pr + 1]);
                }
        }
    }

    /* -------------------- fused masked max-pool epilogue ----------------- */
    if (POOL) {
        const int base = m0 + wm + gid;
        int bj[8]; bool vj[8];
#pragma unroll
        for (int j = 0; j < 8; j++) {
            int R = base + 8*j;
            int bb = R / KTOP;
            bj[j] = bb;
            vj[j] = (R - bb*KTOP) < g_lens[bb];
        }
        float* outp = (float*)Cout;
        const int bF = bj[0], bL = bj[7];
#pragma unroll
        for (int nj = 0; nj < 8; nj++) {
            int cc = n0 + wn + nj*8 + 2*tig;
            float b0f = bias[cc], b1f = bias[cc + 1];
            float mA0 = -3e38f, mA1 = -3e38f, mB0 = -3e38f, mB1 = -3e38f;
#pragma unroll
            for (int j = 0; j < 8; j++) {
                int mt = j >> 1, rh = (j & 1) << 1;
                float x0 = acc[mt][nj][rh]     + b0f;
                float x1 = acc[mt][nj][rh + 1] + b1f;
                bool sameb = (bj[j] == bF);
                if (vj[j] && sameb)  { mA0 = fmaxf(mA0, x0); mA1 = fmaxf(mA1, x1); }
                if (vj[j] && !sameb) { mB0 = fmaxf(mB0, x0); mB1 = fmaxf(mB1, x1); }
            }
            if (mA0 > -3e38f) atomicMaxF(outp + (size_t)bF*EDIM + cc,     mA0);
            if (mA1 > -3e38f) atomicMaxF(outp + (size_t)bF*EDIM + cc + 1, mA1);
            if (bL != bF) {
                if (mB0 > -3e38f) atomicMaxF(outp + (size_t)bL*EDIM + cc,     mB0);
                if (mB1 > -3e38f) atomicMaxF(outp + (size_t)bL*EDIM + cc + 1, mB1);
            }
        }
        return;
    }

    /* ----------------------------- epilogue ------------------------------ */
    float sg = 0.f;
    if (EPI == 2) sg = 1.0f / (1.0f + expf(-gptr[0]));
    float st1[16], st2[16];
    if (STATS) {
#pragma unroll
        for (int i = 0; i < 16; i++) { st1[i] = 0.f; st2[i] = 0.f; }
    }

#pragma unroll
    for (int mt = 0; mt < 4; mt++) {
#pragma unroll
        for (int nj = 0; nj < 8; nj++) {
            int r  = m0 + wm + mt * 16 + gid;
            int cc = n0 + wn + nj * 8 + 2 * tig;
            float b0v = bias[cc], b1v = bias[cc + 1];
            float v[4];
            v[0] = acc[mt][nj][0] + b0v;
            v[1] = acc[mt][nj][1] + b1v;
            v[2] = acc[mt][nj][2] + b0v;
            v[3] = acc[mt][nj][3] + b1v;
            if (EPI == 1) {
#pragma unroll
                for (int c = 0; c < 4; c++)
                    v[c] = 0.5f * v[c] * (1.0f + erff(v[c] * 0.70710678118654752f));
            }
            if (EPI == 2) {
                const float* x0 = aux + (size_t)r * N + cc;
                const float* x1 = aux + (size_t)(r + 8) * N + cc;
                v[0] = x0[0] + sg * v[0]; v[1] = x0[1] + sg * v[1];
                v[2] = x1[0] + sg * v[2]; v[3] = x1[1] + sg * v[3];
            }
            if (STATS) {
                st1[nj*2+0] += v[0] + v[2];
                st1[nj*2+1] += v[1] + v[3];
                st2[nj*2+0] += v[0]*v[0] + v[2]*v[2];
                st2[nj*2+1] += v[1]*v[1] + v[3]*v[3];
            }
            if (OUTH) {
                __half* Ch = (__half*)Cout;
                *(half2*)(Ch + (size_t)r * ldc + cc)       = __floats2half2_rn(v[0], v[1]);
                *(half2*)(Ch + (size_t)(r + 8) * ldc + cc) = __floats2half2_rn(v[2], v[3]);
            } else {
                float* Cf = (float*)Cout;
                *(float2*)(Cf + (size_t)r * ldc + cc)       = make_float2(v[0], v[1]);
                *(float2*)(Cf + (size_t)(r + 8) * ldc + cc) = make_float2(v[2], v[3]);
            }
        }
    }
    if (STATS) {
#pragma unroll
        for (int i = 0; i < 16; i++) {
            float a = st1[i], q = st2[i];
            a += __shfl_xor_sync(0xffffffffu, a, 4);
            a += __shfl_xor_sync(0xffffffffu, a, 8);
            a += __shfl_xor_sync(0xffffffffu, a, 16);
            q += __shfl_xor_sync(0xffffffffu, q, 4);
            q += __shfl_xor_sync(0xffffffffu, q, 8);
            q += __shfl_xor_sync(0xffffffffu, q, 16);
            if (gid == 0) {
                int col = n0 + wn + (i >> 1) * 8 + 2 * tig + (i & 1);
                atomicAdd(&g_s1[col], a);
                atomicAdd(&g_s2[col], q);
            }
        }
    }
}

/* ---------------- top-k selection (exact jax.lax.top_k order) ------------ */
__global__ void topk_kernel(const int* __restrict__ text,
                            const float* __restrict__ atten)
{
    int b = blockIdx.x;
    int t = threadIdx.x;            /* 512 threads */
    __shared__ float sval[NT];
    __shared__ int   sidx[NT];
    __shared__ int   red[NT];

    int tv = text[b*NT + t];

    red[t] = (tv << 10) | (NT - 1 - t);
    __syncthreads();
    for (int s = NT/2; s > 0; s >>= 1) {
        if (t < s) red[t] = max(red[t], red[t+s]);
        __syncthreads();
    }
    int eos = NT - 1 - (red[0] & 1023);
    __syncthreads();

    red[t] = (tv != 0) ? 1 : 0;
    __syncthreads();
    for (int s = NT/2; s > 0; s >>= 1) {
        if (t < s) red[t] += red[t+s];
        __syncthreads();
    }
    int nz = red[0];
    __syncthreads();

    float v;
    if (t == 0 || t == eos) v = -1.0f;
    else                    v = atten[((size_t)b*NT + eos)*NT + t];
    if (tv == 0) v = 0.0f;

    sval[t] = v; sidx[t] = t;
    __syncthreads();

    for (int ksz = 2; ksz <= NT; ksz <<= 1) {
        for (int j = ksz >> 1; j > 0; j >>= 1) {
            int ixj = t ^ j;
            if (ixj > t) {
                float va = sval[t], vb = sval[ixj];
                int   ia = sidx[t], ib = sidx[ixj];
                bool aBefore = (va > vb) || (va == vb && ia < ib);
                bool desc = ((t & ksz) == 0);
                if (desc ? !aBefore : aBefore) {
                    sval[t] = vb; sval[ixj] = va;
                    sidx[t] = ib; sidx[ixj] = ia;
                }
            }
            __syncthreads();
        }
    }
    if (t < KTOP) g_idx[b*KTOP + t] = sidx[t];
    if (t == 0) {
        int lnn = nz - 2;
        if (lnn > KTOP) lnn = KTOP;
        if (lnn < 1) lnn = 1;
        g_lens[b] = lnn;
    }
}

/* ---------- gather + L2 normalize + LayerNorm (warp per token) ----------- */
__global__ __launch_bounds__(256)
void gather_ln_kernel(const float* __restrict__ features,
                      const float* __restrict__ lnw,
                      const float* __restrict__ lnb)
{
    int warp = threadIdx.x >> 5;
    int lane = threadIdx.x & 31;
    int token = blockIdx.x * 8 + warp;           /* BKTOK = 4896*8 exact */
    int b = token / KTOP;
    int src = g_idx[token];
    const float* f = features + ((size_t)b*NT + src)*DIM;

    float4 v[4];
    float s1 = 0.f, s2 = 0.f;
#pragma unroll
    for (int q = 0; q < 4; q++) {
        v[q] = *(const float4*)(f + lane*4 + q*128);
        s1 += v[q].x + v[q].y + v[q].z + v[q].w;
        s2 += v[q].x*v[q].x + v[q].y*v[q].y + v[q].z*v[q].z + v[q].w*v[q].w;
    }
#pragma unroll
    for (int st = 16; st > 0; st >>= 1) {
        s1 += __shfl_xor_sync(0xffffffffu, s1, st);
        s2 += __shfl_xor_sync(0xffffffffu, s2, st);
    }
    float inv  = 1.0f / (sqrtf(s2) + 1e-6f);
    float mean = s1 * inv * (1.0f/DIM);
    float et2  = s2 * inv * inv * (1.0f/DIM);
    float var  = et2 - mean*mean;
    float rstd = rsqrtf(var + 1e-5f);

    float*  tokp = g_tok + (size_t)token*DIM;
    __half* qp   = g_qh  + (size_t)token*DIM;
#pragma unroll
    for (int q = 0; q < 4; q++) {
        int c = lane*4 + q*128;
        float4 w4 = *(const float4*)(lnw + c);
        float4 b4 = *(const float4*)(lnb + c);
        float t0 = v[q].x * inv, t1 = v[q].y * inv;
        float t2 = v[q].z * inv, t3 = v[q].w * inv;
        *(float4*)(tokp + c) = make_float4(t0, t1, t2, t3);
        half2 h0 = __floats2half2_rn((t0-mean)*rstd*w4.x + b4.x,
                                     (t1-mean)*rstd*w4.y + b4.y);
        half2 h1 = __floats2half2_rn((t2-mean)*rstd*w4.z + b4.z,
                                     (t3-mean)*rstd*w4.w + b4.w);
        *(half2*)(qp + c)     = h0;
        *(half2*)(qp + c + 2) = h1;
    }
}

/* ------------- tensor-core flash attention: one block per (b,h) ---------- */
__global__ __launch_bounds__(ATT_THREADS)
void attn_tc()
{
    const int h = blockIdx.x, b = blockIdx.y;
    extern __shared__ __half ash[];
    __half* sQ = ash;
    __half* sK = ash + ATT_ROWS*64;
    __half* sV = ash + 2*ATT_ROWS*64;
    const int tid = threadIdx.x;
    const int wid = tid >> 5, lane = tid & 31;
    const int gid = lane >> 2, tig = lane & 3;
    const size_t tokbase = (size_t)b * KTOP;
    const __half* qkv = g_qkvh;

    for (int i = tid; i < ATT_ROWS*8; i += ATT_THREADS) {
        int r = i >> 3, c = i & 7;
        uint4 zq = make_uint4(0,0,0,0), zk = zq, zv = zq;
        if (r < KTOP) {
            const __half* base = qkv + (tokbase + r)*1536 + h*64 + c*8;
            zq = *(const uint4*)(base);
            zk = *(const uint4*)(base + 512);
            zv = *(const uint4*)(base + 1024);
        }
        int off = r*64 + ((c ^ (r & 7)) << 3);
        *(uint4*)(sQ + off) = zq;
        *(uint4*)(sK + off) = zk;
        *(uint4*)(sV + off) = zv;
    }
    __syncthreads();

    const uint32_t uQ = smem_u32(sQ), uK = smem_u32(sK), uV = smem_u32(sV);
    const int wm = wid * 16;
    const int mrow = lane & 7, msel = lane >> 3;

    uint32_t aq[4][4];
    {
        int row = wm + mrow + ((msel & 1) << 3);
        int chalf = msel >> 1;
#pragma unroll
        for (int ks = 0; ks < 4; ks++) {
            int ch = 2*ks + chalf;
            ldsm4(aq[ks][0], aq[ks][1], aq[ks][2], aq[ks][3],
                  uQ + (uint32_t)(row*128 + ((ch ^ (row & 7)) << 4)));
        }
    }

    float mr0 = -1e30f, mr1 = -1e30f, l0 = 0.f, l1 = 0.f;
    float o[8][4];
#pragma unroll
    for (int i = 0; i < 8; i++)
#pragma unroll
        for (int c = 0; c < 4; c++) o[i][c] = 0.f;

#pragma unroll 1
    for (int kc = 0; kc < 3; kc++) {
        float sS[8][4];
#pragma unroll
        for (int i = 0; i < 8; i++)
#pragma unroll
            for (int c = 0; c < 4; c++) sS[i][c] = 0.f;

#pragma unroll
        for (int ks = 0; ks < 4; ks++) {
            int chalf = msel >> 1;
            int ch = 2*ks + chalf;
            int nro = mrow + ((msel & 1) << 3);
#pragma unroll
            for (int p = 0; p < 4; p++) {
                int nr = kc*64 + p*16 + nro;
                uint32_t r0, r1, r2, r3;
                ldsm4(r0, r1, r2, r3,
                      uK + (uint32_t)(nr*128 + ((ch ^ (nr & 7)) << 4)));
                mma_h(sS[2*p][0], sS[2*p][1], sS[2*p][2], sS[2*p][3],
                      aq[ks][0], aq[ks][1], aq[ks][2], aq[ks][3], r0, r2);
                mma_h(sS[2*p+1][0], sS[2*p+1][1], sS[2*p+1][2], sS[2*p+1][3],
                      aq[ks][0], aq[ks][1], aq[ks][2], aq[ks][3], r1, r3);
            }
        }

#pragma unroll
        for (int nf = 0; nf < 8; nf++)
#pragma unroll
            for (int c = 0; c < 4; c++) sS[nf][c] *= 0.125f;
        if (kc == 2) {
#pragma unroll
            for (int nf = 0; nf < 8; nf++) {
                int col = 128 + nf*8 + 2*tig;
                if (col     >= KTOP) { sS[nf][0] = -1e30f; sS[nf][2] = -1e30f; }
                if (col + 1 >= KTOP) { sS[nf][1] = -1e30f; sS[nf][3] = -1e30f; }
            }
        }

        float cm0 = -1e30f, cm1 = -1e30f;
#pragma unroll
        for (int nf = 0; nf < 8; nf++) {
            cm0 = fmaxf(cm0, fmaxf(sS[nf][0], sS[nf][1]));
            cm1 = fmaxf(cm1, fmaxf(sS[nf][2], sS[nf][3]));
        }
        cm0 = fmaxf(cm0, __shfl_xor_sync(0xffffffffu, cm0, 1));
        cm0 = fmaxf(cm0, __shfl_xor_sync(0xffffffffu, cm0, 2));
        cm1 = fmaxf(cm1, __shfl_xor_sync(0xffffffffu, cm1, 1));
        cm1 = fmaxf(cm1, __shfl_xor_sync(0xffffffffu, cm1, 2));
        float nm0 = fmaxf(mr0, cm0), nm1 = fmaxf(mr1, cm1);
        float f0 = __expf(mr0 - nm0), f1 = __expf(mr1 - nm1);
        mr0 = nm0; mr1 = nm1;

        float ls0 = 0.f, ls1 = 0.f;
#pragma unroll
        for (int nf = 0; nf < 8; nf++) {
            sS[nf][0] = __expf(sS[nf][0] - nm0);
            sS[nf][1] = __expf(sS[nf][1] - nm0);
            sS[nf][2] = __expf(sS[nf][2] - nm1);
            sS[nf][3] = __expf(sS[nf][3] - nm1);
            ls0 += sS[nf][0] + sS[nf][1];
            ls1 += sS[nf][2] + sS[nf][3];
        }
        ls0 += __shfl_xor_sync(0xffffffffu, ls0, 1);
        ls0 += __shfl_xor_sync(0xffffffffu, ls0, 2);
        ls1 += __shfl_xor_sync(0xffffffffu, ls1, 1);
        ls1 += __shfl_xor_sync(0xffffffffu, ls1, 2);
        l0 = l0*f0 + ls0;
        l1 = l1*f1 + ls1;
#pragma unroll
        for (int df = 0; df < 8; df++) {
            o[df][0] *= f0; o[df][1] *= f0;
            o[df][2] *= f1; o[df][3] *= f1;
        }

        uint32_t ap[4][4];
#pragma unroll
        for (int j = 0; j < 4; j++) {
            ap[j][0] = pack_h2(sS[2*j][0],   sS[2*j][1]);
            ap[j][1] = pack_h2(sS[2*j][2],   sS[2*j][3]);
            ap[j][2] = pack_h2(sS[2*j+1][0], sS[2*j+1][1]);
            ap[j][3] = pack_h2(sS[2*j+1][2], sS[2*j+1][3]);
        }

#pragma unroll
        for (int j = 0; j < 4; j++) {
            int kr = kc*64 + j*16 + mrow + ((msel & 1) << 3);
            int chalf = msel >> 1;
#pragma unroll
            for (int p = 0; p < 4; p++) {
                int ch = 2*p + chalf;
                uint32_t r0, r1, r2, r3;
                ldsm4t(r0, r1, r2, r3,
                       uV + (uint32_t)(kr*128 + ((ch ^ (kr & 7)) << 4)));
                mma_h(o[2*p][0], o[2*p][1], o[2*p][2], o[2*p][3],
                      ap[j][0], ap[j][1], ap[j][2], ap[j][3], r0, r1);
                mma_h(o[2*p+1][0], o[2*p+1][1], o[2*p+1][2], o[2*p+1][3],
                      ap[j][0], ap[j][1], ap[j][2], ap[j][3], r2, r3);
            }
        }
    }

    float inv0 = 1.0f / l0, inv1 = 1.0f / l1;
    int r0g = wm + gid, r1g = wm + gid + 8;
#pragma unroll
    for (int df = 0; df < 8; df++) {
        int d = df*8 + 2*tig;
        if (r0g < KTOP)
            *(half2*)(g_sa + (tokbase + r0g)*512 + h*64 + d) =
                __floats2half2_rn(o[df][0]*inv0, o[df][1]*inv0);
        if (r1g < KTOP)
            *(half2*)(g_sa + (tokbase + r1g)*512 + h*64 + d) =
                __floats2half2_rn(o[df][2]*inv1, o[df][3]*inv1);
    }
}

/* --------------------------- BatchNorm (train) --------------------------- */
__global__ void bn_final()
{
    int c = threadIdx.x;                   /* 512 */
    float mean = g_s1[c] / (float)BKTOK;
    float var  = g_s2[c] / (float)BKTOK - mean*mean;
    g_mu[c]   = mean;
    g_rstd[c] = rsqrtf(var + 1e-5f);
}

__global__ void bn_apply(const float* __restrict__ bnw, const float* __restrict__ bnb)
{
    size_t i = (size_t)blockIdx.x*256 + threadIdx.x;   /* over BKTOK*256 h2 */
    if (i < (size_t)BKTOK*256) {
        int c2 = (int)(i & 255);
        int c  = c2 * 2;
        size_t row = i >> 8;
        half2 hv = ((const half2*)g_hh)[i];
        float x0 = __low2float(hv), x1 = __high2float(hv);
        x0 = (x0 - g_mu[c  ]) * g_rstd[c  ] * bnw[c  ] + bnb[c  ];
        x1 = (x1 - g_mu[c+1]) * g_rstd[c+1] * bnw[c+1] + bnb[c+1];
        ((half2*)(g_comb + row*1024 + 512))[c2] =
            __floats2half2_rn(fmaxf(x0, 0.f), fmaxf(x1, 0.f));
    }
}

/* ------------------------------- launcher -------------------------------- */
extern "C" void kernel_launch(void* const* d_in, const int* in_sizes, int n_in,
                              void* d_out, int out_size)
{
    const float* features = (const float*)d_in[0];
    const int*   text     = (const int*)  d_in[1];
    const float* atten    = (const float*)d_in[2];
    const float* ln_q_w   = (const float*)d_in[3];
    const float* ln_q_b   = (const float*)d_in[4];
    const float* sa_in_w  = (const float*)d_in[5];
    const float* sa_in_b  = (const float*)d_in[6];
    const float* sa_out_w = (const float*)d_in[7];
    const float* sa_out_b = (const float*)d_in[8];
    const float* ref_w1   = (const float*)d_in[9];
    const float* ref_b1   = (const float*)d_in[10];
    const float* ref_w2   = (const float*)d_in[11];
    const float* ref_b2   = (const float*)d_in[12];
    const float* gscal    = (const float*)d_in[13];
    const float* lin_w    = (const float*)d_in[14];
    const float* lin_b    = (const float*)d_in[15];
    const float* mlp_w1   = (const float*)d_in[16];
    const float* mlp_b1   = (const float*)d_in[17];
    const float* bn_w     = (const float*)d_in[18];
    const float* bn_b     = (const float*)d_in[19];
    const float* mlp_w2   = (const float*)d_in[20];
    const float* mlp_b2   = (const float*)d_in[21];
    float* out = (float*)d_out;

    float *p_tok, *p_bfin, *p_bfuse, *p_zero;
    __half *p_qh, *p_qkvh, *p_sa, *p_y1h, *p_comb, *p_hh;
    __half *w_sain, *w_soT, *w_ref1, *w_ref2, *w_mlp1, *w_fin, *w_fuse;
    cudaGetSymbolAddress((void**)&p_tok,  g_tok);
    cudaGetSymbolAddress((void**)&p_qh,   g_qh);
    cudaGetSymbolAddress((void**)&p_qkvh, g_qkvh);
    cudaGetSymbolAddress((void**)&p_sa,   g_sa);
    cudaGetSymbolAddress((void**)&p_y1h,  g_y1h);
    cudaGetSymbolAddress((void**)&p_comb, g_comb);
    cudaGetSymbolAddress((void**)&p_hh,   g_hh);
    cudaGetSymbolAddress((void**)&p_bfin, g_bias_fin);
    cudaGetSymbolAddress((void**)&p_bfuse, g_bfuse);
    cudaGetSymbolAddress((void**)&p_zero, g_zero512);
    cudaGetSymbolAddress((void**)&w_sain,  g_w_sain);
    cudaGetSymbolAddress((void**)&w_soT,   g_w_soT);
    cudaGetSymbolAddress((void**)&w_ref1,  g_w_ref1);
    cudaGetSymbolAddress((void**)&w_ref2,  g_w_ref2);
    cudaGetSymbolAddress((void**)&w_mlp1,  g_w_mlp1);
    cudaGetSymbolAddress((void**)&w_fin,   g_w_fin);
    cudaGetSymbolAddress((void**)&w_fuse,  g_w_fuse);

    cudaFuncSetAttribute(gemm_h16<0,1,0,0>, cudaFuncAttributeMaxDynamicSharedMemorySize, GEMM_SMEM);
    cudaFuncSetAttribute(gemm_h16<0,1,1,0>, cudaFuncAttributeMaxDynamicSharedMemorySize, GEMM_SMEM);
    cudaFuncSetAttribute(gemm_h16<1,1,0,0>, cudaFuncAttributeMaxDynamicSharedMemorySize, GEMM_SMEM);
    cudaFuncSetAttribute(gemm_h16<2,1,0,0>, cudaFuncAttributeMaxDynamicSharedMemorySize, GEMM_SMEM);
    cudaFuncSetAttribute(gemm_h16<0,0,0,1>, cudaFuncAttributeMaxDynamicSharedMemorySize, GEMM_SMEM);
    cudaFuncSetAttribute(attn_tc, cudaFuncAttributeMaxDynamicSharedMemorySize, ATT_SMEM);

    const int MROWS = BKTOK;             /* 39168 = 306*128 */

    cvt_all_kernel<<<(P6+255)/256, 256>>>(sa_in_w, sa_out_w, ref_w1, ref_w2,
                                          lin_w, mlp_w1, mlp_w2, lin_b, mlp_b2);
    /* W_fuse = W_r1 @ W_so */
    gemm_h16<0,1,0,0><<<dim3(512/128, 1024/128), 128, GEMM_SMEM>>>(
        w_ref1, 512, w_soT, p_zero, w_fuse, 512, 1024, 512, 512, nullptr, nullptr);
    fuse_bias_kernel<<<1024, 128>>>(ref_w1, sa_out_b, ref_b1);
    out_init_kernel<<<BATCH*EDIM/256, 256>>>(out);

    topk_kernel<<<BATCH, NT>>>(text, atten);
    gather_ln_kernel<<<BKTOK/8, 256>>>(features, ln_q_w, ln_q_b);

    /* qkv = LN(tok) @ sa_in_w^T + b  (half out) */
    gemm_h16<0,1,0,0><<<dim3(1536/128, MROWS/128), 128, GEMM_SMEM>>>(
        p_qh, 512, w_sain, sa_in_b, p_qkvh, 1536, MROWS, 1536, 512, nullptr, nullptr);
    attn_tc<<<dim3(NHEADS, BATCH), ATT_THREADS, ATT_SMEM>>>();

    /* y1 = gelu(sa @ W_fuse^T + b_fuse)  (half out) */
    gemm_h16<1,1,0,0><<<dim3(1024/128, MROWS/128), 128, GEMM_SMEM>>>(
        p_sa, 512, w_fuse, p_bfuse, p_y1h, 1024, MROWS, 1024, 512, nullptr, nullptr);
    /* comb[:,0:512] = tok + sigmoid(g)*(y1 @ ref_w2^T + b)  (half out, ldc=1024) */
    gemm_h16<2,1,0,0><<<dim3(512/128, MROWS/128), 128, GEMM_SMEM>>>(
        p_y1h, 1024, w_ref2, ref_b2, p_comb, 1024, MROWS, 512, 1024, p_tok, gscal);
    /* h = tok_h @ mlp_w1^T + b  (half out + fused BN stats) */
    gemm_h16<0,1,1,0><<<dim3(512/128, MROWS/128), 128, GEMM_SMEM>>>(
        p_comb, 1024, w_mlp1, mlp_b1, p_hh, 512, MROWS, 512, 512, nullptr, nullptr);
    bn_final<<<1, 512>>>();
    bn_apply<<<(int)(((size_t)BKTOK*256 + 255)/256), 256>>>(bn_w, bn_b);

    /* feat GEMM with fused masked max-pool -> out (atomicMax) */
    gemm_h16<0,0,0,1><<<dim3(1024/128, MROWS/128), 128, GEMM_SMEM>>>(
        p_comb, 1024, w_fin, p_bfin, out, 1024, MROWS, 1024, 1024, nullptr, nullptr);
}

// round 14
// speedup vs baseline: 7.7640x; 1.0150x over previous
#include <cuda_runtime.h>
#include <cuda_fp16.h>
#include <math.h>
#include <stdint.h>

#define BATCH 256
#define NT 512
#define DIM 512
#define KTOP 153
#define BKTOK (BATCH*KTOP)      /* 39168 = 306*128 */
#define EDIM 1024
#define NHEADS 8

#define GEMM_SMEM (4*16384)     /* 4 stages x (A 8KB + B 8KB) */
#define ATT_THREADS 320
#define ATT_ROWS 192            /* padded tile rows (3 chunks of 64) */
#define ATT_SMEM (3*ATT_ROWS*64*2)   /* Q,K,V half tiles: 73728 B */

/* ---------------- scratch (device globals; no allocation) ---------------- */
__device__ int    g_idx[BKTOK];
__device__ int    g_lens[BATCH];
__device__ __half g_tokh0[(size_t)BKTOK*DIM];      /* half residual source */
__device__ __half g_qh[(size_t)BKTOK*DIM];         /* LN out (GEMM A) */
__device__ __half g_qkvh[(size_t)BKTOK*3*DIM];     /* half qkv */
__device__ __half g_sa[(size_t)BKTOK*DIM];
__device__ __half g_y1h[(size_t)BKTOK*2*DIM];
__device__ __half g_comb[(size_t)BKTOK*1024];      /* [tok_h | relu_bn_h] */
__device__ __half g_hh[(size_t)BKTOK*DIM];         /* pre-BN h (half) */
__device__ float  g_s1[512];
__device__ float  g_s2[512];
/* half-converted weights */
__device__ __half g_w_sain[1536*512];
__device__ __half g_w_soT[512*512];                /* sa_out_w transposed */
__device__ __half g_w_ref1[1024*512];
__device__ __half g_w_ref2[512*1024];
__device__ __half g_w_mlp1[512*512];
__device__ __half g_w_fin[1024*1024];              /* [lin_w | mlp_w2] */
__device__ __half g_w_fuse[1024*512];              /* W_r1 @ W_so */
__device__ float  g_bias_fin[1024];                /* lin_b + mlp_b2 */
__device__ float  g_bfuse[1024];                   /* W_r1 @ b_so + b_r1 */
__device__ float  g_zero512[512];

/* ------------------------------ helpers ---------------------------------- */
__device__ __forceinline__ uint32_t smem_u32(const void* p) {
    uint32_t a;
    asm("{ .reg .u64 t; cvta.to.shared.u64 t, %1; cvt.u32.u64 %0, t; }"
        : "=r"(a) : "l"(p));
    return a;
}
#define CP_ASYNC16(dst, src) \
    asm volatile("cp.async.cg.shared.global [%0], [%1], 16;" :: "r"(dst), "l"(src))
#define CP_COMMIT()  asm volatile("cp.async.commit_group;" ::: "memory")
#define CP_WAIT_2()  asm volatile("cp.async.wait_group 2;" ::: "memory")

__device__ __forceinline__ void ldsm4(uint32_t& r0, uint32_t& r1,
                                      uint32_t& r2, uint32_t& r3, uint32_t addr) {
    asm volatile("ldmatrix.sync.aligned.m8n8.x4.shared.b16 {%0,%1,%2,%3}, [%4];"
                 : "=r"(r0), "=r"(r1), "=r"(r2), "=r"(r3) : "r"(addr));
}
__device__ __forceinline__ void ldsm4t(uint32_t& r0, uint32_t& r1,
                                       uint32_t& r2, uint32_t& r3, uint32_t addr) {
    asm volatile("ldmatrix.sync.aligned.m8n8.x4.trans.shared.b16 {%0,%1,%2,%3}, [%4];"
                 : "=r"(r0), "=r"(r1), "=r"(r2), "=r"(r3) : "r"(addr));
}
__device__ __forceinline__ void mma_h(float& d0, float& d1, float& d2, float& d3,
                                      uint32_t a0, uint32_t a1, uint32_t a2, uint32_t a3,
                                      uint32_t b0, uint32_t b1)
{
    asm volatile(
        "mma.sync.aligned.m16n8k16.row.col.f32.f16.f16.f32 "
        "{%0,%1,%2,%3}, {%4,%5,%6,%7}, {%8,%9}, {%0,%1,%2,%3};"
        : "+f"(d0), "+f"(d1), "+f"(d2), "+f"(d3)
        : "r"(a0), "r"(a1), "r"(a2), "r"(a3), "r"(b0), "r"(b1));
}
__device__ __forceinline__ uint32_t pack_h2(float a, float b) {
    half2 h = __floats2half2_rn(a, b);
    return *(uint32_t*)&h;
}
/* exact order-independent float atomic max (sign-split trick) */
__device__ __forceinline__ void atomicMaxF(float* a, float v) {
    if (v >= 0.f) atomicMax((int*)a, __float_as_int(v));
    else          atomicMin((unsigned int*)a, __float_as_uint(v));
}

/* -------- weight conversion fp32 -> fp16 + stats zero + bias sum --------- */
/* counts in half2 units */
#define P0 393216                 /* sain  1536x512 */
#define P1 (P0+131072)            /* saout  512x512 -> TRANSPOSED g_w_soT */
#define P2 (P1+262144)            /* ref1  1024x512 */
#define P3 (P2+262144)            /* ref2   512x1024 */
#define P4 (P3+262144)            /* lin   1024x512 -> fin cols 0..511 */
#define P5 (P4+131072)            /* mlp1   512x512 */
#define P6 (P5+262144)            /* mlp2  1024x512 -> fin cols 512..1023 */
__global__ void cvt_all_kernel(const float* s_sain, const float* s_saout,
                               const float* s_ref1, const float* s_ref2,
                               const float* s_lin,  const float* s_mlp1,
                               const float* s_mlp2,
                               const float* lin_b,  const float* mlp_b2,
                               float* __restrict__ out)
{
    int t = threadIdx.x;
    if (blockIdx.x == 0) {
        g_s1[t] = 0.f; g_s1[t+256] = 0.f;
        g_s2[t] = 0.f; g_s2[t+256] = 0.f;
        g_zero512[t] = 0.f; g_zero512[t+256] = 0.f;
    }
    if (blockIdx.x == 1) {
#pragma unroll
        for (int q = 0; q < 4; q++)
            g_bias_fin[t + q*256] = lin_b[t + q*256] + mlp_b2[t + q*256];
    }
    if (blockIdx.x < BATCH*EDIM/256)     /* init out to -inf (fused pool) */
        out[blockIdx.x * 256 + t] = __int_as_float(0xff800000);

    int i = blockIdx.x * 256 + t;
    if (i >= P6) return;
    if (i < P0) {
        float2 v = ((const float2*)s_sain)[i];
        ((half2*)g_w_sain)[i] = __floats2half2_rn(v.x, v.y);
    } else if (i < P1) {
        int o = i - P0;
        int k = o >> 8, c2 = o & 255;
        float2 v = ((const float2*)s_saout)[o];
        g_w_soT[(2*c2  )*512 + k] = __float2half_rn(v.x);
        g_w_soT[(2*c2+1)*512 + k] = __float2half_rn(v.y);
    } else if (i < P2) {
        int o = i - P1;
        float2 v = ((const float2*)s_ref1)[o];
        ((half2*)g_w_ref1)[o] = __floats2half2_rn(v.x, v.y);
    } else if (i < P3) {
        int o = i - P2;
        float2 v = ((const float2*)s_ref2)[o];
        ((half2*)g_w_ref2)[o] = __floats2half2_rn(v.x, v.y);
    } else if (i < P4) {
        int o = i - P3;
        int n = o >> 8, kk = o & 255;
        float2 v = ((const float2*)s_lin)[o];
        ((half2*)g_w_fin)[n*512 + kk] = __floats2half2_rn(v.x, v.y);
    } else if (i < P5) {
        int o = i - P4;
        float2 v = ((const float2*)s_mlp1)[o];
        ((half2*)g_w_mlp1)[o] = __floats2half2_rn(v.x, v.y);
    } else {
        int o = i - P5;
        int n = o >> 8, kk = o & 255;
        float2 v = ((const float2*)s_mlp2)[o];
        ((half2*)g_w_fin)[n*512 + 256 + kk] = __floats2half2_rn(v.x, v.y);
    }
}

/* ---- fused bias: b_fuse[i] = dot(ref_w1[i,:], sa_out_b) + ref_b1[i] ----- */
__global__ void fuse_bias_kernel(const float* __restrict__ ref_w1,
                                 const float* __restrict__ sa_out_b,
                                 const float* __restrict__ ref_b1)
{
    int row = blockIdx.x;                /* 1024 */
    int t = threadIdx.x;                 /* 128 */
    const float* wr = ref_w1 + (size_t)row * 512;
    float s = 0.f;
#pragma unroll
    for (int q = 0; q < 4; q++) s += wr[t + q*128] * sa_out_b[t + q*128];
    __shared__ float red[128];
    red[t] = s;
    __syncthreads();
    for (int st = 64; st > 0; st >>= 1) {
        if (t < st) red[t] += red[t+st];
        __syncthreads();
    }
    if (t == 0) g_bfuse[row] = red[0] + ref_b1[row];
}

/* ---- fp16 tensor-core GEMM (cp.async + ldmatrix): C = A @ W^T + bias ---- */
/* 128 threads, 4 warps, warp tile 64x64 (2x2 warp grid over 128x128 tile).  */
/* EPI: 0=bias 1=gelu(bias) 2=C=auxh+sigmoid(g)*(acc+bias) (aux is half)     */
/* OUTH: store half.  STATS: BN column sums.  POOL: fused masked max-pool.   */
template<int EPI, int OUTH, int STATS, int POOL>
__global__ __launch_bounds__(128, 2)
void gemm_h16(const __half* __restrict__ A, int lda,
              const __half* __restrict__ W,
              const float* __restrict__ bias, void* __restrict__ Cout, int ldc,
              int M, int N, int K,
              const void* __restrict__ aux, const float* __restrict__ gptr)
{
    extern __shared__ __half smh[];
    const int tid  = threadIdx.x;
    const int wid  = tid >> 5;           /* 0..3 */
    const int lane = tid & 31;
    const int gid  = lane >> 2;
    const int tig  = lane & 3;
    const int wm   = (wid & 1) * 64;
    const int wn   = (wid >> 1) * 64;
    const int m0   = blockIdx.y * 128;
    const int n0   = blockIdx.x * 128;

    const uint32_t sbase = smem_u32(smh);

    uint32_t sto[4];
    const __half* srcA[4];
    const __half* srcB[4];
#pragma unroll
    for (int q = 0; q < 4; q++) {
        int id  = tid + q * 128;
        int row = id >> 2, cc = id & 3;
        sto[q]  = (uint32_t)(row * 64 + ((cc ^ (row & 3)) << 4));
        srcA[q] = A + (size_t)(m0 + row) * lda + cc * 8;
        srcB[q] = W + (size_t)(n0 + row) * K + cc * 8;
    }

    uint32_t aOff[4], bOff[4];
#pragma unroll
    for (int mt = 0; mt < 4; mt++) {
        int r  = wm + mt * 16 + (lane & 15);
        int ch = lane >> 4;
        aOff[mt] = (uint32_t)(r * 64 + ((ch ^ (r & 3)) << 4));
    }
#pragma unroll
    for (int njp = 0; njp < 4; njp++) {
        int r  = wn + njp * 16 + (lane & 7) + ((lane >> 4) << 3);
        int ch = (lane >> 3) & 1;
        bOff[njp] = (uint32_t)(8192 + r * 64 + ((ch ^ (r & 3)) << 4));
    }

    float acc[4][8][4];
#pragma unroll
    for (int i = 0; i < 4; i++)
#pragma unroll
        for (int j = 0; j < 8; j++)
#pragma unroll
            for (int c = 0; c < 4; c++) acc[i][j][c] = 0.f;

    const int nch = K >> 5;

    auto load_chunk = [&](int c) {
        uint32_t sb = sbase + (uint32_t)(c & 3) * 16384u;
        size_t ko = (size_t)c * 32;
#pragma unroll
        for (int q = 0; q < 4; q++) {
            CP_ASYNC16(sb + sto[q],        srcA[q] + ko);
            CP_ASYNC16(sb + 8192 + sto[q], srcB[q] + ko);
        }
    };

    load_chunk(0); CP_COMMIT();
    load_chunk(1); CP_COMMIT();
    load_chunk(2); CP_COMMIT();

    for (int c = 0; c < nch; c++) {
        CP_WAIT_2();
        __syncthreads();
        if (c + 3 < nch) load_chunk(c + 3);
        CP_COMMIT();

        uint32_t stb = sbase + (uint32_t)(c & 3) * 16384u;
#pragma unroll
        for (int ks = 0; ks < 2; ks++) {
            const uint32_t kx = (uint32_t)(ks << 5);
            uint32_t af[4][4], bf[4][4];
#pragma unroll
            for (int mt = 0; mt < 4; mt++)
                ldsm4(af[mt][0], af[mt][1], af[mt][2], af[mt][3],
                      stb + (aOff[mt] ^ kx));
#pragma unroll
            for (int njp = 0; njp < 4; njp++)
                ldsm4(bf[njp][0], bf[njp][1], bf[njp][2], bf[njp][3],
                      stb + (bOff[njp] ^ kx));
#pragma unroll
            for (int mt = 0; mt < 4; mt++)
#pragma unroll
                for (int nj = 0; nj < 8; nj++) {
                    const int njp = nj >> 1, pr = (nj & 1) << 1;
                    mma_h(acc[mt][nj][0], acc[mt][nj][1], acc[mt][nj][2], acc[mt][nj][3],
                          af[mt][0], af[mt][1], af[mt][2], af[mt][3],
                          bf[njp][pr], bf[njp][pr + 1]);
                }
        }
    }

    /* -------------------- fused masked max-pool epilogue ----------------- */
    if (POOL) {
        const int base = m0 + wm + gid;
        int bj[8]; bool vj[8];
#pragma unroll
        for (int j = 0; j < 8; j++) {
            int R = base + 8*j;
            int bb = R / KTOP;
            bj[j] = bb;
            vj[j] = (R - bb*KTOP) < g_lens[bb];
        }
        float* outp = (float*)Cout;
        const int bF = bj[0], bL = bj[7];
#pragma unroll
        for (int nj = 0; nj < 8; nj++) {
            int cc = n0 + wn + nj*8 + 2*tig;
            float b0f = bias[cc], b1f = bias[cc + 1];
            float mA0 = -3e38f, mA1 = -3e38f, mB0 = -3e38f, mB1 = -3e38f;
#pragma unroll
            for (int j = 0; j < 8; j++) {
                int mt = j >> 1, rh = (j & 1) << 1;
                float x0 = acc[mt][nj][rh]     + b0f;
                float x1 = acc[mt][nj][rh + 1] + b1f;
                bool sameb = (bj[j] == bF);
                if (vj[j] && sameb)  { mA0 = fmaxf(mA0, x0); mA1 = fmaxf(mA1, x1); }
                if (vj[j] && !sameb) { mB0 = fmaxf(mB0, x0); mB1 = fmaxf(mB1, x1); }
            }
            if (mA0 > -3e38f) atomicMaxF(outp + (size_t)bF*EDIM + cc,     mA0);
            if (mA1 > -3e38f) atomicMaxF(outp + (size_t)bF*EDIM + cc + 1, mA1);
            if (bL != bF) {
                if (mB0 > -3e38f) atomicMaxF(outp + (size_t)bL*EDIM + cc,     mB0);
                if (mB1 > -3e38f) atomicMaxF(outp + (size_t)bL*EDIM + cc + 1, mB1);
            }
        }
        return;
    }

    /* ----------------------------- epilogue ------------------------------ */
    float sg = 0.f;
    if (EPI == 2) sg = 1.0f / (1.0f + expf(-gptr[0]));
    float st1[16], st2[16];
    if (STATS) {
#pragma unroll
        for (int i = 0; i < 16; i++) { st1[i] = 0.f; st2[i] = 0.f; }
    }

#pragma unroll
    for (int mt = 0; mt < 4; mt++) {
#pragma unroll
        for (int nj = 0; nj < 8; nj++) {
            int r  = m0 + wm + mt * 16 + gid;
            int cc = n0 + wn + nj * 8 + 2 * tig;
            float b0v = bias[cc], b1v = bias[cc + 1];
            float v[4];
            v[0] = acc[mt][nj][0] + b0v;
            v[1] = acc[mt][nj][1] + b1v;
            v[2] = acc[mt][nj][2] + b0v;
            v[3] = acc[mt][nj][3] + b1v;
            if (EPI == 1) {
#pragma unroll
                for (int c = 0; c < 4; c++)
                    v[c] = 0.5f * v[c] * (1.0f + erff(v[c] * 0.70710678118654752f));
            }
            if (EPI == 2) {
                const __half* auxh = (const __half*)aux;
                half2 a0 = *(const half2*)(auxh + (size_t)r * N + cc);
                half2 a1 = *(const half2*)(auxh + (size_t)(r + 8) * N + cc);
                v[0] = __low2float(a0)  + sg * v[0];
                v[1] = __high2float(a0) + sg * v[1];
                v[2] = __low2float(a1)  + sg * v[2];
                v[3] = __high2float(a1) + sg * v[3];
            }
            if (STATS) {
                st1[nj*2+0] += v[0] + v[2];
                st1[nj*2+1] += v[1] + v[3];
                st2[nj*2+0] += v[0]*v[0] + v[2]*v[2];
                st2[nj*2+1] += v[1]*v[1] + v[3]*v[3];
            }
            if (OUTH) {
                __half* Ch = (__half*)Cout;
                *(half2*)(Ch + (size_t)r * ldc + cc)       = __floats2half2_rn(v[0], v[1]);
                *(half2*)(Ch + (size_t)(r + 8) * ldc + cc) = __floats2half2_rn(v[2], v[3]);
            } else {
                float* Cf = (float*)Cout;
                *(float2*)(Cf + (size_t)r * ldc + cc)       = make_float2(v[0], v[1]);
                *(float2*)(Cf + (size_t)(r + 8) * ldc + cc) = make_float2(v[2], v[3]);
            }
        }
    }
    if (STATS) {
#pragma unroll
        for (int i = 0; i < 16; i++) {
            float a = st1[i], q = st2[i];
            a += __shfl_xor_sync(0xffffffffu, a, 4);
            a += __shfl_xor_sync(0xffffffffu, a, 8);
            a += __shfl_xor_sync(0xffffffffu, a, 16);
            q += __shfl_xor_sync(0xffffffffu, q, 4);
            q += __shfl_xor_sync(0xffffffffu, q, 8);
            q += __shfl_xor_sync(0xffffffffu, q, 16);
            if (gid == 0) {
                int col = n0 + wn + (i >> 1) * 8 + 2 * tig + (i & 1);
                atomicAdd(&g_s1[col], a);
                atomicAdd(&g_s2[col], q);
            }
        }
    }
}

/* ---------------- top-k selection (exact jax.lax.top_k order) ------------ */
__global__ void topk_kernel(const int* __restrict__ text,
                            const float* __restrict__ atten)
{
    int b = blockIdx.x;
    int t = threadIdx.x;            /* 512 threads */
    __shared__ float sval[NT];
    __shared__ int   sidx[NT];
    __shared__ int   red[NT];

    int tv = text[b*NT + t];

    red[t] = (tv << 10) | (NT - 1 - t);
    __syncthreads();
    for (int s = NT/2; s > 0; s >>= 1) {
        if (t < s) red[t] = max(red[t], red[t+s]);
        __syncthreads();
    }
    int eos = NT - 1 - (red[0] & 1023);
    __syncthreads();

    red[t] = (tv != 0) ? 1 : 0;
    __syncthreads();
    for (int s = NT/2; s > 0; s >>= 1) {
        if (t < s) red[t] += red[t+s];
        __syncthreads();
    }
    int nz = red[0];
    __syncthreads();

    float v;
    if (t == 0 || t == eos) v = -1.0f;
    else                    v = atten[((size_t)b*NT + eos)*NT + t];
    if (tv == 0) v = 0.0f;

    sval[t] = v; sidx[t] = t;
    __syncthreads();

    for (int ksz = 2; ksz <= NT; ksz <<= 1) {
        for (int j = ksz >> 1; j > 0; j >>= 1) {
            int ixj = t ^ j;
            if (ixj > t) {
                float va = sval[t], vb = sval[ixj];
                int   ia = sidx[t], ib = sidx[ixj];
                bool aBefore = (va > vb) || (va == vb && ia < ib);
                bool desc = ((t & ksz) == 0);
                if (desc ? !aBefore : aBefore) {
                    sval[t] = vb; sval[ixj] = va;
                    sidx[t] = ib; sidx[ixj] = ia;
                }
            }
            __syncthreads();
        }
    }
    if (t < KTOP) g_idx[b*KTOP + t] = sidx[t];
    if (t == 0) {
        int lnn = nz - 2;
        if (lnn > KTOP) lnn = KTOP;
        if (lnn < 1) lnn = 1;
        g_lens[b] = lnn;
    }
}

/* ---------- gather + L2 normalize + LayerNorm (warp per token) ----------- */
__global__ __launch_bounds__(256)
void gather_ln_kernel(const float* __restrict__ features,
                      const float* __restrict__ lnw,
                      const float* __restrict__ lnb)
{
    int warp = threadIdx.x >> 5;
    int lane = threadIdx.x & 31;
    int token = blockIdx.x * 8 + warp;           /* BKTOK = 4896*8 exact */
    int b = token / KTOP;
    int src = g_idx[token];
    const float* f = features + ((size_t)b*NT + src)*DIM;

    float4 v[4];
    float s1 = 0.f, s2 = 0.f;
#pragma unroll
    for (int q = 0; q < 4; q++) {
        v[q] = *(const float4*)(f + lane*4 + q*128);
        s1 += v[q].x + v[q].y + v[q].z + v[q].w;
        s2 += v[q].x*v[q].x + v[q].y*v[q].y + v[q].z*v[q].z + v[q].w*v[q].w;
    }
#pragma unroll
    for (int st = 16; st > 0; st >>= 1) {
        s1 += __shfl_xor_sync(0xffffffffu, s1, st);
        s2 += __shfl_xor_sync(0xffffffffu, s2, st);
    }
    float inv  = 1.0f / (sqrtf(s2) + 1e-6f);
    float mean = s1 * inv * (1.0f/DIM);
    float et2  = s2 * inv * inv * (1.0f/DIM);
    float var  = et2 - mean*mean;
    float rstd = rsqrtf(var + 1e-5f);

    __half* tokp = g_tokh0 + (size_t)token*DIM;
    __half* qp   = g_qh    + (size_t)token*DIM;
#pragma unroll
    for (int q = 0; q < 4; q++) {
        int c = lane*4 + q*128;
        float4 w4 = *(const float4*)(lnw + c);
        float4 b4 = *(const float4*)(lnb + c);
        float t0 = v[q].x * inv, t1 = v[q].y * inv;
        float t2 = v[q].z * inv, t3 = v[q].w * inv;
        *(half2*)(tokp + c)     = __floats2half2_rn(t0, t1);
        *(half2*)(tokp + c + 2) = __floats2half2_rn(t2, t3);
        half2 h0 = __floats2half2_rn((t0-mean)*rstd*w4.x + b4.x,
                                     (t1-mean)*rstd*w4.y + b4.y);
        half2 h1 = __floats2half2_rn((t2-mean)*rstd*w4.z + b4.z,
                                     (t3-mean)*rstd*w4.w + b4.w);
        *(half2*)(qp + c)     = h0;
        *(half2*)(qp + c + 2) = h1;
    }
}

/* ------------- tensor-core flash attention: one block per (b,h) ---------- */
__global__ __launch_bounds__(ATT_THREADS)
void attn_tc()
{
    const int h = blockIdx.x, b = blockIdx.y;
    extern __shared__ __half ash[];
    __half* sQ = ash;
    __half* sK = ash + ATT_ROWS*64;
    __half* sV = ash + 2*ATT_ROWS*64;
    const int tid = threadIdx.x;
    const int wid = tid >> 5, lane = tid & 31;
    const int gid = lane >> 2, tig = lane & 3;
    const size_t tokbase = (size_t)b * KTOP;
    const __half* qkv = g_qkvh;

    for (int i = tid; i < ATT_ROWS*8; i += ATT_THREADS) {
        int r = i >> 3, c = i & 7;
        uint4 zq = make_uint4(0,0,0,0), zk = zq, zv = zq;
        if (r < KTOP) {
            const __half* base = qkv + (tokbase + r)*1536 + h*64 + c*8;
            zq = *(const uint4*)(base);
            zk = *(const uint4*)(base + 512);
            zv = *(const uint4*)(base + 1024);
        }
        int off = r*64 + ((c ^ (r & 7)) << 3);
        *(uint4*)(sQ + off) = zq;
        *(uint4*)(sK + off) = zk;
        *(uint4*)(sV + off) = zv;
    }
    __syncthreads();

    const uint32_t uQ = smem_u32(sQ), uK = smem_u32(sK), uV = smem_u32(sV);
    const int wm = wid * 16;
    const int mrow = lane & 7, msel = lane >> 3;

    uint32_t aq[4][4];
    {
        int row = wm + mrow + ((msel & 1) << 3);
        int chalf = msel >> 1;
#pragma unroll
        for (int ks = 0; ks < 4; ks++) {
            int ch = 2*ks + chalf;
            ldsm4(aq[ks][0], aq[ks][1], aq[ks][2], aq[ks][3],
                  uQ + (uint32_t)(row*128 + ((ch ^ (row & 7)) << 4)));
        }
    }

    float mr0 = -1e30f, mr1 = -1e30f, l0 = 0.f, l1 = 0.f;
    float o[8][4];
#pragma unroll
    for (int i = 0; i < 8; i++)
#pragma unroll
        for (int c = 0; c < 4; c++) o[i][c] = 0.f;

#pragma unroll 1
    for (int kc = 0; kc < 3; kc++) {
        float sS[8][4];
#pragma unroll
        for (int i = 0; i < 8; i++)
#pragma unroll
            for (int c = 0; c < 4; c++) sS[i][c] = 0.f;

#pragma unroll
        for (int ks = 0; ks < 4; ks++) {
            int chalf = msel >> 1;
            int ch = 2*ks + chalf;
            int nro = mrow + ((msel & 1) << 3);
#pragma unroll
            for (int p = 0; p < 4; p++) {
                int nr = kc*64 + p*16 + nro;
                uint32_t r0, r1, r2, r3;
                ldsm4(r0, r1, r2, r3,
                      uK + (uint32_t)(nr*128 + ((ch ^ (nr & 7)) << 4)));
                mma_h(sS[2*p][0], sS[2*p][1], sS[2*p][2], sS[2*p][3],
                      aq[ks][0], aq[ks][1], aq[ks][2], aq[ks][3], r0, r2);
                mma_h(sS[2*p+1][0], sS[2*p+1][1], sS[2*p+1][2], sS[2*p+1][3],
                      aq[ks][0], aq[ks][1], aq[ks][2], aq[ks][3], r1, r3);
            }
        }

#pragma unroll
        for (int nf = 0; nf < 8; nf++)
#pragma unroll
            for (int c = 0; c < 4; c++) sS[nf][c] *= 0.125f;
        if (kc == 2) {
#pragma unroll
            for (int nf = 0; nf < 8; nf++) {
                int col = 128 + nf*8 + 2*tig;
                if (col     >= KTOP) { sS[nf][0] = -1e30f; sS[nf][2] = -1e30f; }
                if (col + 1 >= KTOP) { sS[nf][1] = -1e30f; sS[nf][3] = -1e30f; }
            }
        }

        float cm0 = -1e30f, cm1 = -1e30f;
#pragma unroll
        for (int nf = 0; nf < 8; nf++) {
            cm0 = fmaxf(cm0, fmaxf(sS[nf][0], sS[nf][1]));
            cm1 = fmaxf(cm1, fmaxf(sS[nf][2], sS[nf][3]));
        }
        cm0 = fmaxf(cm0, __shfl_xor_sync(0xffffffffu, cm0, 1));
        cm0 = fmaxf(cm0, __shfl_xor_sync(0xffffffffu, cm0, 2));
        cm1 = fmaxf(cm1, __shfl_xor_sync(0xffffffffu, cm1, 1));
        cm1 = fmaxf(cm1, __shfl_xor_sync(0xffffffffu, cm1, 2));
        float nm0 = fmaxf(mr0, cm0), nm1 = fmaxf(mr1, cm1);
        float f0 = __expf(mr0 - nm0), f1 = __expf(mr1 - nm1);
        mr0 = nm0; mr1 = nm1;

        float ls0 = 0.f, ls1 = 0.f;
#pragma unroll
        for (int nf = 0; nf < 8; nf++) {
            sS[nf][0] = __expf(sS[nf][0] - nm0);
            sS[nf][1] = __expf(sS[nf][1] - nm0);
            sS[nf][2] = __expf(sS[nf][2] - nm1);
            sS[nf][3] = __expf(sS[nf][3] - nm1);
            ls0 += sS[nf][0] + sS[nf][1];
            ls1 += sS[nf][2] + sS[nf][3];
        }
        ls0 += __shfl_xor_sync(0xffffffffu, ls0, 1);
        ls0 += __shfl_xor_sync(0xffffffffu, ls0, 2);
        ls1 += __shfl_xor_sync(0xffffffffu, ls1, 1);
        ls1 += __shfl_xor_sync(0xffffffffu, ls1, 2);
        l0 = l0*f0 + ls0;
        l1 = l1*f1 + ls1;
#pragma unroll
        for (int df = 0; df < 8; df++) {
            o[df][0] *= f0; o[df][1] *= f0;
            o[df][2] *= f1; o[df][3] *= f1;
        }

        uint32_t ap[4][4];
#pragma unroll
        for (int j = 0; j < 4; j++) {
            ap[j][0] = pack_h2(sS[2*j][0],   sS[2*j][1]);
            ap[j][1] = pack_h2(sS[2*j][2],   sS[2*j][3]);
            ap[j][2] = pack_h2(sS[2*j+1][0], sS[2*j+1][1]);
            ap[j][3] = pack_h2(sS[2*j+1][2], sS[2*j+1][3]);
        }

#pragma unroll
        for (int j = 0; j < 4; j++) {
            int kr = kc*64 + j*16 + mrow + ((msel & 1) << 3);
            int chalf = msel >> 1;
#pragma unroll
            for (int p = 0; p < 4; p++) {
                int ch = 2*p + chalf;
                uint32_t r0, r1, r2, r3;
                ldsm4t(r0, r1, r2, r3,
                       uV + (uint32_t)(kr*128 + ((ch ^ (kr & 7)) << 4)));
                mma_h(o[2*p][0], o[2*p][1], o[2*p][2], o[2*p][3],
                      ap[j][0], ap[j][1], ap[j][2], ap[j][3], r0, r1);
                mma_h(o[2*p+1][0], o[2*p+1][1], o[2*p+1][2], o[2*p+1][3],
                      ap[j][0], ap[j][1], ap[j][2], ap[j][3], r2, r3);
            }
        }
    }

    float inv0 = 1.0f / l0, inv1 = 1.0f / l1;
    int r0g = wm + gid, r1g = wm + gid + 8;
#pragma unroll
    for (int df = 0; df < 8; df++) {
        int d = df*8 + 2*tig;
        if (r0g < KTOP)
            *(half2*)(g_sa + (tokbase + r0g)*512 + h*64 + d) =
                __floats2half2_rn(o[df][0]*inv0, o[df][1]*inv0);
        if (r1g < KTOP)
            *(half2*)(g_sa + (tokbase + r1g)*512 + h*64 + d) =
                __floats2half2_rn(o[df][2]*inv1, o[df][3]*inv1);
    }
}

/* ------------- BatchNorm apply (stats finalized inline) ------------------ */
__global__ void bn_apply(const float* __restrict__ bnw, const float* __restrict__ bnb)
{
    size_t i = (size_t)blockIdx.x*256 + threadIdx.x;   /* over BKTOK*256 h2 */
    if (i < (size_t)BKTOK*256) {
        int c2 = (int)(i & 255);
        int c  = c2 * 2;
        size_t row = i >> 8;
        float m0 = g_s1[c  ] * (1.0f/BKTOK);
        float m1 = g_s1[c+1] * (1.0f/BKTOK);
        float r0 = rsqrtf(g_s2[c  ] * (1.0f/BKTOK) - m0*m0 + 1e-5f);
        float r1 = rsqrtf(g_s2[c+1] * (1.0f/BKTOK) - m1*m1 + 1e-5f);
        half2 hv = ((const half2*)g_hh)[i];
        float x0 = __low2float(hv), x1 = __high2float(hv);
        x0 = (x0 - m0) * r0 * bnw[c  ] + bnb[c  ];
        x1 = (x1 - m1) * r1 * bnw[c+1] + bnb[c+1];
        ((half2*)(g_comb + row*1024 + 512))[c2] =
            __floats2half2_rn(fmaxf(x0, 0.f), fmaxf(x1, 0.f));
    }
}

/* ------------------------------- launcher -------------------------------- */
extern "C" void kernel_launch(void* const* d_in, const int* in_sizes, int n_in,
                              void* d_out, int out_size)
{
    const float* features = (const float*)d_in[0];
    const int*   text     = (const int*)  d_in[1];
    const float* atten    = (const float*)d_in[2];
    const float* ln_q_w   = (const float*)d_in[3];
    const float* ln_q_b   = (const float*)d_in[4];
    const float* sa_in_w  = (const float*)d_in[5];
    const float* sa_in_b  = (const float*)d_in[6];
    const float* sa_out_w = (const float*)d_in[7];
    const float* sa_out_b = (const float*)d_in[8];
    const float* ref_w1   = (const float*)d_in[9];
    const float* ref_b1   = (const float*)d_in[10];
    const float* ref_w2   = (const float*)d_in[11];
    const float* ref_b2   = (const float*)d_in[12];
    const float* gscal    = (const float*)d_in[13];
    const float* lin_w    = (const float*)d_in[14];
    const float* lin_b    = (const float*)d_in[15];
    const float* mlp_w1   = (const float*)d_in[16];
    const float* mlp_b1   = (const float*)d_in[17];
    const float* bn_w     = (const float*)d_in[18];
    const float* bn_b     = (const float*)d_in[19];
    const float* mlp_w2   = (const float*)d_in[20];
    const float* mlp_b2   = (const float*)d_in[21];
    float* out = (float*)d_out;

    float *p_bfin, *p_bfuse, *p_zero;
    __half *p_tok0, *p_qh, *p_qkvh, *p_sa, *p_y1h, *p_comb, *p_hh;
    __half *w_sain, *w_soT, *w_ref1, *w_ref2, *w_mlp1, *w_fin, *w_fuse;
    cudaGetSymbolAddress((void**)&p_tok0, g_tokh0);
    cudaGetSymbolAddress((void**)&p_qh,   g_qh);
    cudaGetSymbolAddress((void**)&p_qkvh, g_qkvh);
    cudaGetSymbolAddress((void**)&p_sa,   g_sa);
    cudaGetSymbolAddress((void**)&p_y1h,  g_y1h);
    cudaGetSymbolAddress((void**)&p_comb, g_comb);
    cudaGetSymbolAddress((void**)&p_hh,   g_hh);
    cudaGetSymbolAddress((void**)&p_bfin, g_bias_fin);
    cudaGetSymbolAddress((void**)&p_bfuse, g_bfuse);
    cudaGetSymbolAddress((void**)&p_zero, g_zero512);
    cudaGetSymbolAddress((void**)&w_sain,  g_w_sain);
    cudaGetSymbolAddress((void**)&w_soT,   g_w_soT);
    cudaGetSymbolAddress((void**)&w_ref1,  g_w_ref1);
    cudaGetSymbolAddress((void**)&w_ref2,  g_w_ref2);
    cudaGetSymbolAddress((void**)&w_mlp1,  g_w_mlp1);
    cudaGetSymbolAddress((void**)&w_fin,   g_w_fin);
    cudaGetSymbolAddress((void**)&w_fuse,  g_w_fuse);

    cudaFuncSetAttribute(gemm_h16<0,1,0,0>, cudaFuncAttributeMaxDynamicSharedMemorySize, GEMM_SMEM);
    cudaFuncSetAttribute(gemm_h16<0,1,1,0>, cudaFuncAttributeMaxDynamicSharedMemorySize, GEMM_SMEM);
    cudaFuncSetAttribute(gemm_h16<1,1,0,0>, cudaFuncAttributeMaxDynamicSharedMemorySize, GEMM_SMEM);
    cudaFuncSetAttribute(gemm_h16<2,1,0,0>, cudaFuncAttributeMaxDynamicSharedMemorySize, GEMM_SMEM);
    cudaFuncSetAttribute(gemm_h16<0,0,0,1>, cudaFuncAttributeMaxDynamicSharedMemorySize, GEMM_SMEM);
    cudaFuncSetAttribute(attn_tc, cudaFuncAttributeMaxDynamicSharedMemorySize, ATT_SMEM);

    const int MROWS = BKTOK;             /* 39168 = 306*128 */

    cvt_all_kernel<<<(P6+255)/256, 256>>>(sa_in_w, sa_out_w, ref_w1, ref_w2,
                                          lin_w, mlp_w1, mlp_w2, lin_b, mlp_b2, out);
    /* W_fuse = W_r1 @ W_so */
    gemm_h16<0,1,0,0><<<dim3(512/128, 1024/128), 128, GEMM_SMEM>>>(
        w_ref1, 512, w_soT, p_zero, w_fuse, 512, 1024, 512, 512, nullptr, nullptr);
    fuse_bias_kernel<<<1024, 128>>>(ref_w1, sa_out_b, ref_b1);

    topk_kernel<<<BATCH, NT>>>(text, atten);
    gather_ln_kernel<<<BKTOK/8, 256>>>(features, ln_q_w, ln_q_b);

    /* qkv = LN(tok) @ sa_in_w^T + b  (half out) */
    gemm_h16<0,1,0,0><<<dim3(1536/128, MROWS/128), 128, GEMM_SMEM>>>(
        p_qh, 512, w_sain, sa_in_b, p_qkvh, 1536, MROWS, 1536, 512, nullptr, nullptr);
    attn_tc<<<dim3(NHEADS, BATCH), ATT_THREADS, ATT_SMEM>>>();

    /* y1 = gelu(sa @ W_fuse^T + b_fuse)  (half out) */
    gemm_h16<1,1,0,0><<<dim3(1024/128, MROWS/128), 128, GEMM_SMEM>>>(
        p_sa, 512, w_fuse, p_bfuse, p_y1h, 1024, MROWS, 1024, 512, nullptr, nullptr);
    /* comb[:,0:512] = tok_h + sigmoid(g)*(y1 @ ref_w2^T + b)  (half out) */
    gemm_h16<2,1,0,0><<<dim3(512/128, MROWS/128), 128, GEMM_SMEM>>>(
        p_y1h, 1024, w_ref2, ref_b2, p_comb, 1024, MROWS, 512, 1024, p_tok0, gscal);
    /* h = tok_h @ mlp_w1^T + b  (half out + fused BN stats) */
    gemm_h16<0,1,1,0><<<dim3(512/128, MROWS/128), 128, GEMM_SMEM>>>(
        p_comb, 1024, w_mlp1, mlp_b1, p_hh, 512, MROWS, 512, 512, nullptr, nullptr);
    bn_apply<<<(int)(((size_t)BKTOK*256 + 255)/256), 256>>>(bn_w, bn_b);

    /* feat GEMM with fused masked max-pool -> out (atomicMax) */
    gemm_h16<0,0,0,1><<<dim3(1024/128, MROWS/128), 128, GEMM_SMEM>>>(
        p_comb, 1024, w_fin, p_bfin, out, 1024, MROWS, 1024, 1024, nullptr, nullptr);
}